// round 2
// baseline (speedup 1.0000x reference)
#include <cuda_runtime.h>
#include <math.h>
#include <stdint.h>

// Problem constants (fixed by the dataset)
#define NN    100000
#define KNB   20
#define DNF   128     // node/memory/event feature dim, time dim
#define DQF   256     // query dim
#define DKF   384     // key/value dim
#define UROW  385     // 384 u-values + 1 ck scalar per head

// ---------------- scratch (device globals; reused across stages) ------------
__device__ float g_qbuf[(size_t)NN * 128];    // q = node_feat[idx]+memory[idx]
__device__ float g_bufA[(size_t)NN * 256];    // qh, later ao (attn out pre-Wo)
__device__ float g_bufB[(size_t)NN * 770];    // u (2x385), later o (256)
__device__ float g_bufC[(size_t)NN * 768];    // mixed (2x384), later h1 (128)
__device__ unsigned char g_flags[NN];         // no-neighbor flag
__device__ float g_WkT[2 * UROW * 128];       // WkT[h][c][d] = Wk[h*128+d][c]; row 384 = bk_h
__device__ float g_qhconst[256];              // bq + Wq[:,128:] @ cos(time_b)
__device__ int g_mask_is_byte;                // 1 if mask is uint8 layout, 0 if int32

// ---------------- mask layout probe -----------------------------------------
// If the harness stored the bool mask as int32, bytes at (pos % 4 != 0) are
// always zero. If it stored uint8 bools, ~half of ALL byte positions are
// nonzero. Scan the first 8KB and decide. Deterministic for fixed input.
__global__ void k_flagreset() { g_mask_is_byte = 0; }

__global__ void k_maskprobe(const unsigned char* __restrict__ m, int nbytes)
{
    int i = blockIdx.x * 256 + threadIdx.x;
    if (i < nbytes && (i & 3) != 0 && m[i] != 0) g_mask_is_byte = 1;
}

__device__ __forceinline__ int mget(const void* m, int i, int isbyte)
{
    return isbyte ? (((const unsigned char*)m)[i] != 0)
                  : (((const int*)m)[i] != 0);
}

// ---------------- small setup kernels ---------------------------------------

__global__ void k_gatherq(const int* __restrict__ idx,
                          const float* __restrict__ nf,
                          const float* __restrict__ mem,
                          float* __restrict__ qbuf, int n)
{
    int i = blockIdx.x * 256 + threadIdx.x;       // over n*32 float4s
    if (i >= n * 32) return;
    int node = i >> 5, c4 = i & 31;
    int src = idx[node];
    float4 a = ((const float4*)nf)[(size_t)src * 32 + c4];
    float4 b = ((const float4*)mem)[(size_t)src * 32 + c4];
    ((float4*)qbuf)[i] = make_float4(a.x + b.x, a.y + b.y, a.z + b.z, a.w + b.w);
}

// qh_const[r] = bq[r] + sum_j Wq[r][128+j] * cos(time_b[j])   (q_time is constant)
__global__ void k_qhconst(const float* __restrict__ Wq,
                          const float* __restrict__ bq,
                          const float* __restrict__ time_b,
                          float* __restrict__ qhc)
{
    __shared__ float cb[128];
    int tid = threadIdx.x;
    if (tid < 128) cb[tid] = cosf(time_b[tid]);
    __syncthreads();
    float acc = bq[tid];
    const float* row = Wq + (size_t)tid * 256 + 128;
    #pragma unroll 8
    for (int j = 0; j < 128; j++) acc += row[j] * cb[j];
    qhc[tid] = acc;
}

// Build WkT[h][c][d]; c==384 row holds bk_h so the u-GEMM also produces ck = qh_h . bk_h
__global__ void k_wkt(const float* __restrict__ Wk, const float* __restrict__ bk,
                      float* __restrict__ wkt)
{
    int i = blockIdx.x * 256 + threadIdx.x;       // over 2*385*128
    if (i >= 2 * UROW * 128) return;
    int d = i & 127;
    int c = (i >> 7) % UROW;
    int h = i / (UROW * 128);
    wkt[i] = (c < 384) ? Wk[(size_t)(h * 128 + d) * DKF + c] : bk[h * 128 + d];
}

// ---------------- generic fp32 tiled GEMM:  C[n,r] = sum_c A[n,c]*B[r,c] -----
// 64x64 tile, K-chunk 16, 256 threads, 4x4 micro-tile, float4 smem reads.
template<bool SPLIT_A, bool RELU, bool USE_FLAGS>
__global__ __launch_bounds__(256)
void gemm_kernel(const float* __restrict__ A, int lda,
                 const float* __restrict__ A2, int lda2, int csplit,
                 const float* __restrict__ B, int ldb, int Rdim, int Cdim,
                 const float* __restrict__ bias,
                 float* __restrict__ Out, int ldc, int coff,
                 const unsigned char* __restrict__ flags, int Ntot)
{
    __shared__ float As[16 * 68];
    __shared__ float Bs[16 * 68];
    const int tid = threadIdx.x;
    const int tx = tid & 15, ty = tid >> 4;
    const int n0 = blockIdx.x * 64;
    const int r0 = blockIdx.y * 64;
    const int lrow = tid >> 2;             // 0..63
    const int lcol = (tid & 3) * 4;        // 0,4,8,12

    float acc[4][4] = {};

    for (int kt = 0; kt < Cdim; kt += 16) {
        // A tile (64 n x 16 c)
        {
            int n = n0 + lrow;
            float4 v = make_float4(0.f, 0.f, 0.f, 0.f);
            if (n < Ntot) {
                const float* p;
                if (SPLIT_A && kt >= csplit)
                    p = A2 + (size_t)n * lda2 + (kt - csplit) + lcol;
                else
                    p = A + (size_t)n * lda + kt + lcol;
                v = *(const float4*)p;
            }
            As[(lcol + 0) * 68 + lrow] = v.x;
            As[(lcol + 1) * 68 + lrow] = v.y;
            As[(lcol + 2) * 68 + lrow] = v.z;
            As[(lcol + 3) * 68 + lrow] = v.w;
        }
        // B tile (64 r x 16 c)
        {
            int r = r0 + lrow;
            float4 v = make_float4(0.f, 0.f, 0.f, 0.f);
            if (r < Rdim) v = *(const float4*)(B + (size_t)r * ldb + kt + lcol);
            Bs[(lcol + 0) * 68 + lrow] = v.x;
            Bs[(lcol + 1) * 68 + lrow] = v.y;
            Bs[(lcol + 2) * 68 + lrow] = v.z;
            Bs[(lcol + 3) * 68 + lrow] = v.w;
        }
        __syncthreads();
        #pragma unroll
        for (int k = 0; k < 16; k++) {
            float4 a = *(const float4*)&As[k * 68 + ty * 4];
            float4 b = *(const float4*)&Bs[k * 68 + tx * 4];
            acc[0][0] += a.x * b.x; acc[0][1] += a.x * b.y; acc[0][2] += a.x * b.z; acc[0][3] += a.x * b.w;
            acc[1][0] += a.y * b.x; acc[1][1] += a.y * b.y; acc[1][2] += a.y * b.z; acc[1][3] += a.y * b.w;
            acc[2][0] += a.z * b.x; acc[2][1] += a.z * b.y; acc[2][2] += a.z * b.z; acc[2][3] += a.z * b.w;
            acc[3][0] += a.w * b.x; acc[3][1] += a.w * b.y; acc[3][2] += a.w * b.z; acc[3][3] += a.w * b.w;
        }
        __syncthreads();
    }

    #pragma unroll
    for (int i = 0; i < 4; i++) {
        int n = n0 + ty * 4 + i;
        if (n >= Ntot) continue;
        float zf = 1.f;
        if (USE_FLAGS) zf = flags[n] ? 0.f : 1.f;
        #pragma unroll
        for (int j = 0; j < 4; j++) {
            int r = r0 + tx * 4 + j;
            if (r >= Rdim) continue;
            float v = acc[i][j];
            if (bias) v += bias[r];
            if (RELU) v = fmaxf(v, 0.f);
            v *= zf;
            Out[(size_t)n * ldc + coff + r] = v;
        }
    }
}

// ---------------- fused per-node edge kernel --------------------------------
// Builds kvc (20x384) in smem from gathers + time encoding, computes masked
// scores via u, softmax, and the attention-weighted kvc mix (2x384).
__global__ __launch_bounds__(256)
void k_edge(const int* __restrict__ neighbors, const float* __restrict__ t,
            const float* __restrict__ e_t, const int* __restrict__ e_id,
            const void* __restrict__ mask,
            const float* __restrict__ node_feat, const float* __restrict__ memory,
            const float* __restrict__ event_feat,
            const float* __restrict__ time_w, const float* __restrict__ time_b,
            const float* __restrict__ u, float* __restrict__ mixed,
            unsigned char* __restrict__ flags, int Ntot)
{
    int n = blockIdx.x;
    if (n >= Ntot) return;
    int tid = threadIdx.x;
    int lane = tid & 31, warp = tid >> 5;
    const int isb = g_mask_is_byte;

    __shared__ float kvc[KNB][DKF];
    __shared__ float usf[770];
    __shared__ float tw[128], tb[128];
    __shared__ float attn[2][KNB];
    __shared__ int s_nonb;

    if (tid < 128) { tw[tid] = time_w[tid]; tb[tid] = time_b[tid]; }
    for (int i = tid; i < 770; i += 256) usf[i] = u[(size_t)n * 770 + i];
    if (warp == 0) {
        unsigned mbit = 0;
        if (lane < KNB) mbit = mget(mask, n * KNB + lane, isb) ? 1u : 0u;
        unsigned any = __ballot_sync(0xffffffffu, mbit != 0);
        if (lane == 0) s_nonb = (any == 0) ? 1 : 0;
    }
    __syncthreads();

    float tn = t[n];
    for (int k = warp; k < KNB; k += 8) {
        int nb = neighbors[n * KNB + k];
        int mk = mget(mask, n * KNB + k, isb);
        float dt = tn - e_t[n * KNB + k];
        int eid = e_id[n * KNB + k];
        const float4* nf4 = (const float4*)(node_feat + (size_t)nb * 128);
        const float4* mm4 = (const float4*)(memory + (size_t)nb * 128);
        const float4* ef4 = (const float4*)(event_feat + (size_t)eid * 128);
        for (int c4 = lane; c4 < 96; c4 += 32) {
            float4 v;
            if (c4 < 32) {
                if (mk) {
                    float4 a = nf4[c4], b = mm4[c4];
                    v = make_float4(a.x + b.x, a.y + b.y, a.z + b.z, a.w + b.w);
                } else {
                    v = make_float4(0.f, 0.f, 0.f, 0.f);
                }
            } else if (c4 < 64) {
                int j = (c4 - 32) * 4;
                v.x = cosf(__fadd_rn(__fmul_rn(dt, tw[j + 0]), tb[j + 0]));
                v.y = cosf(__fadd_rn(__fmul_rn(dt, tw[j + 1]), tb[j + 1]));
                v.z = cosf(__fadd_rn(__fmul_rn(dt, tw[j + 2]), tb[j + 2]));
                v.w = cosf(__fadd_rn(__fmul_rn(dt, tw[j + 3]), tb[j + 3]));
            } else {
                v = ef4[c4 - 64];
            }
            *(float4*)&kvc[k][c4 * 4] = v;
        }
    }
    __syncthreads();

    // scores: 40 (head,k) dot products of length 384
    __shared__ float sc[2][KNB];
    for (int p = warp; p < 2 * KNB; p += 8) {
        int h = p / KNB, k = p % KNB;
        float s = 0.f;
        const float* uh = &usf[h * UROW];
        #pragma unroll 4
        for (int c = lane; c < DKF; c += 32) s += uh[c] * kvc[k][c];
        #pragma unroll
        for (int off = 16; off; off >>= 1) s += __shfl_down_sync(0xffffffffu, s, off);
        if (lane == 0) sc[h][k] = (s + uh[384]) * 0.08838834764831845f; // 1/sqrt(128)
    }
    __syncthreads();

    // masked softmax per head (warps 0,1)
    if (warp < 2) {
        int h = warp;
        int valid = 0;
        float s = -INFINITY;
        if (lane < KNB) {
            valid = mget(mask, n * KNB + lane, isb) || s_nonb;
            if (valid) s = sc[h][lane];
        }
        float m = s;
        #pragma unroll
        for (int off = 16; off; off >>= 1) m = fmaxf(m, __shfl_xor_sync(0xffffffffu, m, off));
        float e = (lane < KNB && valid) ? expf(s - m) : 0.f;
        float sum = e;
        #pragma unroll
        for (int off = 16; off; off >>= 1) sum += __shfl_xor_sync(0xffffffffu, sum, off);
        if (lane < KNB) attn[h][lane] = e / sum;
    }
    __syncthreads();

    // mixed[h][j] = sum_k attn[h][k] * kvc[k][j]
    for (int i = tid; i < 2 * DKF; i += 256) {
        int h = i / DKF, j = i % DKF;
        float acc = 0.f;
        #pragma unroll
        for (int k = 0; k < KNB; k++) acc += attn[h][k] * kvc[k][j];
        mixed[(size_t)n * 768 + i] = acc;
    }
    if (tid == 0) flags[n] = (unsigned char)s_nonb;
}

// ---------------- launch ------------------------------------------------------
extern "C" void kernel_launch(void* const* d_in, const int* in_sizes, int n_in,
                              void* d_out, int out_size)
{
    const int*   idx        = (const int*)d_in[0];
    const float* t          = (const float*)d_in[1];
    const int*   neighbors  = (const int*)d_in[2];
    const float* e_t        = (const float*)d_in[3];
    const int*   e_id       = (const int*)d_in[4];
    const void*  mask       = d_in[5];
    const float* node_feat  = (const float*)d_in[6];
    const float* memory     = (const float*)d_in[7];
    const float* event_feat = (const float*)d_in[8];
    const float* time_w     = (const float*)d_in[9];
    const float* time_b     = (const float*)d_in[10];
    const float* Wq = (const float*)d_in[11];
    const float* bq = (const float*)d_in[12];
    const float* Wk = (const float*)d_in[13];
    const float* bk = (const float*)d_in[14];
    const float* Wv = (const float*)d_in[15];
    const float* bv = (const float*)d_in[16];
    const float* Wo = (const float*)d_in[17];
    const float* bo = (const float*)d_in[18];
    const float* W1 = (const float*)d_in[19];
    const float* b1 = (const float*)d_in[20];
    const float* W2 = (const float*)d_in[21];
    const float* b2 = (const float*)d_in[22];
    float* out = (float*)d_out;

    int N = in_sizes[0];
    if (N > NN) N = NN;

    float *qbuf, *bufA, *bufB, *bufC, *wkt, *qhc;
    unsigned char* flags;
    cudaGetSymbolAddress((void**)&qbuf, g_qbuf);
    cudaGetSymbolAddress((void**)&bufA, g_bufA);
    cudaGetSymbolAddress((void**)&bufB, g_bufB);
    cudaGetSymbolAddress((void**)&bufC, g_bufC);
    cudaGetSymbolAddress((void**)&wkt, g_WkT);
    cudaGetSymbolAddress((void**)&qhc, g_qhconst);
    cudaGetSymbolAddress((void**)&flags, g_flags);

    int gx = (N + 63) / 64;

    // mask layout probe (bytes vs int32): scan first 8KB
    k_flagreset<<<1, 1>>>();
    k_maskprobe<<<32, 256>>>((const unsigned char*)mask, 8192);

    // setup
    k_gatherq<<<(N * 32 + 255) / 256, 256>>>(idx, node_feat, memory, qbuf, N);
    k_qhconst<<<1, 256>>>(Wq, bq, time_b, qhc);
    k_wkt<<<(2 * UROW * 128 + 255) / 256, 256>>>(Wk, bk, wkt);

    // K1: qh = q @ Wq[:, :128]^T + qh_const       -> bufA (N x 256)
    gemm_kernel<false, false, false><<<dim3(gx, 4), 256>>>(
        qbuf, 128, nullptr, 0, 0, Wq, 256, 256, 128, qhc, bufA, 256, 0, nullptr, N);

    // K2: u_h = WkT_h @ qh_h (row 384 gives ck)   -> bufB (N x 2 x 385)
    for (int h = 0; h < 2; h++) {
        gemm_kernel<false, false, false><<<dim3(gx, (UROW + 63) / 64), 256>>>(
            bufA + h * 128, 256, nullptr, 0, 0, wkt + (size_t)h * UROW * 128, 128,
            UROW, 128, nullptr, bufB, 770, h * UROW, nullptr, N);
    }

    // K3: fused gather + time-encode + scores + softmax + mix  -> bufC (N x 768)
    k_edge<<<N, 256>>>(neighbors, t, e_t, e_id, mask, node_feat, memory,
                       event_feat, time_w, time_b, bufB, bufC, flags, N);

    // K4: ao_h = mixed_h @ Wv_h^T + bv_h          -> bufA (N x 256) [qh dead]
    for (int h = 0; h < 2; h++) {
        gemm_kernel<false, false, false><<<dim3(gx, 2), 256>>>(
            bufC + h * 384, 768, nullptr, 0, 0, Wv + (size_t)h * 128 * 384, 384,
            128, 384, bv + h * 128, bufA, 256, h * 128, nullptr, N);
    }

    // K5: o = ao @ Wo^T + bo, zeroed where no neighbors -> bufB (N x 256) [u dead]
    gemm_kernel<false, false, true><<<dim3(gx, 4), 256>>>(
        bufA, 256, nullptr, 0, 0, Wo, 256, 256, 256, bo, bufB, 256, 0, flags, N);

    // K6: h1 = relu([o, q] @ W1^T + b1)           -> bufC (N x 128) [mixed dead]
    gemm_kernel<true, true, false><<<dim3(gx, 2), 256>>>(
        bufB, 256, qbuf, 128, 256, W1, 384, 128, 384, b1, bufC, 128, 0, nullptr, N);

    // K7: out = h1 @ W2^T + b2                    -> d_out (N x 128)
    gemm_kernel<false, false, false><<<dim3(gx, 2), 256>>>(
        bufC, 128, nullptr, 0, 0, W2, 128, 128, 128, b2, out, 128, 0, nullptr, N);
}

// round 3
// speedup vs baseline: 1.2601x; 1.2601x over previous
#include <cuda_runtime.h>
#include <math.h>
#include <stdint.h>

#define NN    100000
#define KNB   20
#define DKF   384
#define UROW  385     // 384 u-values + 1 ck scalar per head

// ---------------- scratch (device globals) ----------------------------------
__device__ float g_qbuf[(size_t)NN * 128];    // q = node_feat[idx]+memory[idx]
__device__ float g_bufA[(size_t)NN * 256];    // h1
__device__ float g_bufB[(size_t)NN * 770];    // u (2x385)
__device__ float g_bufC[(size_t)NN * 768];    // mixed (2x384)
__device__ unsigned char g_flags[NN];         // no-neighbor flag
__device__ float g_qhconst[256];              // bq + Wq[:,128:] @ cos(time_b)
__device__ float g_Mu[770 * 128];             // composed u matrix
__device__ float g_du[770];                   // composed u bias
__device__ float g_Pt[256 * 128];             // (W1o @ Wo)^T : Pt[a][r]
__device__ float g_Bf[128 * 896];             // fused final matrix [r][j]
__device__ float g_cvec[128];                 // fused constant (gated by flags)
__device__ int   g_mask_is_byte;

// ---------------- mask layout probe ------------------------------------------
__global__ void k_flagreset() { g_mask_is_byte = 0; }
__global__ void k_maskprobe(const unsigned char* __restrict__ m, int nbytes)
{
    int i = blockIdx.x * 256 + threadIdx.x;
    if (i < nbytes && (i & 3) != 0 && m[i] != 0) g_mask_is_byte = 1;
}
__device__ __forceinline__ int mget(const void* m, int i, int isbyte)
{
    return isbyte ? (((const unsigned char*)m)[i] != 0)
                  : (((const int*)m)[i] != 0);
}

// ---------------- setup / compose kernels ------------------------------------

__global__ void k_gatherq(const int* __restrict__ idx,
                          const float* __restrict__ nf,
                          const float* __restrict__ mem,
                          float* __restrict__ qbuf, int n)
{
    int i = blockIdx.x * 256 + threadIdx.x;
    if (i >= n * 32) return;
    int node = i >> 5, c4 = i & 31;
    int src = idx[node];
    float4 a = ((const float4*)nf)[(size_t)src * 32 + c4];
    float4 b = ((const float4*)mem)[(size_t)src * 32 + c4];
    ((float4*)qbuf)[i] = make_float4(a.x + b.x, a.y + b.y, a.z + b.z, a.w + b.w);
}

// qh_const[r] = bq[r] + sum_j Wq[r][128+j] * cos(time_b[j])
__global__ void k_qhconst(const float* __restrict__ Wq,
                          const float* __restrict__ bq,
                          const float* __restrict__ time_b,
                          float* __restrict__ qhc)
{
    __shared__ float cb[128];
    int tid = threadIdx.x;
    if (tid < 128) cb[tid] = cosf(time_b[tid]);
    __syncthreads();
    float acc = bq[tid];
    const float* row = Wq + (size_t)tid * 256 + 128;
    #pragma unroll 8
    for (int j = 0; j < 128; j++) acc += row[j] * cb[j];
    qhc[tid] = acc;
}

// Pt[a][r] = sum_s W1[r][s] * Wo[s][a]  (r<128, a,s<256); also cvec.
__global__ void k_composeP(const float* __restrict__ W1, const float* __restrict__ Wo,
                           const float* __restrict__ bv, const float* __restrict__ bo,
                           float* __restrict__ Pt, float* __restrict__ cvec)
{
    int r = blockIdx.x;           // 0..127
    int a = threadIdx.x;          // 0..255
    __shared__ float w1row[256];
    __shared__ float red[256];
    w1row[a] = W1[(size_t)r * 384 + a];
    __syncthreads();
    float acc = 0.f;
    #pragma unroll 8
    for (int s = 0; s < 256; s++) acc += w1row[s] * Wo[(size_t)s * 256 + a];
    Pt[(size_t)a * 128 + r] = acc;
    // cvec[r] = sum_a P[r][a]*bv[a] + sum_s W1[r][s]*bo[s]
    red[a] = acc * bv[a] + w1row[a] * bo[a];
    __syncthreads();
    for (int off = 128; off; off >>= 1) {
        if (a < off) red[a] += red[a + off];
        __syncthreads();
    }
    if (a == 0) cvec[r] = red[0];
}

// Bf[r][j]: j<768 -> sum_d Pt[h*128+d][r] * Wv[h*128+d][c]; j>=768 -> W1[r][256+e]
__global__ void k_composeC(const float* __restrict__ Pt, const float* __restrict__ Wv,
                           const float* __restrict__ W1, float* __restrict__ Bf)
{
    int j = blockIdx.x;           // 0..895
    int r = threadIdx.x;          // 0..127
    if (j >= 768) {
        Bf[(size_t)r * 896 + j] = W1[(size_t)r * 384 + 256 + (j - 768)];
        return;
    }
    int h = j / 384, c = j % 384;
    __shared__ float wvcol[128];
    wvcol[r] = Wv[(size_t)(h * 128 + r) * 384 + c];
    __syncthreads();
    float acc = 0.f;
    #pragma unroll 8
    for (int d = 0; d < 128; d++)
        acc += Pt[(size_t)(h * 128 + d) * 128 + r] * wvcol[d];
    Bf[(size_t)r * 896 + j] = acc;
}

// Mu[hc][e] = sum_d K(h,c,d)*Wq[h*128+d][e];  du[hc] = sum_d K(h,c,d)*qhc[h*128+d]
// K(h,c,d) = (c<384 ? Wk[(h*128+d)*384+c] : bk[h*128+d])
__global__ void k_composeU(const float* __restrict__ Wk, const float* __restrict__ bk,
                           const float* __restrict__ Wq, const float* __restrict__ qhc,
                           float* __restrict__ Mu, float* __restrict__ du)
{
    int hc = blockIdx.x;          // 0..769
    int h = hc / UROW, c = hc % UROW;
    int e = threadIdx.x;          // 0..159 (guard <=128)
    __shared__ float krow[128];
    if (e < 128)
        krow[e] = (c < 384) ? Wk[(size_t)(h * 128 + e) * 384 + c] : bk[h * 128 + e];
    __syncthreads();
    if (e < 128) {
        float acc = 0.f;
        #pragma unroll 8
        for (int d = 0; d < 128; d++)
            acc += krow[d] * Wq[(size_t)(h * 128 + d) * 256 + e];
        Mu[(size_t)hc * 128 + e] = acc;
    } else if (e == 128) {
        float acc = 0.f;
        for (int d = 0; d < 128; d++) acc += krow[d] * qhc[h * 128 + d];
        du[hc] = acc;
    }
}

// ---------------- 128x128 fp32 GEMM:  Out[n,r] = sum_c A[n,c]*B[r,c] ---------
// 256 threads, 8x8 micro-tile, BK=16.
template<bool SPLIT_A, bool RELU, bool BIAS2>
__global__ __launch_bounds__(256, 2)
void gemm128(const float* __restrict__ A, int lda,
             const float* __restrict__ A2, int lda2, int csplit,
             const float* __restrict__ B, int ldb, int Rdim, int Cdim,
             const float* __restrict__ bias, const float* __restrict__ bias2,
             float* __restrict__ Out, int ldc,
             const unsigned char* __restrict__ flags, int Ntot)
{
    __shared__ float As[16][132];
    __shared__ float Bs[16][132];
    const int tid = threadIdx.x;
    const int tx = tid & 15;      // r dir (8 cols each)
    const int ty = tid >> 4;      // n dir (8 rows each)
    const int n0 = blockIdx.x * 128;
    const int r0 = blockIdx.y * 128;

    float acc[8][8] = {};

    for (int kt = 0; kt < Cdim; kt += 16) {
        #pragma unroll
        for (int s = 0; s < 2; s++) {
            int l = tid + s * 256;               // 0..511
            int row = l >> 2, c = (l & 3) * 4;
            // A tile
            {
                int n = n0 + row;
                float4 v = make_float4(0.f, 0.f, 0.f, 0.f);
                if (n < Ntot) {
                    int cc = kt + c;
                    const float* p;
                    if (SPLIT_A && cc >= csplit)
                        p = A2 + (size_t)n * lda2 + (cc - csplit);
                    else
                        p = A + (size_t)n * lda + cc;
                    v = *(const float4*)p;
                }
                As[c + 0][row] = v.x; As[c + 1][row] = v.y;
                As[c + 2][row] = v.z; As[c + 3][row] = v.w;
            }
            // B tile
            {
                int r = r0 + row;
                float4 v = make_float4(0.f, 0.f, 0.f, 0.f);
                if (r < Rdim) v = *(const float4*)(B + (size_t)r * ldb + kt + c);
                Bs[c + 0][row] = v.x; Bs[c + 1][row] = v.y;
                Bs[c + 2][row] = v.z; Bs[c + 3][row] = v.w;
            }
        }
        __syncthreads();
        #pragma unroll
        for (int k = 0; k < 16; k++) {
            float a[8], b[8];
            *(float4*)&a[0] = *(const float4*)&As[k][ty * 8];
            *(float4*)&a[4] = *(const float4*)&As[k][ty * 8 + 4];
            *(float4*)&b[0] = *(const float4*)&Bs[k][tx * 8];
            *(float4*)&b[4] = *(const float4*)&Bs[k][tx * 8 + 4];
            #pragma unroll
            for (int i = 0; i < 8; i++)
                #pragma unroll
                for (int j = 0; j < 8; j++)
                    acc[i][j] += a[i] * b[j];
        }
        __syncthreads();
    }

    #pragma unroll
    for (int i = 0; i < 8; i++) {
        int n = n0 + ty * 8 + i;
        if (n >= Ntot) continue;
        bool fl = BIAS2 ? (flags[n] != 0) : false;
        #pragma unroll
        for (int j = 0; j < 8; j++) {
            int r = r0 + tx * 8 + j;
            if (r >= Rdim) continue;
            float v = acc[i][j] + bias[r];
            if (BIAS2 && !fl) v += bias2[r];
            if (RELU) v = fmaxf(v, 0.f);
            Out[(size_t)n * ldc + r] = v;
        }
    }
}

// ---------------- fused per-node edge kernel ---------------------------------
__global__ __launch_bounds__(256)
void k_edge(const int* __restrict__ neighbors, const float* __restrict__ t,
            const float* __restrict__ e_t, const int* __restrict__ e_id,
            const void* __restrict__ mask,
            const float* __restrict__ node_feat, const float* __restrict__ memory,
            const float* __restrict__ event_feat,
            const float* __restrict__ time_w, const float* __restrict__ time_b,
            const float* __restrict__ u, float* __restrict__ mixed,
            unsigned char* __restrict__ flags, int Ntot)
{
    int n = blockIdx.x;
    if (n >= Ntot) return;
    int tid = threadIdx.x;
    int lane = tid & 31, warp = tid >> 5;
    const int isb = g_mask_is_byte;

    __shared__ float kvc[KNB][DKF];
    __shared__ float usf[770];
    __shared__ float tw[128], tb[128];
    __shared__ float attn[2][KNB];
    __shared__ float sc[2][KNB];
    __shared__ int s_nonb;

    if (tid < 128) { tw[tid] = time_w[tid]; tb[tid] = time_b[tid]; }
    for (int i = tid; i < 770; i += 256) usf[i] = u[(size_t)n * 770 + i];
    if (warp == 0) {
        unsigned mbit = 0;
        if (lane < KNB) mbit = mget(mask, n * KNB + lane, isb) ? 1u : 0u;
        unsigned any = __ballot_sync(0xffffffffu, mbit != 0);
        if (lane == 0) s_nonb = (any == 0) ? 1 : 0;
    }
    __syncthreads();

    float tn = t[n];
    for (int k = warp; k < KNB; k += 8) {
        int nb = neighbors[n * KNB + k];
        int mk = mget(mask, n * KNB + k, isb);
        float dt = tn - e_t[n * KNB + k];
        int eid = e_id[n * KNB + k];
        const float4* nf4 = (const float4*)(node_feat + (size_t)nb * 128);
        const float4* mm4 = (const float4*)(memory + (size_t)nb * 128);
        const float4* ef4 = (const float4*)(event_feat + (size_t)eid * 128);
        for (int c4 = lane; c4 < 96; c4 += 32) {
            float4 v;
            if (c4 < 32) {
                if (mk) {
                    float4 a = nf4[c4], b = mm4[c4];
                    v = make_float4(a.x + b.x, a.y + b.y, a.z + b.z, a.w + b.w);
                } else {
                    v = make_float4(0.f, 0.f, 0.f, 0.f);
                }
            } else if (c4 < 64) {
                int j = (c4 - 32) * 4;
                v.x = cosf(__fadd_rn(__fmul_rn(dt, tw[j + 0]), tb[j + 0]));
                v.y = cosf(__fadd_rn(__fmul_rn(dt, tw[j + 1]), tb[j + 1]));
                v.z = cosf(__fadd_rn(__fmul_rn(dt, tw[j + 2]), tb[j + 2]));
                v.w = cosf(__fadd_rn(__fmul_rn(dt, tw[j + 3]), tb[j + 3]));
            } else {
                v = ef4[c4 - 64];
            }
            *(float4*)&kvc[k][c4 * 4] = v;
        }
    }
    __syncthreads();

    for (int p = warp; p < 2 * KNB; p += 8) {
        int h = p / KNB, k = p % KNB;
        float s = 0.f;
        const float* uh = &usf[h * UROW];
        #pragma unroll 4
        for (int c = lane; c < DKF; c += 32) s += uh[c] * kvc[k][c];
        #pragma unroll
        for (int off = 16; off; off >>= 1) s += __shfl_down_sync(0xffffffffu, s, off);
        if (lane == 0) sc[h][k] = (s + uh[384]) * 0.08838834764831845f;
    }
    __syncthreads();

    if (warp < 2) {
        int h = warp;
        int valid = 0;
        float s = -INFINITY;
        if (lane < KNB) {
            valid = mget(mask, n * KNB + lane, isb) || s_nonb;
            if (valid) s = sc[h][lane];
        }
        float m = s;
        #pragma unroll
        for (int off = 16; off; off >>= 1) m = fmaxf(m, __shfl_xor_sync(0xffffffffu, m, off));
        float e = (lane < KNB && valid) ? expf(s - m) : 0.f;
        float sum = e;
        #pragma unroll
        for (int off = 16; off; off >>= 1) sum += __shfl_xor_sync(0xffffffffu, sum, off);
        if (lane < KNB) attn[h][lane] = e / sum;
    }
    __syncthreads();

    float gate = s_nonb ? 0.f : 1.f;   // zero mixed for no-neighbor rows
    for (int i = tid; i < 2 * DKF; i += 256) {
        int h = i / DKF, j = i % DKF;
        float acc = 0.f;
        #pragma unroll
        for (int k = 0; k < KNB; k++) acc += attn[h][k] * kvc[k][j];
        mixed[(size_t)n * 768 + i] = acc * gate;
    }
    if (tid == 0) flags[n] = (unsigned char)s_nonb;
}

// ---------------- launch ------------------------------------------------------
extern "C" void kernel_launch(void* const* d_in, const int* in_sizes, int n_in,
                              void* d_out, int out_size)
{
    const int*   idx        = (const int*)d_in[0];
    const float* t          = (const float*)d_in[1];
    const int*   neighbors  = (const int*)d_in[2];
    const float* e_t        = (const float*)d_in[3];
    const int*   e_id       = (const int*)d_in[4];
    const void*  mask       = d_in[5];
    const float* node_feat  = (const float*)d_in[6];
    const float* memory     = (const float*)d_in[7];
    const float* event_feat = (const float*)d_in[8];
    const float* time_w     = (const float*)d_in[9];
    const float* time_b     = (const float*)d_in[10];
    const float* Wq = (const float*)d_in[11];
    const float* bq = (const float*)d_in[12];
    const float* Wk = (const float*)d_in[13];
    const float* bk = (const float*)d_in[14];
    const float* Wv = (const float*)d_in[15];
    const float* bv = (const float*)d_in[16];
    const float* Wo = (const float*)d_in[17];
    const float* bo = (const float*)d_in[18];
    const float* W1 = (const float*)d_in[19];
    const float* b1 = (const float*)d_in[20];
    const float* W2 = (const float*)d_in[21];
    const float* b2 = (const float*)d_in[22];
    float* out = (float*)d_out;

    int N = in_sizes[0];
    if (N > NN) N = NN;

    float *qbuf, *bufA, *bufB, *bufC, *qhc, *Mu, *du, *Pt, *Bf, *cvec;
    unsigned char* flags;
    cudaGetSymbolAddress((void**)&qbuf, g_qbuf);
    cudaGetSymbolAddress((void**)&bufA, g_bufA);
    cudaGetSymbolAddress((void**)&bufB, g_bufB);
    cudaGetSymbolAddress((void**)&bufC, g_bufC);
    cudaGetSymbolAddress((void**)&qhc, g_qhconst);
    cudaGetSymbolAddress((void**)&Mu, g_Mu);
    cudaGetSymbolAddress((void**)&du, g_du);
    cudaGetSymbolAddress((void**)&Pt, g_Pt);
    cudaGetSymbolAddress((void**)&Bf, g_Bf);
    cudaGetSymbolAddress((void**)&cvec, g_cvec);
    cudaGetSymbolAddress((void**)&flags, g_flags);

    int gx = (N + 127) / 128;

    // 0..4: setup & compose (launch order chosen so ncu -s 5 lands on u-GEMM)
    k_qhconst<<<1, 256>>>(Wq, bq, time_b, qhc);
    k_composeP<<<128, 256>>>(W1, Wo, bv, bo, Pt, cvec);
    k_composeC<<<896, 128>>>(Pt, Wv, W1, Bf);
    k_composeU<<<770, 160>>>(Wk, bk, Wq, qhc, Mu, du);
    k_gatherq<<<(N * 32 + 255) / 256, 256>>>(idx, node_feat, memory, qbuf, N);

    // 5: u = Mu @ q + du   -> bufB (N x 770)
    gemm128<false, false, false><<<dim3(gx, 7), 256>>>(
        qbuf, 128, nullptr, 0, 0, Mu, 128, 770, 128, du, nullptr, bufB, 770, nullptr, N);

    // 6,7: mask probe
    k_flagreset<<<1, 1>>>();
    k_maskprobe<<<32, 256>>>((const unsigned char*)mask, 8192);

    // 8: fused gather + time-encode + scores + softmax + mix -> bufC (N x 768)
    k_edge<<<N, 256>>>(neighbors, t, e_t, e_id, mask, node_feat, memory,
                       event_feat, time_w, time_b, bufB, bufC, flags, N);

    // 9: h1 = relu(Bf @ [mixed, q] + b1 + gated cvec) -> bufA (N x 128)
    gemm128<true, true, true><<<dim3(gx, 1), 256>>>(
        bufC, 768, qbuf, 128, 768, Bf, 896, 128, 896, b1, cvec, bufA, 128, flags, N);

    // 10: out = h1 @ W2^T + b2 -> d_out (N x 128)
    gemm128<false, false, false><<<dim3(gx, 1), 256>>>(
        bufA, 128, nullptr, 0, 0, W2, 128, 128, 128, b2, nullptr, out, 128, nullptr, N);
}

// round 4
// speedup vs baseline: 1.2866x; 1.0210x over previous
#include <cuda_runtime.h>
#include <math.h>
#include <stdint.h>

#define NN    100000
#define KNB   20
#define DKF   384
#define UROW  385     // 384 u-values + 1 ck scalar per head

// ---------------- scratch (device globals) ----------------------------------
__device__ float g_qbuf[(size_t)NN * 128];    // q = node_feat[idx]+memory[idx]
__device__ float g_bufA[(size_t)NN * 256];    // h1
__device__ float g_bufB[(size_t)NN * 770];    // u (2x385)
__device__ float g_bufC[(size_t)NN * 768];    // mixed (2x384)
__device__ unsigned char g_flags[NN];         // no-neighbor flag
__device__ float g_qhconst[256];              // bq + Wq[:,128:] @ cos(time_b)
__device__ float g_Mu[770 * 128];             // composed u matrix
__device__ float g_du[770];                   // composed u bias
__device__ float g_Pt[256 * 128];             // (W1o @ Wo)^T : Pt[a][r]
__device__ float g_Bf[128 * 896];             // fused final matrix [r][j]
__device__ float g_cvec[128];                 // fused constant (gated by flags)
__device__ int   g_mask_is_byte;

// ---------------- mask layout probe ------------------------------------------
__global__ void k_flagreset() { g_mask_is_byte = 0; }
__global__ void k_maskprobe(const unsigned char* __restrict__ m, int nbytes)
{
    int i = blockIdx.x * 256 + threadIdx.x;
    if (i < nbytes && (i & 3) != 0 && m[i] != 0) g_mask_is_byte = 1;
}
__device__ __forceinline__ int mget(const void* m, int i, int isbyte)
{
    return isbyte ? (((const unsigned char*)m)[i] != 0)
                  : (((const int*)m)[i] != 0);
}

// ---------------- setup / compose kernels ------------------------------------

__global__ void k_gatherq(const int* __restrict__ idx,
                          const float* __restrict__ nf,
                          const float* __restrict__ mem,
                          float* __restrict__ qbuf, int n)
{
    int i = blockIdx.x * 256 + threadIdx.x;
    if (i >= n * 32) return;
    int node = i >> 5, c4 = i & 31;
    int src = idx[node];
    float4 a = ((const float4*)nf)[(size_t)src * 32 + c4];
    float4 b = ((const float4*)mem)[(size_t)src * 32 + c4];
    ((float4*)qbuf)[i] = make_float4(a.x + b.x, a.y + b.y, a.z + b.z, a.w + b.w);
}

// qh_const[r] = bq[r] + sum_j Wq[r][128+j] * cos(time_b[j])
__global__ void k_qhconst(const float* __restrict__ Wq,
                          const float* __restrict__ bq,
                          const float* __restrict__ time_b,
                          float* __restrict__ qhc)
{
    __shared__ float cb[128];
    int tid = threadIdx.x;
    if (tid < 128) cb[tid] = cosf(time_b[tid]);
    __syncthreads();
    float acc = bq[tid];
    const float* row = Wq + (size_t)tid * 256 + 128;
    #pragma unroll 8
    for (int j = 0; j < 128; j++) acc += row[j] * cb[j];
    qhc[tid] = acc;
}

// Pt[a][r] = sum_s W1[r][s] * Wo[s][a]  (r<128, a,s<256); also cvec.
__global__ void k_composeP(const float* __restrict__ W1, const float* __restrict__ Wo,
                           const float* __restrict__ bv, const float* __restrict__ bo,
                           float* __restrict__ Pt, float* __restrict__ cvec)
{
    int r = blockIdx.x;           // 0..127
    int a = threadIdx.x;          // 0..255
    __shared__ float w1row[256];
    __shared__ float red[256];
    w1row[a] = W1[(size_t)r * 384 + a];
    __syncthreads();
    float acc = 0.f;
    #pragma unroll 8
    for (int s = 0; s < 256; s++) acc += w1row[s] * Wo[(size_t)s * 256 + a];
    Pt[(size_t)a * 128 + r] = acc;
    red[a] = acc * bv[a] + w1row[a] * bo[a];
    __syncthreads();
    for (int off = 128; off; off >>= 1) {
        if (a < off) red[a] += red[a + off];
        __syncthreads();
    }
    if (a == 0) cvec[r] = red[0];
}

// Bf[r][j]: j<768 -> sum_d Pt[h*128+d][r] * Wv[h*128+d][c]; j>=768 -> W1[r][256+e]
__global__ void k_composeC(const float* __restrict__ Pt, const float* __restrict__ Wv,
                           const float* __restrict__ W1, float* __restrict__ Bf)
{
    int j = blockIdx.x;           // 0..895
    int r = threadIdx.x;          // 0..127
    if (j >= 768) {
        Bf[(size_t)r * 896 + j] = W1[(size_t)r * 384 + 256 + (j - 768)];
        return;
    }
    int h = j / 384, c = j % 384;
    __shared__ float wvcol[128];
    wvcol[r] = Wv[(size_t)(h * 128 + r) * 384 + c];
    __syncthreads();
    float acc = 0.f;
    #pragma unroll 8
    for (int d = 0; d < 128; d++)
        acc += Pt[(size_t)(h * 128 + d) * 128 + r] * wvcol[d];
    Bf[(size_t)r * 896 + j] = acc;
}

// Mu[hc][e] = sum_d K(h,c,d)*Wq[h*128+d][e];  du[hc] = sum_d K(h,c,d)*qhc[h*128+d]
__global__ void k_composeU(const float* __restrict__ Wk, const float* __restrict__ bk,
                           const float* __restrict__ Wq, const float* __restrict__ qhc,
                           float* __restrict__ Mu, float* __restrict__ du)
{
    int hc = blockIdx.x;          // 0..769
    int h = hc / UROW, c = hc % UROW;
    int e = threadIdx.x;          // 0..159 (guard <=128)
    __shared__ float krow[128];
    if (e < 128)
        krow[e] = (c < 384) ? Wk[(size_t)(h * 128 + e) * 384 + c] : bk[h * 128 + e];
    __syncthreads();
    if (e < 128) {
        float acc = 0.f;
        #pragma unroll 8
        for (int d = 0; d < 128; d++)
            acc += krow[d] * Wq[(size_t)(h * 128 + d) * 256 + e];
        Mu[(size_t)hc * 128 + e] = acc;
    } else if (e == 128) {
        float acc = 0.f;
        for (int d = 0; d < 128; d++) acc += krow[d] * qhc[h * 128 + d];
        du[hc] = acc;
    }
}

// ---------------- 128x128 fp32 GEMM with packed FFMA2 ------------------------
// Out[n,r] = sum_c A[n,c]*B[r,c].  256 threads, 8x8 micro-tile, BK=16.
// Inner product uses fma.rn.f32x2: accumulator pairs along r, B pairs read
// straight from smem as 64-bit words, A broadcast-packed via mov.b64 (ALU pipe).
template<bool SPLIT_A, bool RELU, bool BIAS2>
__global__ __launch_bounds__(256, 2)
void gemm128(const float* __restrict__ A, int lda,
             const float* __restrict__ A2, int lda2, int csplit,
             const float* __restrict__ B, int ldb, int Rdim, int Cdim,
             const float* __restrict__ bias, const float* __restrict__ bias2,
             float* __restrict__ Out, int ldc,
             const unsigned char* __restrict__ flags, int Ntot)
{
    __shared__ float As[16][132];
    __shared__ float Bs[16][132];
    const int tid = threadIdx.x;
    const int tx = tid & 15;      // r dir (8 cols each)
    const int ty = tid >> 4;      // n dir (8 rows each)
    const int n0 = blockIdx.x * 128;
    const int r0 = blockIdx.y * 128;

    unsigned long long acc2[8][4];
    #pragma unroll
    for (int i = 0; i < 8; i++)
        #pragma unroll
        for (int j = 0; j < 4; j++) acc2[i][j] = 0ull;

    for (int kt = 0; kt < Cdim; kt += 16) {
        #pragma unroll
        for (int s = 0; s < 2; s++) {
            int l = tid + s * 256;               // 0..511
            int row = l >> 2, c = (l & 3) * 4;
            // A tile
            {
                int n = n0 + row;
                float4 v = make_float4(0.f, 0.f, 0.f, 0.f);
                if (n < Ntot) {
                    int cc = kt + c;
                    const float* p;
                    if (SPLIT_A && cc >= csplit)
                        p = A2 + (size_t)n * lda2 + (cc - csplit);
                    else
                        p = A + (size_t)n * lda + cc;
                    v = *(const float4*)p;
                }
                As[c + 0][row] = v.x; As[c + 1][row] = v.y;
                As[c + 2][row] = v.z; As[c + 3][row] = v.w;
            }
            // B tile
            {
                int r = r0 + row;
                float4 v = make_float4(0.f, 0.f, 0.f, 0.f);
                if (r < Rdim) v = *(const float4*)(B + (size_t)r * ldb + kt + c);
                Bs[c + 0][row] = v.x; Bs[c + 1][row] = v.y;
                Bs[c + 2][row] = v.z; Bs[c + 3][row] = v.w;
            }
        }
        __syncthreads();
        #pragma unroll
        for (int k = 0; k < 16; k++) {
            float a[8];
            *(float4*)&a[0] = *(const float4*)&As[k][ty * 8];
            *(float4*)&a[4] = *(const float4*)&As[k][ty * 8 + 4];
            unsigned long long b2[4];
            const unsigned long long* bp =
                (const unsigned long long*)&Bs[k][tx * 8];
            #pragma unroll
            for (int j = 0; j < 4; j++) b2[j] = bp[j];
            #pragma unroll
            for (int i = 0; i < 8; i++) {
                unsigned long long ad;
                asm("mov.b64 %0, {%1, %1};" : "=l"(ad) : "r"(__float_as_uint(a[i])));
                #pragma unroll
                for (int j = 0; j < 4; j++)
                    asm("fma.rn.f32x2 %0, %1, %2, %0;"
                        : "+l"(acc2[i][j]) : "l"(ad), "l"(b2[j]));
            }
        }
        __syncthreads();
    }

    #pragma unroll
    for (int i = 0; i < 8; i++) {
        int n = n0 + ty * 8 + i;
        if (n >= Ntot) continue;
        bool fl = BIAS2 ? (flags[n] != 0) : false;
        #pragma unroll
        for (int j = 0; j < 4; j++) {
            unsigned lo, hi;
            asm("mov.b64 {%0, %1}, %2;" : "=r"(lo), "=r"(hi) : "l"(acc2[i][j]));
            #pragma unroll
            for (int half = 0; half < 2; half++) {
                int r = r0 + tx * 8 + 2 * j + half;
                if (r >= Rdim) continue;
                float v = __uint_as_float(half ? hi : lo) + bias[r];
                if (BIAS2 && !fl) v += bias2[r];
                if (RELU) v = fmaxf(v, 0.f);
                Out[(size_t)n * ldc + r] = v;
            }
        }
    }
}

// ---------------- fused per-node edge kernel ---------------------------------
__global__ __launch_bounds__(256)
void k_edge(const int* __restrict__ neighbors, const float* __restrict__ t,
            const float* __restrict__ e_t, const int* __restrict__ e_id,
            const void* __restrict__ mask,
            const float* __restrict__ node_feat, const float* __restrict__ memory,
            const float* __restrict__ event_feat,
            const float* __restrict__ time_w, const float* __restrict__ time_b,
            const float* __restrict__ u, float* __restrict__ mixed,
            unsigned char* __restrict__ flags, int Ntot)
{
    int n = blockIdx.x;
    if (n >= Ntot) return;
    int tid = threadIdx.x;
    int lane = tid & 31, warp = tid >> 5;
    const int isb = g_mask_is_byte;

    __shared__ float kvc[KNB][DKF];
    __shared__ float usf[770];
    __shared__ float tw[128], tb[128];
    __shared__ float attn[2][KNB];
    __shared__ float sc[2][KNB];
    __shared__ int s_nonb;

    if (tid < 128) { tw[tid] = time_w[tid]; tb[tid] = time_b[tid]; }
    for (int i = tid; i < 770; i += 256) usf[i] = u[(size_t)n * 770 + i];
    if (warp == 0) {
        unsigned mbit = 0;
        if (lane < KNB) mbit = mget(mask, n * KNB + lane, isb) ? 1u : 0u;
        unsigned any = __ballot_sync(0xffffffffu, mbit != 0);
        if (lane == 0) s_nonb = (any == 0) ? 1 : 0;
    }
    __syncthreads();

    float tn = t[n];
    for (int k = warp; k < KNB; k += 8) {
        int nb = neighbors[n * KNB + k];
        int mk = mget(mask, n * KNB + k, isb);
        float dt = tn - e_t[n * KNB + k];
        int eid = e_id[n * KNB + k];
        const float4* nf4 = (const float4*)(node_feat + (size_t)nb * 128);
        const float4* mm4 = (const float4*)(memory + (size_t)nb * 128);
        const float4* ef4 = (const float4*)(event_feat + (size_t)eid * 128);
        for (int c4 = lane; c4 < 96; c4 += 32) {
            float4 v;
            if (c4 < 32) {
                if (mk) {
                    float4 a = nf4[c4], b = mm4[c4];
                    v = make_float4(a.x + b.x, a.y + b.y, a.z + b.z, a.w + b.w);
                } else {
                    v = make_float4(0.f, 0.f, 0.f, 0.f);
                }
            } else if (c4 < 64) {
                int j = (c4 - 32) * 4;
                v.x = cosf(__fadd_rn(__fmul_rn(dt, tw[j + 0]), tb[j + 0]));
                v.y = cosf(__fadd_rn(__fmul_rn(dt, tw[j + 1]), tb[j + 1]));
                v.z = cosf(__fadd_rn(__fmul_rn(dt, tw[j + 2]), tb[j + 2]));
                v.w = cosf(__fadd_rn(__fmul_rn(dt, tw[j + 3]), tb[j + 3]));
            } else {
                v = ef4[c4 - 64];
            }
            *(float4*)&kvc[k][c4 * 4] = v;
        }
    }
    __syncthreads();

    for (int p = warp; p < 2 * KNB; p += 8) {
        int h = p / KNB, k = p % KNB;
        float s = 0.f;
        const float* uh = &usf[h * UROW];
        #pragma unroll 4
        for (int c = lane; c < DKF; c += 32) s += uh[c] * kvc[k][c];
        #pragma unroll
        for (int off = 16; off; off >>= 1) s += __shfl_down_sync(0xffffffffu, s, off);
        if (lane == 0) sc[h][k] = (s + uh[384]) * 0.08838834764831845f;
    }
    __syncthreads();

    if (warp < 2) {
        int h = warp;
        int valid = 0;
        float s = -INFINITY;
        if (lane < KNB) {
            valid = mget(mask, n * KNB + lane, isb) || s_nonb;
            if (valid) s = sc[h][lane];
        }
        float m = s;
        #pragma unroll
        for (int off = 16; off; off >>= 1) m = fmaxf(m, __shfl_xor_sync(0xffffffffu, m, off));
        float e = (lane < KNB && valid) ? expf(s - m) : 0.f;
        float sum = e;
        #pragma unroll
        for (int off = 16; off; off >>= 1) sum += __shfl_xor_sync(0xffffffffu, sum, off);
        if (lane < KNB) attn[h][lane] = e / sum;
    }
    __syncthreads();

    float gate = s_nonb ? 0.f : 1.f;
    for (int i = tid; i < 2 * DKF; i += 256) {
        int h = i / DKF, j = i % DKF;
        float acc = 0.f;
        #pragma unroll
        for (int k = 0; k < KNB; k++) acc += attn[h][k] * kvc[k][j];
        mixed[(size_t)n * 768 + i] = acc * gate;
    }
    if (tid == 0) flags[n] = (unsigned char)s_nonb;
}

// ---------------- launch ------------------------------------------------------
extern "C" void kernel_launch(void* const* d_in, const int* in_sizes, int n_in,
                              void* d_out, int out_size)
{
    const int*   idx        = (const int*)d_in[0];
    const float* t          = (const float*)d_in[1];
    const int*   neighbors  = (const int*)d_in[2];
    const float* e_t        = (const float*)d_in[3];
    const int*   e_id       = (const int*)d_in[4];
    const void*  mask       = d_in[5];
    const float* node_feat  = (const float*)d_in[6];
    const float* memory     = (const float*)d_in[7];
    const float* event_feat = (const float*)d_in[8];
    const float* time_w     = (const float*)d_in[9];
    const float* time_b     = (const float*)d_in[10];
    const float* Wq = (const float*)d_in[11];
    const float* bq = (const float*)d_in[12];
    const float* Wk = (const float*)d_in[13];
    const float* bk = (const float*)d_in[14];
    const float* Wv = (const float*)d_in[15];
    const float* bv = (const float*)d_in[16];
    const float* Wo = (const float*)d_in[17];
    const float* bo = (const float*)d_in[18];
    const float* W1 = (const float*)d_in[19];
    const float* b1 = (const float*)d_in[20];
    const float* W2 = (const float*)d_in[21];
    const float* b2 = (const float*)d_in[22];
    float* out = (float*)d_out;

    int N = in_sizes[0];
    if (N > NN) N = NN;

    float *qbuf, *bufA, *bufB, *bufC, *qhc, *Mu, *du, *Pt, *Bf, *cvec;
    unsigned char* flags;
    cudaGetSymbolAddress((void**)&qbuf, g_qbuf);
    cudaGetSymbolAddress((void**)&bufA, g_bufA);
    cudaGetSymbolAddress((void**)&bufB, g_bufB);
    cudaGetSymbolAddress((void**)&bufC, g_bufC);
    cudaGetSymbolAddress((void**)&qhc, g_qhconst);
    cudaGetSymbolAddress((void**)&Mu, g_Mu);
    cudaGetSymbolAddress((void**)&du, g_du);
    cudaGetSymbolAddress((void**)&Pt, g_Pt);
    cudaGetSymbolAddress((void**)&Bf, g_Bf);
    cudaGetSymbolAddress((void**)&cvec, g_cvec);
    cudaGetSymbolAddress((void**)&flags, g_flags);

    int gx = (N + 127) / 128;

    // setup & compose
    k_qhconst<<<1, 256>>>(Wq, bq, time_b, qhc);
    k_composeP<<<128, 256>>>(W1, Wo, bv, bo, Pt, cvec);
    k_composeC<<<896, 128>>>(Pt, Wv, W1, Bf);
    k_composeU<<<770, 160>>>(Wk, bk, Wq, qhc, Mu, du);
    k_gatherq<<<(N * 32 + 255) / 256, 256>>>(idx, node_feat, memory, qbuf, N);

    // u = Mu @ q + du   -> bufB (N x 770)
    gemm128<false, false, false><<<dim3(gx, 7), 256>>>(
        qbuf, 128, nullptr, 0, 0, Mu, 128, 770, 128, du, nullptr, bufB, 770, nullptr, N);

    // mask probe
    k_flagreset<<<1, 1>>>();
    k_maskprobe<<<32, 256>>>((const unsigned char*)mask, 8192);

    // fused gather + time-encode + scores + softmax + mix -> bufC (N x 768)
    k_edge<<<N, 256>>>(neighbors, t, e_t, e_id, mask, node_feat, memory,
                       event_feat, time_w, time_b, bufB, bufC, flags, N);

    // h1 = relu(Bf @ [mixed, q] + b1 + gated cvec) -> bufA (N x 128)
    gemm128<true, true, true><<<dim3(gx, 1), 256>>>(
        bufC, 768, qbuf, 128, 768, Bf, 896, 128, 896, b1, cvec, bufA, 128, flags, N);

    // out = h1 @ W2^T + b2 -> d_out (N x 128)
    gemm128<false, false, false><<<dim3(gx, 1), 256>>>(
        bufA, 128, nullptr, 0, 0, W2, 128, 128, 128, b2, nullptr, out, 128, nullptr, N);
}

// round 6
// speedup vs baseline: 1.5730x; 1.2226x over previous
#include <cuda_runtime.h>
#include <cuda_bf16.h>
#include <math.h>
#include <stdint.h>

#define NN    100000
#define KNB   20
#define DKF   384
#define UROW  385

// ================= device scratch =================
__device__ float g_u[(size_t)NN * 770];          // u (2x385) f32, read by k_edge
__device__ uint4 g_qh[(size_t)NN * 16];          // q hi  (N x 128 bf16)
__device__ uint4 g_ql[(size_t)NN * 16];          // q lo
__device__ uint4 g_mh[(size_t)NN * 96];          // mixed hi (N x 768 bf16)
__device__ uint4 g_ml[(size_t)NN * 96];          // mixed lo
__device__ uint4 g_h1h[(size_t)NN * 16];         // h1 hi (N x 128 bf16)
__device__ uint4 g_h1l[(size_t)NN * 16];         // h1 lo
__device__ uint4 g_Muh[14336], g_Mul[14336];     // Mu 896(pad 770) x 128 bf16
__device__ uint4 g_Bfh[14336], g_Bfl[14336];     // Bf 128 x 896 bf16
__device__ uint4 g_W2h[2048], g_W2l[2048];       // W2 128 x 128 bf16
__device__ float g_du[896];
__device__ float g_Pt[256 * 128];
__device__ float g_cvec[128];
__device__ float g_qhc[256];
__device__ unsigned char g_flags[NN];
__device__ int   g_mask_is_byte;

// ================= PTX helpers (baseline features only) =================
__device__ __forceinline__ uint32_t smem_u32(const void* p) {
    uint32_t r;
    asm("{ .reg .u64 t; cvta.to.shared.u64 t, %1; cvt.u32.u64 %0, t; }" : "=r"(r) : "l"(p));
    return r;
}
__device__ __forceinline__ void ldm_x4(uint32_t* r, uint32_t addr) {
    asm volatile("ldmatrix.sync.aligned.m8n8.x4.shared.b16 {%0,%1,%2,%3}, [%4];"
                 : "=r"(r[0]), "=r"(r[1]), "=r"(r[2]), "=r"(r[3]) : "r"(addr));
}
__device__ __forceinline__ void ldm_x2(uint32_t* r, uint32_t addr) {
    asm volatile("ldmatrix.sync.aligned.m8n8.x2.shared.b16 {%0,%1}, [%2];"
                 : "=r"(r[0]), "=r"(r[1]) : "r"(addr));
}
__device__ __forceinline__ void mma16816(float* c, const uint32_t* a, const uint32_t* b) {
    asm volatile("mma.sync.aligned.m16n8k16.row.col.f32.bf16.bf16.f32 "
        "{%0,%1,%2,%3}, {%4,%5,%6,%7}, {%8,%9}, {%0,%1,%2,%3};"
        : "+f"(c[0]), "+f"(c[1]), "+f"(c[2]), "+f"(c[3])
        : "r"(a[0]), "r"(a[1]), "r"(a[2]), "r"(a[3]), "r"(b[0]), "r"(b[1]));
}

// ================= mask layout probe =================
__global__ void k_flagreset() { g_mask_is_byte = 0; }
__global__ void k_maskprobe(const unsigned char* __restrict__ m, int nbytes) {
    int i = blockIdx.x * 256 + threadIdx.x;
    if (i < nbytes && (i & 3) != 0 && m[i] != 0) g_mask_is_byte = 1;
}
__device__ __forceinline__ int mget(const void* m, int i, int isbyte) {
    return isbyte ? (((const unsigned char*)m)[i] != 0) : (((const int*)m)[i] != 0);
}

// ================= setup / compose =================
__device__ __forceinline__ void split_store(__nv_bfloat16* ph, __nv_bfloat16* pl, size_t i, float v) {
    __nv_bfloat16 h = __float2bfloat16(v);
    ph[i] = h;
    pl[i] = __float2bfloat16(v - __bfloat162float(h));
}

__global__ void k_gatherq(const int* __restrict__ idx, const float* __restrict__ nf,
                          const float* __restrict__ mem,
                          __nv_bfloat16* __restrict__ qh, __nv_bfloat16* __restrict__ ql, int n)
{
    int i = blockIdx.x * 256 + threadIdx.x;    // over n*32 float4s
    if (i >= n * 32) return;
    int node = i >> 5, c4 = i & 31;
    int src = idx[node];
    float4 a = ((const float4*)nf)[(size_t)src * 32 + c4];
    float4 b = ((const float4*)mem)[(size_t)src * 32 + c4];
    float v[4] = { a.x + b.x, a.y + b.y, a.z + b.z, a.w + b.w };
    size_t base = (size_t)i * 4;
    #pragma unroll
    for (int j = 0; j < 4; j++) split_store(qh, ql, base + j, v[j]);
}

__global__ void k_qhconst(const float* __restrict__ Wq, const float* __restrict__ bq,
                          const float* __restrict__ time_b, float* __restrict__ qhc)
{
    __shared__ float cb[128];
    int tid = threadIdx.x;
    if (tid < 128) cb[tid] = cosf(time_b[tid]);
    __syncthreads();
    float acc = bq[tid];
    const float* row = Wq + (size_t)tid * 256 + 128;
    #pragma unroll 8
    for (int j = 0; j < 128; j++) acc += row[j] * cb[j];
    qhc[tid] = acc;
}

__global__ void k_composeP(const float* __restrict__ W1, const float* __restrict__ Wo,
                           const float* __restrict__ bv, const float* __restrict__ bo,
                           float* __restrict__ Pt, float* __restrict__ cvec)
{
    int r = blockIdx.x;           // 0..127
    int a = threadIdx.x;          // 0..255
    __shared__ float w1row[256];
    __shared__ float red[256];
    w1row[a] = W1[(size_t)r * 384 + a];
    __syncthreads();
    float acc = 0.f;
    #pragma unroll 8
    for (int s = 0; s < 256; s++) acc += w1row[s] * Wo[(size_t)s * 256 + a];
    Pt[(size_t)a * 128 + r] = acc;
    red[a] = acc * bv[a] + w1row[a] * bo[a];
    __syncthreads();
    for (int off = 128; off; off >>= 1) {
        if (a < off) red[a] += red[a + off];
        __syncthreads();
    }
    if (a == 0) cvec[r] = red[0];
}

__global__ void k_composeC(const float* __restrict__ Pt, const float* __restrict__ Wv,
                           const float* __restrict__ W1,
                           __nv_bfloat16* __restrict__ Bh, __nv_bfloat16* __restrict__ Bl)
{
    int j = blockIdx.x;           // 0..895
    int r = threadIdx.x;          // 0..127
    if (j >= 768) {
        split_store(Bh, Bl, (size_t)r * 896 + j, W1[(size_t)r * 384 + 256 + (j - 768)]);
        return;
    }
    int h = j / 384, c = j % 384;
    __shared__ float wvcol[128];
    wvcol[r] = Wv[(size_t)(h * 128 + r) * 384 + c];
    __syncthreads();
    float acc = 0.f;
    #pragma unroll 8
    for (int d = 0; d < 128; d++)
        acc += Pt[(size_t)(h * 128 + d) * 128 + r] * wvcol[d];
    split_store(Bh, Bl, (size_t)r * 896 + j, acc);
}

__global__ void k_composeU(const float* __restrict__ Wk, const float* __restrict__ bk,
                           const float* __restrict__ Wq, const float* __restrict__ qhc,
                           __nv_bfloat16* __restrict__ Mh, __nv_bfloat16* __restrict__ Ml,
                           float* __restrict__ du)
{
    int hc = blockIdx.x;          // 0..769
    int h = hc / UROW, c = hc % UROW;
    int e = threadIdx.x;          // 0..159
    __shared__ float krow[128];
    if (e < 128)
        krow[e] = (c < 384) ? Wk[(size_t)(h * 128 + e) * 384 + c] : bk[h * 128 + e];
    __syncthreads();
    if (e < 128) {
        float acc = 0.f;
        #pragma unroll 8
        for (int d = 0; d < 128; d++)
            acc += krow[d] * Wq[(size_t)(h * 128 + d) * 256 + e];
        split_store(Mh, Ml, (size_t)hc * 128 + e, acc);
    } else if (e == 128) {
        float acc = 0.f;
        for (int d = 0; d < 128; d++) acc += krow[d] * qhc[h * 128 + d];
        du[hc] = acc;
    }
}

__global__ void k_splitW2(const float* __restrict__ W2,
                          __nv_bfloat16* __restrict__ wh, __nv_bfloat16* __restrict__ wl)
{
    int i = blockIdx.x * 256 + threadIdx.x;
    if (i < 128 * 128) split_store(wh, wl, i, W2[i]);
}

// ================= HMMA GEMM (mma.sync bf16, split hi/lo 3-term) =============
// Out[n,r] = sum_c A[n,c]*B[r,c].  CTA tile 128x128, BK=32, 8 warps (64x32 each).
// EPI: 0 = u (f32 + bias, Rtot guard), 1 = h1 (bias + gated cvec, relu, bf16
// split out), 2 = final (f32 + bias).
#define LDS_STRIDE 40   // bf16 elements; 80B rows -> ldmatrix conflict-free

template<int EPI>
__global__ __launch_bounds__(256)
void mma_gemm(const __nv_bfloat16* __restrict__ Ah, const __nv_bfloat16* __restrict__ Al, int lda,
              const __nv_bfloat16* __restrict__ A2h, const __nv_bfloat16* __restrict__ A2l, int lda2, int ksplit,
              const __nv_bfloat16* __restrict__ Bh, const __nv_bfloat16* __restrict__ Bl, int ldb,
              int ktiles, int Rtot,
              const float* __restrict__ bias, const float* __restrict__ bias2,
              const unsigned char* __restrict__ flags,
              float* __restrict__ OutF, int ldc,
              __nv_bfloat16* __restrict__ OutH, __nv_bfloat16* __restrict__ OutL, int Ntot)
{
    __shared__ __nv_bfloat16 AsH[128 * LDS_STRIDE];
    __shared__ __nv_bfloat16 AsL[128 * LDS_STRIDE];
    __shared__ __nv_bfloat16 BsH[128 * LDS_STRIDE];
    __shared__ __nv_bfloat16 BsL[128 * LDS_STRIDE];

    const int tid = threadIdx.x;
    const int lane = tid & 31, wid = tid >> 5;
    const int wm = wid >> 2, wn = wid & 3;      // 2 x 4 warp grid
    const int m0 = blockIdx.x * 128;
    const int r0 = blockIdx.y * 128;

    const uint32_t sAH = smem_u32(AsH), sAL = smem_u32(AsL);
    const uint32_t sBH = smem_u32(BsH), sBL = smem_u32(BsL);

    int vrows = Ntot - m0;
    if (vrows > 128) vrows = 128;
    if (vrows < 0) vrows = 0;

    float acc[4][4][4];
    #pragma unroll
    for (int a = 0; a < 4; a++)
        #pragma unroll
        for (int b = 0; b < 4; b++)
            #pragma unroll
            for (int c = 0; c < 4; c++) acc[a][b][c] = 0.f;

    // ldmatrix source addresses (constant across k-tiles except ks offset)
    const int arow = wm * 64 + (lane & 15);
    const int acolsel = ((lane >> 4) & 1) * 8;
    const int l16 = lane & 15;
    const int brow = wn * 32 + (l16 & 7);
    const int bcolsel = ((l16 >> 3) & 1) * 8;

    for (int kt = 0; kt < ktiles; kt++) {
        // ---- global -> smem ----
        const __nv_bfloat16 *sh, *sl; int st, k0;
        if (kt < ksplit) { sh = Ah;  sl = Al;  st = lda;  k0 = kt * 32; }
        else             { sh = A2h; sl = A2l; st = lda2; k0 = (kt - ksplit) * 32; }
        #pragma unroll
        for (int i = 0; i < 2; i++) {
            int u = tid + i * 256;              // 0..511
            int row = u >> 2, c8 = (u & 3) * 8;
            uint4 vh = make_uint4(0u, 0u, 0u, 0u), vl = vh;
            if (row < vrows) {
                vh = *(const uint4*)(sh + (size_t)(m0 + row) * st + k0 + c8);
                vl = *(const uint4*)(sl + (size_t)(m0 + row) * st + k0 + c8);
            }
            *(uint4*)&AsH[row * LDS_STRIDE + c8] = vh;
            *(uint4*)&AsL[row * LDS_STRIDE + c8] = vl;
            uint4 wh = *(const uint4*)(Bh + (size_t)(r0 + row) * ldb + kt * 32 + c8);
            uint4 wl = *(const uint4*)(Bl + (size_t)(r0 + row) * ldb + kt * 32 + c8);
            *(uint4*)&BsH[row * LDS_STRIDE + c8] = wh;
            *(uint4*)&BsL[row * LDS_STRIDE + c8] = wl;
        }
        __syncthreads();

        // ---- compute: 2 k16 steps ----
        #pragma unroll
        for (int ks = 0; ks < 2; ks++) {
            const int acol = ks * 16 + acolsel;
            const int bcol = ks * 16 + bcolsel;
            uint32_t af[4][4], bhf[4][2], blf[4][2];
            #pragma unroll
            for (int mi = 0; mi < 4; mi++)
                ldm_x4(af[mi], sAH + (uint32_t)(((arow + mi * 16) * LDS_STRIDE + acol) * 2));
            #pragma unroll
            for (int ni = 0; ni < 4; ni++) {
                ldm_x2(bhf[ni], sBH + (uint32_t)(((brow + ni * 8) * LDS_STRIDE + bcol) * 2));
                ldm_x2(blf[ni], sBL + (uint32_t)(((brow + ni * 8) * LDS_STRIDE + bcol) * 2));
            }
            #pragma unroll
            for (int mi = 0; mi < 4; mi++)
                #pragma unroll
                for (int ni = 0; ni < 4; ni++) {
                    mma16816(acc[mi][ni], af[mi], bhf[ni]);   // Ah*Bh
                    mma16816(acc[mi][ni], af[mi], blf[ni]);   // Ah*Bl
                }
            #pragma unroll
            for (int mi = 0; mi < 4; mi++)
                ldm_x4(af[mi], sAL + (uint32_t)(((arow + mi * 16) * LDS_STRIDE + acol) * 2));
            #pragma unroll
            for (int mi = 0; mi < 4; mi++)
                #pragma unroll
                for (int ni = 0; ni < 4; ni++)
                    mma16816(acc[mi][ni], af[mi], bhf[ni]);   // Al*Bh
        }
        __syncthreads();
    }

    // ---- epilogue ----
    #pragma unroll
    for (int mi = 0; mi < 4; mi++) {
        int nrow0 = m0 + wm * 64 + mi * 16 + (lane >> 2);
        #pragma unroll
        for (int half = 0; half < 2; half++) {
            int n = nrow0 + half * 8;
            if (n >= Ntot) continue;
            bool fl = false;
            if (EPI == 1) fl = (flags[n] != 0);
            #pragma unroll
            for (int ni = 0; ni < 4; ni++) {
                int r = r0 + wn * 32 + ni * 8 + (lane & 3) * 2;
                float v0 = acc[mi][ni][half * 2 + 0];
                float v1 = acc[mi][ni][half * 2 + 1];
                if (EPI == 0) {
                    if (r < Rtot)     OutF[(size_t)n * ldc + r]     = v0 + bias[r];
                    if (r + 1 < Rtot) OutF[(size_t)n * ldc + r + 1] = v1 + bias[r + 1];
                } else if (EPI == 1) {
                    v0 += bias[r]     + (fl ? 0.f : bias2[r]);
                    v1 += bias[r + 1] + (fl ? 0.f : bias2[r + 1]);
                    v0 = fmaxf(v0, 0.f);
                    v1 = fmaxf(v1, 0.f);
                    __nv_bfloat16 h0 = __float2bfloat16(v0), h1 = __float2bfloat16(v1);
                    *(__nv_bfloat162*)(OutH + (size_t)n * 128 + r) = __halves2bfloat162(h0, h1);
                    __nv_bfloat16 l0 = __float2bfloat16(v0 - __bfloat162float(h0));
                    __nv_bfloat16 l1 = __float2bfloat16(v1 - __bfloat162float(h1));
                    *(__nv_bfloat162*)(OutL + (size_t)n * 128 + r) = __halves2bfloat162(l0, l1);
                } else {
                    OutF[(size_t)n * ldc + r]     = v0 + bias[r];
                    OutF[(size_t)n * ldc + r + 1] = v1 + bias[r + 1];
                }
            }
        }
    }
}

// ================= fused per-node edge kernel =================
__global__ __launch_bounds__(256)
void k_edge(const int* __restrict__ neighbors, const float* __restrict__ t,
            const float* __restrict__ e_t, const int* __restrict__ e_id,
            const void* __restrict__ mask,
            const float* __restrict__ node_feat, const float* __restrict__ memory,
            const float* __restrict__ event_feat,
            const float* __restrict__ time_w, const float* __restrict__ time_b,
            const float* __restrict__ u,
            __nv_bfloat16* __restrict__ mixh, __nv_bfloat16* __restrict__ mixl,
            unsigned char* __restrict__ flags, int Ntot)
{
    int n = blockIdx.x;
    if (n >= Ntot) return;
    int tid = threadIdx.x;
    int lane = tid & 31, warp = tid >> 5;
    const int isb = g_mask_is_byte;

    __shared__ float kvc[KNB][DKF];
    __shared__ float usf[770];
    __shared__ float tw[128], tb[128];
    __shared__ float attn[2][KNB];
    __shared__ float sc[2][KNB];
    __shared__ int s_nonb;

    if (tid < 128) { tw[tid] = time_w[tid]; tb[tid] = time_b[tid]; }
    for (int i = tid; i < 770; i += 256) usf[i] = u[(size_t)n * 770 + i];
    if (warp == 0) {
        unsigned mbit = 0;
        if (lane < KNB) mbit = mget(mask, n * KNB + lane, isb) ? 1u : 0u;
        unsigned any = __ballot_sync(0xffffffffu, mbit != 0);
        if (lane == 0) s_nonb = (any == 0) ? 1 : 0;
    }
    __syncthreads();

    float tn = t[n];
    for (int k = warp; k < KNB; k += 8) {
        int nb = neighbors[n * KNB + k];
        int mk = mget(mask, n * KNB + k, isb);
        float dt = tn - e_t[n * KNB + k];
        int eid = e_id[n * KNB + k];
        const float4* nf4 = (const float4*)(node_feat + (size_t)nb * 128);
        const float4* mm4 = (const float4*)(memory + (size_t)nb * 128);
        const float4* ef4 = (const float4*)(event_feat + (size_t)eid * 128);
        for (int c4 = lane; c4 < 96; c4 += 32) {
            float4 v;
            if (c4 < 32) {
                if (mk) {
                    float4 a = nf4[c4], b = mm4[c4];
                    v = make_float4(a.x + b.x, a.y + b.y, a.z + b.z, a.w + b.w);
                } else {
                    v = make_float4(0.f, 0.f, 0.f, 0.f);
                }
            } else if (c4 < 64) {
                int j = (c4 - 32) * 4;
                v.x = cosf(__fadd_rn(__fmul_rn(dt, tw[j + 0]), tb[j + 0]));
                v.y = cosf(__fadd_rn(__fmul_rn(dt, tw[j + 1]), tb[j + 1]));
                v.z = cosf(__fadd_rn(__fmul_rn(dt, tw[j + 2]), tb[j + 2]));
                v.w = cosf(__fadd_rn(__fmul_rn(dt, tw[j + 3]), tb[j + 3]));
            } else {
                v = ef4[c4 - 64];
            }
            *(float4*)&kvc[k][c4 * 4] = v;
        }
    }
    __syncthreads();

    for (int p = warp; p < 2 * KNB; p += 8) {
        int h = p / KNB, k = p % KNB;
        float s = 0.f;
        const float* uh = &usf[h * UROW];
        #pragma unroll 4
        for (int c = lane; c < DKF; c += 32) s += uh[c] * kvc[k][c];
        #pragma unroll
        for (int off = 16; off; off >>= 1) s += __shfl_down_sync(0xffffffffu, s, off);
        if (lane == 0) sc[h][k] = (s + uh[384]) * 0.08838834764831845f;
    }
    __syncthreads();

    if (warp < 2) {
        int h = warp;
        int valid = 0;
        float s = -INFINITY;
        if (lane < KNB) {
            valid = mget(mask, n * KNB + lane, isb) || s_nonb;
            if (valid) s = sc[h][lane];
        }
        float m = s;
        #pragma unroll
        for (int off = 16; off; off >>= 1) m = fmaxf(m, __shfl_xor_sync(0xffffffffu, m, off));
        float e = (lane < KNB && valid) ? expf(s - m) : 0.f;
        float sum = e;
        #pragma unroll
        for (int off = 16; off; off >>= 1) sum += __shfl_xor_sync(0xffffffffu, sum, off);
        if (lane < KNB) attn[h][lane] = e / sum;
    }
    __syncthreads();

    float gate = s_nonb ? 0.f : 1.f;
    for (int i = tid; i < 2 * DKF; i += 256) {
        int h = i / DKF, j = i % DKF;
        float acc = 0.f;
        #pragma unroll
        for (int k = 0; k < KNB; k++) acc += attn[h][k] * kvc[k][j];
        float m = acc * gate;
        __nv_bfloat16 hh = __float2bfloat16(m);
        mixh[(size_t)n * 768 + i] = hh;
        mixl[(size_t)n * 768 + i] = __float2bfloat16(m - __bfloat162float(hh));
    }
    if (tid == 0) flags[n] = (unsigned char)s_nonb;
}

// ================= launch =================
extern "C" void kernel_launch(void* const* d_in, const int* in_sizes, int n_in,
                              void* d_out, int out_size)
{
    const int*   idx        = (const int*)d_in[0];
    const float* t          = (const float*)d_in[1];
    const int*   neighbors  = (const int*)d_in[2];
    const float* e_t        = (const float*)d_in[3];
    const int*   e_id       = (const int*)d_in[4];
    const void*  mask       = d_in[5];
    const float* node_feat  = (const float*)d_in[6];
    const float* memory     = (const float*)d_in[7];
    const float* event_feat = (const float*)d_in[8];
    const float* time_w     = (const float*)d_in[9];
    const float* time_b     = (const float*)d_in[10];
    const float* Wq = (const float*)d_in[11];
    const float* bq = (const float*)d_in[12];
    const float* Wk = (const float*)d_in[13];
    const float* bk = (const float*)d_in[14];
    const float* Wv = (const float*)d_in[15];
    const float* bv = (const float*)d_in[16];
    const float* Wo = (const float*)d_in[17];
    const float* bo = (const float*)d_in[18];
    const float* W1 = (const float*)d_in[19];
    const float* b1 = (const float*)d_in[20];
    const float* W2 = (const float*)d_in[21];
    const float* b2 = (const float*)d_in[22];
    float* out = (float*)d_out;

    int N = in_sizes[0];
    if (N > NN) N = NN;

    float *u, *du, *Pt, *cvec, *qhc;
    __nv_bfloat16 *qh, *ql, *mh, *ml, *h1h, *h1l, *Muh, *Mul, *Bfh, *Bfl, *W2h, *W2l;
    unsigned char* flags;
    cudaGetSymbolAddress((void**)&u, g_u);
    cudaGetSymbolAddress((void**)&du, g_du);
    cudaGetSymbolAddress((void**)&Pt, g_Pt);
    cudaGetSymbolAddress((void**)&cvec, g_cvec);
    cudaGetSymbolAddress((void**)&qhc, g_qhc);
    cudaGetSymbolAddress((void**)&qh, g_qh);
    cudaGetSymbolAddress((void**)&ql, g_ql);
    cudaGetSymbolAddress((void**)&mh, g_mh);
    cudaGetSymbolAddress((void**)&ml, g_ml);
    cudaGetSymbolAddress((void**)&h1h, g_h1h);
    cudaGetSymbolAddress((void**)&h1l, g_h1l);
    cudaGetSymbolAddress((void**)&Muh, g_Muh);
    cudaGetSymbolAddress((void**)&Mul, g_Mul);
    cudaGetSymbolAddress((void**)&Bfh, g_Bfh);
    cudaGetSymbolAddress((void**)&Bfl, g_Bfl);
    cudaGetSymbolAddress((void**)&W2h, g_W2h);
    cudaGetSymbolAddress((void**)&W2l, g_W2l);
    cudaGetSymbolAddress((void**)&flags, g_flags);

    int mtiles = (N + 127) / 128;

    // launches 0..2 (keeps the u-GEMM as profiled launch index 3)
    k_qhconst<<<1, 256>>>(Wq, bq, time_b, qhc);
    k_composeU<<<770, 160>>>(Wk, bk, Wq, qhc, Muh, Mul, du);
    k_gatherq<<<(N * 32 + 255) / 256, 256>>>(idx, node_feat, memory, qh, ql, N);

    // 3: u = Mu @ q + du  -> g_u (N x 770)   K=128 (4 k-tiles), R=770 (7 r-tiles)
    mma_gemm<0><<<dim3(mtiles, 7), 256>>>(
        qh, ql, 128, nullptr, nullptr, 0, 1000,
        Muh, Mul, 128, 4, 770,
        du, nullptr, nullptr, u, 770, nullptr, nullptr, N);

    // 4..8
    k_composeP<<<128, 256>>>(W1, Wo, bv, bo, Pt, cvec);
    k_composeC<<<896, 128>>>(Pt, Wv, W1, Bfh, Bfl);
    k_splitW2<<<64, 256>>>(W2, W2h, W2l);
    k_flagreset<<<1, 1>>>();
    k_maskprobe<<<32, 256>>>((const unsigned char*)mask, 8192);

    // 9: fused edge kernel -> mixed hi/lo (N x 768)
    k_edge<<<N, 256>>>(neighbors, t, e_t, e_id, mask, node_feat, memory,
                       event_feat, time_w, time_b, u, mh, ml, flags, N);

    // 10: h1 = relu(Bf @ [mixed, q] + b1 + gated cvec) -> h1 hi/lo (N x 128)
    //     K = 768 (mixed, 24 tiles) + 128 (q, 4 tiles) = 28 k-tiles
    mma_gemm<1><<<dim3(mtiles, 1), 256>>>(
        mh, ml, 768, qh, ql, 128, 24,
        Bfh, Bfl, 896, 28, 128,
        b1, cvec, flags, nullptr, 0, h1h, h1l, N);

    // 11: out = h1 @ W2^T + b2 -> d_out (N x 128)   K=128 (4 k-tiles)
    mma_gemm<2><<<dim3(mtiles, 1), 256>>>(
        h1h, h1l, 128, nullptr, nullptr, 0, 1000,
        W2h, W2l, 128, 4, 128,
        b2, nullptr, nullptr, out, 128, nullptr, nullptr, N);
}

// round 7
// speedup vs baseline: 1.7118x; 1.0882x over previous
#include <cuda_runtime.h>
#include <cuda_bf16.h>
#include <math.h>
#include <stdint.h>

#define NN    100000
#define KNB   20
#define DKF   384
#define UROW  385

// ================= device scratch =================
__device__ float g_u[(size_t)NN * 770];          // u (2x385) f32, read by k_edge
__device__ uint4 g_qh[(size_t)NN * 16];          // q hi  (N x 128 bf16)
__device__ uint4 g_ql[(size_t)NN * 16];          // q lo
__device__ uint4 g_mh[(size_t)NN * 96];          // mixed hi (N x 768 bf16)
__device__ uint4 g_ml[(size_t)NN * 96];          // mixed lo
__device__ uint4 g_h1h[(size_t)NN * 16];         // h1 hi (N x 128 bf16)
__device__ uint4 g_h1l[(size_t)NN * 16];         // h1 lo
__device__ uint4 g_Muh[14336], g_Mul[14336];     // Mu 896(pad 770) x 128 bf16
__device__ uint4 g_Bfh[14336], g_Bfl[14336];     // Bf 128 x 896 bf16
__device__ uint4 g_W2h[2048], g_W2l[2048];       // W2 128 x 128 bf16
__device__ float g_du[896];
__device__ float g_Pt[256 * 128];
__device__ float g_cvec[128];
__device__ float g_qhc[256];
__device__ unsigned char g_flags[NN];
__device__ int   g_mask_is_byte;

// ================= PTX helpers (baseline features only) =================
__device__ __forceinline__ uint32_t smem_u32(const void* p) {
    uint32_t r;
    asm("{ .reg .u64 t; cvta.to.shared.u64 t, %1; cvt.u32.u64 %0, t; }" : "=r"(r) : "l"(p));
    return r;
}
__device__ __forceinline__ void ldm_x4(uint32_t* r, uint32_t addr) {
    asm volatile("ldmatrix.sync.aligned.m8n8.x4.shared.b16 {%0,%1,%2,%3}, [%4];"
                 : "=r"(r[0]), "=r"(r[1]), "=r"(r[2]), "=r"(r[3]) : "r"(addr));
}
__device__ __forceinline__ void ldm_x2(uint32_t* r, uint32_t addr) {
    asm volatile("ldmatrix.sync.aligned.m8n8.x2.shared.b16 {%0,%1}, [%2];"
                 : "=r"(r[0]), "=r"(r[1]) : "r"(addr));
}
__device__ __forceinline__ void mma16816(float* c, const uint32_t* a, const uint32_t* b) {
    asm volatile("mma.sync.aligned.m16n8k16.row.col.f32.bf16.bf16.f32 "
        "{%0,%1,%2,%3}, {%4,%5,%6,%7}, {%8,%9}, {%0,%1,%2,%3};"
        : "+f"(c[0]), "+f"(c[1]), "+f"(c[2]), "+f"(c[3])
        : "r"(a[0]), "r"(a[1]), "r"(a[2]), "r"(a[3]), "r"(b[0]), "r"(b[1]));
}
__device__ __forceinline__ void cpasync16(uint32_t dst, const void* src, uint32_t srcsize) {
    asm volatile("cp.async.ca.shared.global [%0], [%1], 16, %2;"
                 :: "r"(dst), "l"(src), "r"(srcsize));
}
__device__ __forceinline__ void cpasync16(uint32_t dst, const void* src) {
    asm volatile("cp.async.ca.shared.global [%0], [%1], 16;" :: "r"(dst), "l"(src));
}

// ================= mask layout probe =================
__global__ void k_flagreset() { g_mask_is_byte = 0; }
__global__ void k_maskprobe(const unsigned char* __restrict__ m, int nbytes) {
    int i = blockIdx.x * 256 + threadIdx.x;
    if (i < nbytes && (i & 3) != 0 && m[i] != 0) g_mask_is_byte = 1;
}
__device__ __forceinline__ int mget(const void* m, int i, int isbyte) {
    return isbyte ? (((const unsigned char*)m)[i] != 0) : (((const int*)m)[i] != 0);
}

// ================= setup / compose =================
__device__ __forceinline__ void split_store(__nv_bfloat16* ph, __nv_bfloat16* pl, size_t i, float v) {
    __nv_bfloat16 h = __float2bfloat16(v);
    ph[i] = h;
    pl[i] = __float2bfloat16(v - __bfloat162float(h));
}

__global__ void k_gatherq(const int* __restrict__ idx, const float* __restrict__ nf,
                          const float* __restrict__ mem,
                          __nv_bfloat16* __restrict__ qh, __nv_bfloat16* __restrict__ ql, int n)
{
    int i = blockIdx.x * 256 + threadIdx.x;    // over n*32 float4s
    if (i >= n * 32) return;
    int node = i >> 5, c4 = i & 31;
    int src = idx[node];
    float4 a = ((const float4*)nf)[(size_t)src * 32 + c4];
    float4 b = ((const float4*)mem)[(size_t)src * 32 + c4];
    float v[4] = { a.x + b.x, a.y + b.y, a.z + b.z, a.w + b.w };
    size_t base = (size_t)i * 4;
    #pragma unroll
    for (int j = 0; j < 4; j++) split_store(qh, ql, base + j, v[j]);
}

__global__ void k_qhconst(const float* __restrict__ Wq, const float* __restrict__ bq,
                          const float* __restrict__ time_b, float* __restrict__ qhc)
{
    __shared__ float cb[128];
    int tid = threadIdx.x;
    if (tid < 128) cb[tid] = cosf(time_b[tid]);
    __syncthreads();
    float acc = bq[tid];
    const float* row = Wq + (size_t)tid * 256 + 128;
    #pragma unroll 8
    for (int j = 0; j < 128; j++) acc += row[j] * cb[j];
    qhc[tid] = acc;
}

__global__ void k_composeP(const float* __restrict__ W1, const float* __restrict__ Wo,
                           const float* __restrict__ bv, const float* __restrict__ bo,
                           float* __restrict__ Pt, float* __restrict__ cvec)
{
    int r = blockIdx.x;           // 0..127
    int a = threadIdx.x;          // 0..255
    __shared__ float w1row[256];
    __shared__ float red[256];
    w1row[a] = W1[(size_t)r * 384 + a];
    __syncthreads();
    float acc = 0.f;
    #pragma unroll 8
    for (int s = 0; s < 256; s++) acc += w1row[s] * Wo[(size_t)s * 256 + a];
    Pt[(size_t)a * 128 + r] = acc;
    red[a] = acc * bv[a] + w1row[a] * bo[a];
    __syncthreads();
    for (int off = 128; off; off >>= 1) {
        if (a < off) red[a] += red[a + off];
        __syncthreads();
    }
    if (a == 0) cvec[r] = red[0];
}

__global__ void k_composeC(const float* __restrict__ Pt, const float* __restrict__ Wv,
                           const float* __restrict__ W1,
                           __nv_bfloat16* __restrict__ Bh, __nv_bfloat16* __restrict__ Bl)
{
    int j = blockIdx.x;           // 0..895
    int r = threadIdx.x;          // 0..127
    if (j >= 768) {
        split_store(Bh, Bl, (size_t)r * 896 + j, W1[(size_t)r * 384 + 256 + (j - 768)]);
        return;
    }
    int h = j / 384, c = j % 384;
    __shared__ float wvcol[128];
    wvcol[r] = Wv[(size_t)(h * 128 + r) * 384 + c];
    __syncthreads();
    float acc = 0.f;
    #pragma unroll 8
    for (int d = 0; d < 128; d++)
        acc += Pt[(size_t)(h * 128 + d) * 128 + r] * wvcol[d];
    split_store(Bh, Bl, (size_t)r * 896 + j, acc);
}

__global__ void k_composeU(const float* __restrict__ Wk, const float* __restrict__ bk,
                           const float* __restrict__ Wq, const float* __restrict__ qhc,
                           __nv_bfloat16* __restrict__ Mh, __nv_bfloat16* __restrict__ Ml,
                           float* __restrict__ du)
{
    int hc = blockIdx.x;          // 0..769
    int h = hc / UROW, c = hc % UROW;
    int e = threadIdx.x;          // 0..159
    __shared__ float krow[128];
    if (e < 128)
        krow[e] = (c < 384) ? Wk[(size_t)(h * 128 + e) * 384 + c] : bk[h * 128 + e];
    __syncthreads();
    if (e < 128) {
        float acc = 0.f;
        #pragma unroll 8
        for (int d = 0; d < 128; d++)
            acc += krow[d] * Wq[(size_t)(h * 128 + d) * 256 + e];
        split_store(Mh, Ml, (size_t)hc * 128 + e, acc);
    } else if (e == 128) {
        float acc = 0.f;
        for (int d = 0; d < 128; d++) acc += krow[d] * qhc[h * 128 + d];
        du[hc] = acc;
    }
}

__global__ void k_splitW2(const float* __restrict__ W2,
                          __nv_bfloat16* __restrict__ wh, __nv_bfloat16* __restrict__ wl)
{
    int i = blockIdx.x * 256 + threadIdx.x;
    if (i < 128 * 128) split_store(wh, wl, i, W2[i]);
}

// ================= HMMA GEMM (cp.async double-buffered) =======================
// Out[n,r] = sum_c A[n,c]*B[r,c].  CTA tile 128x128, BK=32, 8 warps (64x32 each),
// split-bf16 3-term.  2-stage cp.async pipeline in dynamic smem.
#define LDS_STRIDE 40                 // bf16 elems; 80B rows, ldmatrix conflict-free
#define TILE_B     (128 * LDS_STRIDE * 2)   // 10240 bytes per tile
#define STAGE_B    (4 * TILE_B)             // AsH AsL BsH BsL
#define SMEM_GEMM  (2 * STAGE_B)            // 81920

template<int EPI>
__global__ __launch_bounds__(256)
void mma_gemm(const __nv_bfloat16* __restrict__ Ah, const __nv_bfloat16* __restrict__ Al, int lda,
              const __nv_bfloat16* __restrict__ A2h, const __nv_bfloat16* __restrict__ A2l, int lda2, int ksplit,
              const __nv_bfloat16* __restrict__ Bh, const __nv_bfloat16* __restrict__ Bl, int ldb,
              int ktiles, int Rtot,
              const float* __restrict__ bias, const float* __restrict__ bias2,
              const unsigned char* __restrict__ flags,
              float* __restrict__ OutF, int ldc,
              __nv_bfloat16* __restrict__ OutH, __nv_bfloat16* __restrict__ OutL, int Ntot)
{
    extern __shared__ char dsm[];
    const uint32_t sb = smem_u32(dsm);

    const int tid = threadIdx.x;
    const int lane = tid & 31, wid = tid >> 5;
    const int wm = wid >> 2, wn = wid & 3;      // 2 x 4 warp grid
    const int m0 = blockIdx.x * 128;
    const int r0 = blockIdx.y * 128;

    int vrows = Ntot - m0;
    if (vrows > 128) vrows = 128;
    if (vrows < 0) vrows = 0;

    float acc[4][4][4];
    #pragma unroll
    for (int a = 0; a < 4; a++)
        #pragma unroll
        for (int b = 0; b < 4; b++)
            #pragma unroll
            for (int c = 0; c < 4; c++) acc[a][b][c] = 0.f;

    // per-thread load coordinates (2 rows of 4 x 16B each)
    const int lrow = tid >> 2;                 // 0..63 (+64 on 2nd pass)
    const int lc8 = (tid & 3) * 8;             // bf16 col within 32

    auto issue_stage = [&](int kt) {
        uint32_t base = sb + (kt & 1) * STAGE_B;
        const __nv_bfloat16 *sh, *sl; int st, k0;
        if (kt < ksplit) { sh = Ah;  sl = Al;  st = lda;  k0 = kt * 32; }
        else             { sh = A2h; sl = A2l; st = lda2; k0 = (kt - ksplit) * 32; }
        #pragma unroll
        for (int i = 0; i < 2; i++) {
            int row = lrow + i * 64;
            int srow = (row < vrows) ? row : 0;
            uint32_t sz = (row < vrows) ? 16u : 0u;
            uint32_t doff = row * (LDS_STRIDE * 2) + lc8 * 2;
            cpasync16(base + doff,
                      sh + (size_t)(m0 + srow) * st + k0 + lc8, sz);
            cpasync16(base + TILE_B + doff,
                      sl + (size_t)(m0 + srow) * st + k0 + lc8, sz);
            cpasync16(base + 2 * TILE_B + doff,
                      Bh + (size_t)(r0 + row) * ldb + kt * 32 + lc8);
            cpasync16(base + 3 * TILE_B + doff,
                      Bl + (size_t)(r0 + row) * ldb + kt * 32 + lc8);
        }
        asm volatile("cp.async.commit_group;" ::: "memory");
    };

    // ldmatrix coordinates
    const int arow = wm * 64 + (lane & 15);
    const int acolsel = ((lane >> 4) & 1) * 8;
    const int l16 = lane & 15;
    const int brow = wn * 32 + (l16 & 7);
    const int bcolsel = ((l16 >> 3) & 1) * 8;

    issue_stage(0);

    for (int kt = 0; kt < ktiles; kt++) {
        if (kt + 1 < ktiles) {
            issue_stage(kt + 1);
            asm volatile("cp.async.wait_group 1;" ::: "memory");
        } else {
            asm volatile("cp.async.wait_group 0;" ::: "memory");
        }
        __syncthreads();

        const uint32_t cb = sb + (kt & 1) * STAGE_B;
        const uint32_t sAH = cb, sAL = cb + TILE_B;
        const uint32_t sBH = cb + 2 * TILE_B, sBL = cb + 3 * TILE_B;

        #pragma unroll
        for (int ks = 0; ks < 2; ks++) {
            const int acol = ks * 16 + acolsel;
            const int bcol = ks * 16 + bcolsel;
            uint32_t af[4][4], bhf[4][2], blf[4][2];
            #pragma unroll
            for (int mi = 0; mi < 4; mi++)
                ldm_x4(af[mi], sAH + (uint32_t)(((arow + mi * 16) * LDS_STRIDE + acol) * 2));
            #pragma unroll
            for (int ni = 0; ni < 4; ni++) {
                ldm_x2(bhf[ni], sBH + (uint32_t)(((brow + ni * 8) * LDS_STRIDE + bcol) * 2));
                ldm_x2(blf[ni], sBL + (uint32_t)(((brow + ni * 8) * LDS_STRIDE + bcol) * 2));
            }
            #pragma unroll
            for (int mi = 0; mi < 4; mi++)
                #pragma unroll
                for (int ni = 0; ni < 4; ni++) {
                    mma16816(acc[mi][ni], af[mi], bhf[ni]);   // Ah*Bh
                    mma16816(acc[mi][ni], af[mi], blf[ni]);   // Ah*Bl
                }
            #pragma unroll
            for (int mi = 0; mi < 4; mi++)
                ldm_x4(af[mi], sAL + (uint32_t)(((arow + mi * 16) * LDS_STRIDE + acol) * 2));
            #pragma unroll
            for (int mi = 0; mi < 4; mi++)
                #pragma unroll
                for (int ni = 0; ni < 4; ni++)
                    mma16816(acc[mi][ni], af[mi], bhf[ni]);   // Al*Bh
        }
        __syncthreads();
    }

    // ---- epilogue ----
    #pragma unroll
    for (int mi = 0; mi < 4; mi++) {
        int nrow0 = m0 + wm * 64 + mi * 16 + (lane >> 2);
        #pragma unroll
        for (int half = 0; half < 2; half++) {
            int n = nrow0 + half * 8;
            if (n >= Ntot) continue;
            bool fl = false;
            if (EPI == 1) fl = (flags[n] != 0);
            #pragma unroll
            for (int ni = 0; ni < 4; ni++) {
                int r = r0 + wn * 32 + ni * 8 + (lane & 3) * 2;
                float v0 = acc[mi][ni][half * 2 + 0];
                float v1 = acc[mi][ni][half * 2 + 1];
                if (EPI == 0) {
                    if (r < Rtot)     OutF[(size_t)n * ldc + r]     = v0 + bias[r];
                    if (r + 1 < Rtot) OutF[(size_t)n * ldc + r + 1] = v1 + bias[r + 1];
                } else if (EPI == 1) {
                    v0 += bias[r]     + (fl ? 0.f : bias2[r]);
                    v1 += bias[r + 1] + (fl ? 0.f : bias2[r + 1]);
                    v0 = fmaxf(v0, 0.f);
                    v1 = fmaxf(v1, 0.f);
                    __nv_bfloat16 h0 = __float2bfloat16(v0), h1 = __float2bfloat16(v1);
                    *(__nv_bfloat162*)(OutH + (size_t)n * 128 + r) = __halves2bfloat162(h0, h1);
                    __nv_bfloat16 l0 = __float2bfloat16(v0 - __bfloat162float(h0));
                    __nv_bfloat16 l1 = __float2bfloat16(v1 - __bfloat162float(h1));
                    *(__nv_bfloat162*)(OutL + (size_t)n * 128 + r) = __halves2bfloat162(l0, l1);
                } else {
                    OutF[(size_t)n * ldc + r]     = v0 + bias[r];
                    OutF[(size_t)n * ldc + r + 1] = v1 + bias[r + 1];
                }
            }
        }
    }
}

// ================= fused per-node edge kernel =================
__global__ __launch_bounds__(256)
void k_edge(const int* __restrict__ neighbors, const float* __restrict__ t,
            const float* __restrict__ e_t, const int* __restrict__ e_id,
            const void* __restrict__ mask,
            const float* __restrict__ node_feat, const float* __restrict__ memory,
            const float* __restrict__ event_feat,
            const float* __restrict__ time_w, const float* __restrict__ time_b,
            const float* __restrict__ u,
            __nv_bfloat16* __restrict__ mixh, __nv_bfloat16* __restrict__ mixl,
            unsigned char* __restrict__ flags, int Ntot)
{
    int n = blockIdx.x;
    if (n >= Ntot) return;
    int tid = threadIdx.x;
    int lane = tid & 31, warp = tid >> 5;
    const int isb = g_mask_is_byte;

    __shared__ float kvc[KNB][DKF];
    __shared__ float usf[770];
    __shared__ float tw[128], tb[128];
    __shared__ float attn[2][KNB];
    __shared__ float sc[2][KNB];
    __shared__ int s_nonb;

    if (tid < 128) { tw[tid] = time_w[tid]; tb[tid] = time_b[tid]; }
    for (int i = tid; i < 770; i += 256) usf[i] = u[(size_t)n * 770 + i];
    if (warp == 0) {
        unsigned mbit = 0;
        if (lane < KNB) mbit = mget(mask, n * KNB + lane, isb) ? 1u : 0u;
        unsigned any = __ballot_sync(0xffffffffu, mbit != 0);
        if (lane == 0) s_nonb = (any == 0) ? 1 : 0;
    }
    __syncthreads();

    float tn = t[n];
    for (int k = warp; k < KNB; k += 8) {
        int nb = neighbors[n * KNB + k];
        int mk = mget(mask, n * KNB + k, isb);
        float dt = tn - e_t[n * KNB + k];
        int eid = e_id[n * KNB + k];
        const float4* nf4 = (const float4*)(node_feat + (size_t)nb * 128);
        const float4* mm4 = (const float4*)(memory + (size_t)nb * 128);
        const float4* ef4 = (const float4*)(event_feat + (size_t)eid * 128);
        for (int c4 = lane; c4 < 96; c4 += 32) {
            float4 v;
            if (c4 < 32) {
                if (mk) {
                    float4 a = nf4[c4], b = mm4[c4];
                    v = make_float4(a.x + b.x, a.y + b.y, a.z + b.z, a.w + b.w);
                } else {
                    v = make_float4(0.f, 0.f, 0.f, 0.f);
                }
            } else if (c4 < 64) {
                int j = (c4 - 32) * 4;
                v.x = __cosf(__fadd_rn(__fmul_rn(dt, tw[j + 0]), tb[j + 0]));
                v.y = __cosf(__fadd_rn(__fmul_rn(dt, tw[j + 1]), tb[j + 1]));
                v.z = __cosf(__fadd_rn(__fmul_rn(dt, tw[j + 2]), tb[j + 2]));
                v.w = __cosf(__fadd_rn(__fmul_rn(dt, tw[j + 3]), tb[j + 3]));
            } else {
                v = ef4[c4 - 64];
            }
            *(float4*)&kvc[k][c4 * 4] = v;
        }
    }
    __syncthreads();

    for (int p = warp; p < 2 * KNB; p += 8) {
        int h = p / KNB, k = p % KNB;
        float s = 0.f;
        const float* uh = &usf[h * UROW];
        #pragma unroll 4
        for (int c = lane; c < DKF; c += 32) s += uh[c] * kvc[k][c];
        #pragma unroll
        for (int off = 16; off; off >>= 1) s += __shfl_down_sync(0xffffffffu, s, off);
        if (lane == 0) sc[h][k] = (s + uh[384]) * 0.08838834764831845f;
    }
    __syncthreads();

    if (warp < 2) {
        int h = warp;
        int valid = 0;
        float s = -INFINITY;
        if (lane < KNB) {
            valid = mget(mask, n * KNB + lane, isb) || s_nonb;
            if (valid) s = sc[h][lane];
        }
        float m = s;
        #pragma unroll
        for (int off = 16; off; off >>= 1) m = fmaxf(m, __shfl_xor_sync(0xffffffffu, m, off));
        float e = (lane < KNB && valid) ? expf(s - m) : 0.f;
        float sum = e;
        #pragma unroll
        for (int off = 16; off; off >>= 1) sum += __shfl_xor_sync(0xffffffffu, sum, off);
        if (lane < KNB) attn[h][lane] = e / sum;
    }
    __syncthreads();

    float gate = s_nonb ? 0.f : 1.f;
    for (int i = tid; i < 2 * DKF; i += 256) {
        int h = i / DKF, j = i % DKF;
        float acc = 0.f;
        #pragma unroll
        for (int k = 0; k < KNB; k++) acc += attn[h][k] * kvc[k][j];
        float m = acc * gate;
        __nv_bfloat16 hh = __float2bfloat16(m);
        mixh[(size_t)n * 768 + i] = hh;
        mixl[(size_t)n * 768 + i] = __float2bfloat16(m - __bfloat162float(hh));
    }
    if (tid == 0) flags[n] = (unsigned char)s_nonb;
}

// ================= launch =================
extern "C" void kernel_launch(void* const* d_in, const int* in_sizes, int n_in,
                              void* d_out, int out_size)
{
    const int*   idx        = (const int*)d_in[0];
    const float* t          = (const float*)d_in[1];
    const int*   neighbors  = (const int*)d_in[2];
    const float* e_t        = (const float*)d_in[3];
    const int*   e_id       = (const int*)d_in[4];
    const void*  mask       = d_in[5];
    const float* node_feat  = (const float*)d_in[6];
    const float* memory     = (const float*)d_in[7];
    const float* event_feat = (const float*)d_in[8];
    const float* time_w     = (const float*)d_in[9];
    const float* time_b     = (const float*)d_in[10];
    const float* Wq = (const float*)d_in[11];
    const float* bq = (const float*)d_in[12];
    const float* Wk = (const float*)d_in[13];
    const float* bk = (const float*)d_in[14];
    const float* Wv = (const float*)d_in[15];
    const float* bv = (const float*)d_in[16];
    const float* Wo = (const float*)d_in[17];
    const float* bo = (const float*)d_in[18];
    const float* W1 = (const float*)d_in[19];
    const float* b1 = (const float*)d_in[20];
    const float* W2 = (const float*)d_in[21];
    const float* b2 = (const float*)d_in[22];
    float* out = (float*)d_out;

    int N = in_sizes[0];
    if (N > NN) N = NN;

    float *u, *du, *Pt, *cvec, *qhc;
    __nv_bfloat16 *qh, *ql, *mh, *ml, *h1h, *h1l, *Muh, *Mul, *Bfh, *Bfl, *W2h, *W2l;
    unsigned char* flags;
    cudaGetSymbolAddress((void**)&u, g_u);
    cudaGetSymbolAddress((void**)&du, g_du);
    cudaGetSymbolAddress((void**)&Pt, g_Pt);
    cudaGetSymbolAddress((void**)&cvec, g_cvec);
    cudaGetSymbolAddress((void**)&qhc, g_qhc);
    cudaGetSymbolAddress((void**)&qh, g_qh);
    cudaGetSymbolAddress((void**)&ql, g_ql);
    cudaGetSymbolAddress((void**)&mh, g_mh);
    cudaGetSymbolAddress((void**)&ml, g_ml);
    cudaGetSymbolAddress((void**)&h1h, g_h1h);
    cudaGetSymbolAddress((void**)&h1l, g_h1l);
    cudaGetSymbolAddress((void**)&Muh, g_Muh);
    cudaGetSymbolAddress((void**)&Mul, g_Mul);
    cudaGetSymbolAddress((void**)&Bfh, g_Bfh);
    cudaGetSymbolAddress((void**)&Bfl, g_Bfl);
    cudaGetSymbolAddress((void**)&W2h, g_W2h);
    cudaGetSymbolAddress((void**)&W2l, g_W2l);
    cudaGetSymbolAddress((void**)&flags, g_flags);

    cudaFuncSetAttribute(mma_gemm<0>, cudaFuncAttributeMaxDynamicSharedMemorySize, SMEM_GEMM);
    cudaFuncSetAttribute(mma_gemm<1>, cudaFuncAttributeMaxDynamicSharedMemorySize, SMEM_GEMM);
    cudaFuncSetAttribute(mma_gemm<2>, cudaFuncAttributeMaxDynamicSharedMemorySize, SMEM_GEMM);

    int mtiles = (N + 127) / 128;

    // launches 0..2 (keeps the u-GEMM as profiled launch index 3)
    k_qhconst<<<1, 256>>>(Wq, bq, time_b, qhc);
    k_composeU<<<770, 160>>>(Wk, bk, Wq, qhc, Muh, Mul, du);
    k_gatherq<<<(N * 32 + 255) / 256, 256>>>(idx, node_feat, memory, qh, ql, N);

    // 3: u = Mu @ q + du  -> g_u (N x 770)   K=128 (4 k-tiles), R=770 (7 r-tiles)
    mma_gemm<0><<<dim3(mtiles, 7), 256, SMEM_GEMM>>>(
        qh, ql, 128, nullptr, nullptr, 0, 1000,
        Muh, Mul, 128, 4, 770,
        du, nullptr, nullptr, u, 770, nullptr, nullptr, N);

    // 4..8
    k_composeP<<<128, 256>>>(W1, Wo, bv, bo, Pt, cvec);
    k_composeC<<<896, 128>>>(Pt, Wv, W1, Bfh, Bfl);
    k_splitW2<<<64, 256>>>(W2, W2h, W2l);
    k_flagreset<<<1, 1>>>();
    k_maskprobe<<<32, 256>>>((const unsigned char*)mask, 8192);

    // 9: fused edge kernel -> mixed hi/lo (N x 768)
    k_edge<<<N, 256>>>(neighbors, t, e_t, e_id, mask, node_feat, memory,
                       event_feat, time_w, time_b, u, mh, ml, flags, N);

    // 10: h1 = relu(Bf @ [mixed, q] + b1 + gated cvec) -> h1 hi/lo (N x 128)
    mma_gemm<1><<<dim3(mtiles, 1), 256, SMEM_GEMM>>>(
        mh, ml, 768, qh, ql, 128, 24,
        Bfh, Bfl, 896, 28, 128,
        b1, cvec, flags, nullptr, 0, h1h, h1l, N);

    // 11: out = h1 @ W2^T + b2 -> d_out (N x 128)   K=128 (4 k-tiles)
    mma_gemm<2><<<dim3(mtiles, 1), 256, SMEM_GEMM>>>(
        h1h, h1l, 128, nullptr, nullptr, 0, 1000,
        W2h, W2l, 128, 4, 128,
        b2, nullptr, nullptr, out, 128, nullptr, nullptr, N);
}

// round 8
// speedup vs baseline: 1.7850x; 1.0428x over previous
#include <cuda_runtime.h>
#include <cuda_bf16.h>
#include <math.h>
#include <stdint.h>

#define NN    100000
#define KNB   20
#define DKF   384
#define UROW  385

// ================= device scratch =================
__device__ float g_u[(size_t)NN * 770];          // u (2x385) f32, read by k_edge
__device__ uint4 g_qh[(size_t)NN * 16];          // q hi  (N x 128 bf16)
__device__ uint4 g_ql[(size_t)NN * 16];          // q lo
__device__ uint4 g_mh[(size_t)NN * 96];          // mixed hi (N x 768 bf16)
__device__ uint4 g_ml[(size_t)NN * 96];          // mixed lo
__device__ uint4 g_h1h[(size_t)NN * 16];         // h1 hi (N x 128 bf16)
__device__ uint4 g_h1l[(size_t)NN * 16];         // h1 lo
__device__ uint4 g_Muh[14336], g_Mul[14336];     // Mu 896(pad 770) x 128 bf16
__device__ uint4 g_Bfh[14336], g_Bfl[14336];     // Bf 128 x 896 bf16
__device__ uint4 g_W2h[2048], g_W2l[2048];       // W2 128 x 128 bf16
__device__ float g_du[896];
__device__ float g_Pt[256 * 128];
__device__ float g_cvec[128];
__device__ float g_qhc[256];
__device__ unsigned char g_flags[NN];
__device__ int   g_mask_is_byte;

// ================= PTX helpers (baseline features only) =================
__device__ __forceinline__ uint32_t smem_u32(const void* p) {
    uint32_t r;
    asm("{ .reg .u64 t; cvta.to.shared.u64 t, %1; cvt.u32.u64 %0, t; }" : "=r"(r) : "l"(p));
    return r;
}
__device__ __forceinline__ void ldm_x4(uint32_t* r, uint32_t addr) {
    asm volatile("ldmatrix.sync.aligned.m8n8.x4.shared.b16 {%0,%1,%2,%3}, [%4];"
                 : "=r"(r[0]), "=r"(r[1]), "=r"(r[2]), "=r"(r[3]) : "r"(addr));
}
__device__ __forceinline__ void ldm_x2(uint32_t* r, uint32_t addr) {
    asm volatile("ldmatrix.sync.aligned.m8n8.x2.shared.b16 {%0,%1}, [%2];"
                 : "=r"(r[0]), "=r"(r[1]) : "r"(addr));
}
__device__ __forceinline__ void mma16816(float* c, const uint32_t* a, const uint32_t* b) {
    asm volatile("mma.sync.aligned.m16n8k16.row.col.f32.bf16.bf16.f32 "
        "{%0,%1,%2,%3}, {%4,%5,%6,%7}, {%8,%9}, {%0,%1,%2,%3};"
        : "+f"(c[0]), "+f"(c[1]), "+f"(c[2]), "+f"(c[3])
        : "r"(a[0]), "r"(a[1]), "r"(a[2]), "r"(a[3]), "r"(b[0]), "r"(b[1]));
}
__device__ __forceinline__ void cpasync16(uint32_t dst, const void* src, uint32_t srcsize) {
    asm volatile("cp.async.cg.shared.global [%0], [%1], 16, %2;"
                 :: "r"(dst), "l"(src), "r"(srcsize));
}
__device__ __forceinline__ void cpasync16(uint32_t dst, const void* src) {
    asm volatile("cp.async.cg.shared.global [%0], [%1], 16;" :: "r"(dst), "l"(src));
}

// ================= mask layout probe =================
__global__ void k_flagreset() { g_mask_is_byte = 0; }
__global__ void k_maskprobe(const unsigned char* __restrict__ m, int nbytes) {
    int i = blockIdx.x * 256 + threadIdx.x;
    if (i < nbytes && (i & 3) != 0 && m[i] != 0) g_mask_is_byte = 1;
}
__device__ __forceinline__ int mget(const void* m, int i, int isbyte) {
    return isbyte ? (((const unsigned char*)m)[i] != 0) : (((const int*)m)[i] != 0);
}

// ================= setup / compose =================
__device__ __forceinline__ void split_store(__nv_bfloat16* ph, __nv_bfloat16* pl, size_t i, float v) {
    __nv_bfloat16 h = __float2bfloat16(v);
    ph[i] = h;
    pl[i] = __float2bfloat16(v - __bfloat162float(h));
}

__global__ void k_gatherq(const int* __restrict__ idx, const float* __restrict__ nf,
                          const float* __restrict__ mem,
                          __nv_bfloat16* __restrict__ qh, __nv_bfloat16* __restrict__ ql, int n)
{
    int i = blockIdx.x * 256 + threadIdx.x;    // over n*32 float4s
    if (i >= n * 32) return;
    int node = i >> 5, c4 = i & 31;
    int src = idx[node];
    float4 a = ((const float4*)nf)[(size_t)src * 32 + c4];
    float4 b = ((const float4*)mem)[(size_t)src * 32 + c4];
    float v[4] = { a.x + b.x, a.y + b.y, a.z + b.z, a.w + b.w };
    size_t base = (size_t)i * 4;
    #pragma unroll
    for (int j = 0; j < 4; j++) split_store(qh, ql, base + j, v[j]);
}

__global__ void k_qhconst(const float* __restrict__ Wq, const float* __restrict__ bq,
                          const float* __restrict__ time_b, float* __restrict__ qhc)
{
    __shared__ float cb[128];
    int tid = threadIdx.x;
    if (tid < 128) cb[tid] = cosf(time_b[tid]);
    __syncthreads();
    float acc = bq[tid];
    const float* row = Wq + (size_t)tid * 256 + 128;
    #pragma unroll 8
    for (int j = 0; j < 128; j++) acc += row[j] * cb[j];
    qhc[tid] = acc;
}

__global__ void k_composeP(const float* __restrict__ W1, const float* __restrict__ Wo,
                           const float* __restrict__ bv, const float* __restrict__ bo,
                           float* __restrict__ Pt, float* __restrict__ cvec)
{
    int r = blockIdx.x;           // 0..127
    int a = threadIdx.x;          // 0..255
    __shared__ float w1row[256];
    __shared__ float red[256];
    w1row[a] = W1[(size_t)r * 384 + a];
    __syncthreads();
    float acc = 0.f;
    #pragma unroll 8
    for (int s = 0; s < 256; s++) acc += w1row[s] * Wo[(size_t)s * 256 + a];
    Pt[(size_t)a * 128 + r] = acc;
    red[a] = acc * bv[a] + w1row[a] * bo[a];
    __syncthreads();
    for (int off = 128; off; off >>= 1) {
        if (a < off) red[a] += red[a + off];
        __syncthreads();
    }
    if (a == 0) cvec[r] = red[0];
}

__global__ void k_composeC(const float* __restrict__ Pt, const float* __restrict__ Wv,
                           const float* __restrict__ W1,
                           __nv_bfloat16* __restrict__ Bh, __nv_bfloat16* __restrict__ Bl)
{
    int j = blockIdx.x;           // 0..895
    int r = threadIdx.x;          // 0..127
    if (j >= 768) {
        split_store(Bh, Bl, (size_t)r * 896 + j, W1[(size_t)r * 384 + 256 + (j - 768)]);
        return;
    }
    int h = j / 384, c = j % 384;
    __shared__ float wvcol[128];
    wvcol[r] = Wv[(size_t)(h * 128 + r) * 384 + c];
    __syncthreads();
    float acc = 0.f;
    #pragma unroll 8
    for (int d = 0; d < 128; d++)
        acc += Pt[(size_t)(h * 128 + d) * 128 + r] * wvcol[d];
    split_store(Bh, Bl, (size_t)r * 896 + j, acc);
}

__global__ void k_composeU(const float* __restrict__ Wk, const float* __restrict__ bk,
                           const float* __restrict__ Wq, const float* __restrict__ qhc,
                           __nv_bfloat16* __restrict__ Mh, __nv_bfloat16* __restrict__ Ml,
                           float* __restrict__ du)
{
    int hc = blockIdx.x;          // 0..769
    int h = hc / UROW, c = hc % UROW;
    int e = threadIdx.x;          // 0..159
    __shared__ float krow[128];
    if (e < 128)
        krow[e] = (c < 384) ? Wk[(size_t)(h * 128 + e) * 384 + c] : bk[h * 128 + e];
    __syncthreads();
    if (e < 128) {
        float acc = 0.f;
        #pragma unroll 8
        for (int d = 0; d < 128; d++)
            acc += krow[d] * Wq[(size_t)(h * 128 + d) * 256 + e];
        split_store(Mh, Ml, (size_t)hc * 128 + e, acc);
    } else if (e == 128) {
        float acc = 0.f;
        for (int d = 0; d < 128; d++) acc += krow[d] * qhc[h * 128 + d];
        du[hc] = acc;
    }
}

__global__ void k_splitW2(const float* __restrict__ W2,
                          __nv_bfloat16* __restrict__ wh, __nv_bfloat16* __restrict__ wl)
{
    int i = blockIdx.x * 256 + threadIdx.x;
    if (i < 128 * 128) split_store(wh, wl, i, W2[i]);
}

// ================= HMMA GEMM (cp.async double-buffered, 2 CTAs/SM) ===========
// Out[n,r] = sum_c A[n,c]*B[r,c].  CTA tile 128x128, BK=32, 8 warps (64x32 each),
// split-bf16 3-term.  2-stage cp.async pipeline in dynamic smem.
#define LDS_STRIDE 40                 // bf16 elems; 80B rows, ldmatrix conflict-free
#define TILE_B     (128 * LDS_STRIDE * 2)   // 10240 bytes per tile
#define STAGE_B    (4 * TILE_B)             // AsH AsL BsH BsL
#define SMEM_GEMM  (2 * STAGE_B)            // 81920

template<int EPI>
__global__ __launch_bounds__(256, 2)
void mma_gemm(const __nv_bfloat16* __restrict__ Ah, const __nv_bfloat16* __restrict__ Al, int lda,
              const __nv_bfloat16* __restrict__ A2h, const __nv_bfloat16* __restrict__ A2l, int lda2, int ksplit,
              const __nv_bfloat16* __restrict__ Bh, const __nv_bfloat16* __restrict__ Bl, int ldb,
              int ktiles, int Rtot,
              const float* __restrict__ bias, const float* __restrict__ bias2,
              const unsigned char* __restrict__ flags,
              float* __restrict__ OutF, int ldc,
              __nv_bfloat16* __restrict__ OutH, __nv_bfloat16* __restrict__ OutL, int Ntot)
{
    extern __shared__ char dsm[];
    const uint32_t sb = smem_u32(dsm);

    const int tid = threadIdx.x;
    const int lane = tid & 31, wid = tid >> 5;
    const int wm = wid >> 2, wn = wid & 3;      // 2 x 4 warp grid
    const int m0 = blockIdx.x * 128;
    const int r0 = blockIdx.y * 128;

    int vrows = Ntot - m0;
    if (vrows > 128) vrows = 128;
    if (vrows < 0) vrows = 0;

    float acc[4][4][4];
    #pragma unroll
    for (int a = 0; a < 4; a++)
        #pragma unroll
        for (int b = 0; b < 4; b++)
            #pragma unroll
            for (int c = 0; c < 4; c++) acc[a][b][c] = 0.f;

    // per-thread load coordinates (2 rows of 4 x 16B each)
    const int lrow = tid >> 2;                 // 0..63 (+64 on 2nd pass)
    const int lc8 = (tid & 3) * 8;             // bf16 col within 32

    auto issue_stage = [&](int kt) {
        uint32_t base = sb + (kt & 1) * STAGE_B;
        const __nv_bfloat16 *sh, *sl; int st, k0;
        if (kt < ksplit) { sh = Ah;  sl = Al;  st = lda;  k0 = kt * 32; }
        else             { sh = A2h; sl = A2l; st = lda2; k0 = (kt - ksplit) * 32; }
        #pragma unroll
        for (int i = 0; i < 2; i++) {
            int row = lrow + i * 64;
            int srow = (row < vrows) ? row : 0;
            uint32_t sz = (row < vrows) ? 16u : 0u;
            uint32_t doff = row * (LDS_STRIDE * 2) + lc8 * 2;
            cpasync16(base + doff,
                      sh + (size_t)(m0 + srow) * st + k0 + lc8, sz);
            cpasync16(base + TILE_B + doff,
                      sl + (size_t)(m0 + srow) * st + k0 + lc8, sz);
            cpasync16(base + 2 * TILE_B + doff,
                      Bh + (size_t)(r0 + row) * ldb + kt * 32 + lc8);
            cpasync16(base + 3 * TILE_B + doff,
                      Bl + (size_t)(r0 + row) * ldb + kt * 32 + lc8);
        }
        asm volatile("cp.async.commit_group;" ::: "memory");
    };

    // ldmatrix coordinates
    const int arow = wm * 64 + (lane & 15);
    const int acolsel = ((lane >> 4) & 1) * 8;
    const int l16 = lane & 15;
    const int brow = wn * 32 + (l16 & 7);
    const int bcolsel = ((l16 >> 3) & 1) * 8;

    issue_stage(0);

    for (int kt = 0; kt < ktiles; kt++) {
        if (kt + 1 < ktiles) {
            issue_stage(kt + 1);
            asm volatile("cp.async.wait_group 1;" ::: "memory");
        } else {
            asm volatile("cp.async.wait_group 0;" ::: "memory");
        }
        __syncthreads();

        const uint32_t cb = sb + (kt & 1) * STAGE_B;
        const uint32_t sAH = cb, sAL = cb + TILE_B;
        const uint32_t sBH = cb + 2 * TILE_B, sBL = cb + 3 * TILE_B;

        #pragma unroll
        for (int ks = 0; ks < 2; ks++) {
            const int acol = ks * 16 + acolsel;
            const int bcol = ks * 16 + bcolsel;
            uint32_t af[4][4], bhf[4][2], blf[4][2];
            #pragma unroll
            for (int mi = 0; mi < 4; mi++)
                ldm_x4(af[mi], sAH + (uint32_t)(((arow + mi * 16) * LDS_STRIDE + acol) * 2));
            #pragma unroll
            for (int ni = 0; ni < 4; ni++) {
                ldm_x2(bhf[ni], sBH + (uint32_t)(((brow + ni * 8) * LDS_STRIDE + bcol) * 2));
                ldm_x2(blf[ni], sBL + (uint32_t)(((brow + ni * 8) * LDS_STRIDE + bcol) * 2));
            }
            #pragma unroll
            for (int mi = 0; mi < 4; mi++)
                #pragma unroll
                for (int ni = 0; ni < 4; ni++) {
                    mma16816(acc[mi][ni], af[mi], bhf[ni]);   // Ah*Bh
                    mma16816(acc[mi][ni], af[mi], blf[ni]);   // Ah*Bl
                }
            #pragma unroll
            for (int mi = 0; mi < 4; mi++)
                ldm_x4(af[mi], sAL + (uint32_t)(((arow + mi * 16) * LDS_STRIDE + acol) * 2));
            #pragma unroll
            for (int mi = 0; mi < 4; mi++)
                #pragma unroll
                for (int ni = 0; ni < 4; ni++)
                    mma16816(acc[mi][ni], af[mi], bhf[ni]);   // Al*Bh
        }
        __syncthreads();
    }

    // ---- epilogue ----
    #pragma unroll
    for (int mi = 0; mi < 4; mi++) {
        int nrow0 = m0 + wm * 64 + mi * 16 + (lane >> 2);
        #pragma unroll
        for (int half = 0; half < 2; half++) {
            int n = nrow0 + half * 8;
            if (n >= Ntot) continue;
            bool fl = false;
            if (EPI == 1) fl = (flags[n] != 0);
            #pragma unroll
            for (int ni = 0; ni < 4; ni++) {
                int r = r0 + wn * 32 + ni * 8 + (lane & 3) * 2;
                float v0 = acc[mi][ni][half * 2 + 0];
                float v1 = acc[mi][ni][half * 2 + 1];
                if (EPI == 0) {
                    if (r < Rtot)     OutF[(size_t)n * ldc + r]     = v0 + bias[r];
                    if (r + 1 < Rtot) OutF[(size_t)n * ldc + r + 1] = v1 + bias[r + 1];
                } else if (EPI == 1) {
                    v0 += bias[r]     + (fl ? 0.f : bias2[r]);
                    v1 += bias[r + 1] + (fl ? 0.f : bias2[r + 1]);
                    v0 = fmaxf(v0, 0.f);
                    v1 = fmaxf(v1, 0.f);
                    __nv_bfloat16 h0 = __float2bfloat16(v0), h1 = __float2bfloat16(v1);
                    *(__nv_bfloat162*)(OutH + (size_t)n * 128 + r) = __halves2bfloat162(h0, h1);
                    __nv_bfloat16 l0 = __float2bfloat16(v0 - __bfloat162float(h0));
                    __nv_bfloat16 l1 = __float2bfloat16(v1 - __bfloat162float(h1));
                    *(__nv_bfloat162*)(OutL + (size_t)n * 128 + r) = __halves2bfloat162(l0, l1);
                } else {
                    OutF[(size_t)n * ldc + r]     = v0 + bias[r];
                    OutF[(size_t)n * ldc + r + 1] = v1 + bias[r + 1];
                }
            }
        }
    }
}

// ================= fused per-node edge kernel =================
__global__ __launch_bounds__(256)
void k_edge(const int* __restrict__ neighbors, const float* __restrict__ t,
            const float* __restrict__ e_t, const int* __restrict__ e_id,
            const void* __restrict__ mask,
            const float* __restrict__ node_feat, const float* __restrict__ memory,
            const float* __restrict__ event_feat,
            const float* __restrict__ time_w, const float* __restrict__ time_b,
            const float* __restrict__ u,
            __nv_bfloat16* __restrict__ mixh, __nv_bfloat16* __restrict__ mixl,
            unsigned char* __restrict__ flags, int Ntot)
{
    int n = blockIdx.x;
    if (n >= Ntot) return;
    int tid = threadIdx.x;
    int lane = tid & 31, warp = tid >> 5;
    const int isb = g_mask_is_byte;

    __shared__ float kvc[KNB][DKF];
    __shared__ float usf[770];
    __shared__ float tw[128], tb[128];
    __shared__ float attn[2][KNB];
    __shared__ float sc[2][KNB];
    __shared__ int s_nonb;

    if (tid < 128) { tw[tid] = time_w[tid]; tb[tid] = time_b[tid]; }
    for (int i = tid; i < 770; i += 256) usf[i] = u[(size_t)n * 770 + i];
    if (warp == 0) {
        unsigned mbit = 0;
        if (lane < KNB) mbit = mget(mask, n * KNB + lane, isb) ? 1u : 0u;
        unsigned any = __ballot_sync(0xffffffffu, mbit != 0);
        if (lane == 0) s_nonb = (any == 0) ? 1 : 0;
    }
    __syncthreads();

    float tn = t[n];
    for (int k = warp; k < KNB; k += 8) {
        int nb = neighbors[n * KNB + k];
        int mk = mget(mask, n * KNB + k, isb);
        float dt = tn - e_t[n * KNB + k];
        int eid = e_id[n * KNB + k];
        const float4* nf4 = (const float4*)(node_feat + (size_t)nb * 128);
        const float4* mm4 = (const float4*)(memory + (size_t)nb * 128);
        const float4* ef4 = (const float4*)(event_feat + (size_t)eid * 128);
        for (int c4 = lane; c4 < 96; c4 += 32) {
            float4 v;
            if (c4 < 32) {
                if (mk) {
                    float4 a = nf4[c4], b = mm4[c4];
                    v = make_float4(a.x + b.x, a.y + b.y, a.z + b.z, a.w + b.w);
                } else {
                    v = make_float4(0.f, 0.f, 0.f, 0.f);
                }
            } else if (c4 < 64) {
                int j = (c4 - 32) * 4;
                v.x = __cosf(__fadd_rn(__fmul_rn(dt, tw[j + 0]), tb[j + 0]));
                v.y = __cosf(__fadd_rn(__fmul_rn(dt, tw[j + 1]), tb[j + 1]));
                v.z = __cosf(__fadd_rn(__fmul_rn(dt, tw[j + 2]), tb[j + 2]));
                v.w = __cosf(__fadd_rn(__fmul_rn(dt, tw[j + 3]), tb[j + 3]));
            } else {
                v = ef4[c4 - 64];
            }
            *(float4*)&kvc[k][c4 * 4] = v;
        }
    }
    __syncthreads();

    for (int p = warp; p < 2 * KNB; p += 8) {
        int h = p / KNB, k = p % KNB;
        float s = 0.f;
        const float* uh = &usf[h * UROW];
        #pragma unroll 4
        for (int c = lane; c < DKF; c += 32) s += uh[c] * kvc[k][c];
        #pragma unroll
        for (int off = 16; off; off >>= 1) s += __shfl_down_sync(0xffffffffu, s, off);
        if (lane == 0) sc[h][k] = (s + uh[384]) * 0.08838834764831845f;
    }
    __syncthreads();

    if (warp < 2) {
        int h = warp;
        int valid = 0;
        float s = -INFINITY;
        if (lane < KNB) {
            valid = mget(mask, n * KNB + lane, isb) || s_nonb;
            if (valid) s = sc[h][lane];
        }
        float m = s;
        #pragma unroll
        for (int off = 16; off; off >>= 1) m = fmaxf(m, __shfl_xor_sync(0xffffffffu, m, off));
        float e = (lane < KNB && valid) ? expf(s - m) : 0.f;
        float sum = e;
        #pragma unroll
        for (int off = 16; off; off >>= 1) sum += __shfl_xor_sync(0xffffffffu, sum, off);
        if (lane < KNB) attn[h][lane] = e / sum;
    }
    __syncthreads();

    float gate = s_nonb ? 0.f : 1.f;
    for (int i = tid; i < 2 * DKF; i += 256) {
        int h = i / DKF, j = i % DKF;
        float acc = 0.f;
        #pragma unroll
        for (int k = 0; k < KNB; k++) acc += attn[h][k] * kvc[k][j];
        float m = acc * gate;
        __nv_bfloat16 hh = __float2bfloat16(m);
        mixh[(size_t)n * 768 + i] = hh;
        mixl[(size_t)n * 768 + i] = __float2bfloat16(m - __bfloat162float(hh));
    }
    if (tid == 0) flags[n] = (unsigned char)s_nonb;
}

// ================= launch =================
extern "C" void kernel_launch(void* const* d_in, const int* in_sizes, int n_in,
                              void* d_out, int out_size)
{
    const int*   idx        = (const int*)d_in[0];
    const float* t          = (const float*)d_in[1];
    const int*   neighbors  = (const int*)d_in[2];
    const float* e_t        = (const float*)d_in[3];
    const int*   e_id       = (const int*)d_in[4];
    const void*  mask       = d_in[5];
    const float* node_feat  = (const float*)d_in[6];
    const float* memory     = (const float*)d_in[7];
    const float* event_feat = (const float*)d_in[8];
    const float* time_w     = (const float*)d_in[9];
    const float* time_b     = (const float*)d_in[10];
    const float* Wq = (const float*)d_in[11];
    const float* bq = (const float*)d_in[12];
    const float* Wk = (const float*)d_in[13];
    const float* bk = (const float*)d_in[14];
    const float* Wv = (const float*)d_in[15];
    const float* bv = (const float*)d_in[16];
    const float* Wo = (const float*)d_in[17];
    const float* bo = (const float*)d_in[18];
    const float* W1 = (const float*)d_in[19];
    const float* b1 = (const float*)d_in[20];
    const float* W2 = (const float*)d_in[21];
    const float* b2 = (const float*)d_in[22];
    float* out = (float*)d_out;

    int N = in_sizes[0];
    if (N > NN) N = NN;

    float *u, *du, *Pt, *cvec, *qhc;
    __nv_bfloat16 *qh, *ql, *mh, *ml, *h1h, *h1l, *Muh, *Mul, *Bfh, *Bfl, *W2h, *W2l;
    unsigned char* flags;
    cudaGetSymbolAddress((void**)&u, g_u);
    cudaGetSymbolAddress((void**)&du, g_du);
    cudaGetSymbolAddress((void**)&Pt, g_Pt);
    cudaGetSymbolAddress((void**)&cvec, g_cvec);
    cudaGetSymbolAddress((void**)&qhc, g_qhc);
    cudaGetSymbolAddress((void**)&qh, g_qh);
    cudaGetSymbolAddress((void**)&ql, g_ql);
    cudaGetSymbolAddress((void**)&mh, g_mh);
    cudaGetSymbolAddress((void**)&ml, g_ml);
    cudaGetSymbolAddress((void**)&h1h, g_h1h);
    cudaGetSymbolAddress((void**)&h1l, g_h1l);
    cudaGetSymbolAddress((void**)&Muh, g_Muh);
    cudaGetSymbolAddress((void**)&Mul, g_Mul);
    cudaGetSymbolAddress((void**)&Bfh, g_Bfh);
    cudaGetSymbolAddress((void**)&Bfl, g_Bfl);
    cudaGetSymbolAddress((void**)&W2h, g_W2h);
    cudaGetSymbolAddress((void**)&W2l, g_W2l);
    cudaGetSymbolAddress((void**)&flags, g_flags);

    cudaFuncSetAttribute(mma_gemm<0>, cudaFuncAttributeMaxDynamicSharedMemorySize, SMEM_GEMM);
    cudaFuncSetAttribute(mma_gemm<1>, cudaFuncAttributeMaxDynamicSharedMemorySize, SMEM_GEMM);
    cudaFuncSetAttribute(mma_gemm<2>, cudaFuncAttributeMaxDynamicSharedMemorySize, SMEM_GEMM);

    int mtiles = (N + 127) / 128;

    // launches 0..2 (keeps the u-GEMM as profiled launch index 3)
    k_qhconst<<<1, 256>>>(Wq, bq, time_b, qhc);
    k_composeU<<<770, 160>>>(Wk, bk, Wq, qhc, Muh, Mul, du);
    k_gatherq<<<(N * 32 + 255) / 256, 256>>>(idx, node_feat, memory, qh, ql, N);

    // 3: u = Mu @ q + du  -> g_u (N x 770)   K=128 (4 k-tiles), R=770 (7 r-tiles)
    mma_gemm<0><<<dim3(mtiles, 7), 256, SMEM_GEMM>>>(
        qh, ql, 128, nullptr, nullptr, 0, 1000,
        Muh, Mul, 128, 4, 770,
        du, nullptr, nullptr, u, 770, nullptr, nullptr, N);

    // 4..8
    k_composeP<<<128, 256>>>(W1, Wo, bv, bo, Pt, cvec);
    k_composeC<<<896, 128>>>(Pt, Wv, W1, Bfh, Bfl);
    k_splitW2<<<64, 256>>>(W2, W2h, W2l);
    k_flagreset<<<1, 1>>>();
    k_maskprobe<<<32, 256>>>((const unsigned char*)mask, 8192);

    // 9: fused edge kernel -> mixed hi/lo (N x 768)
    k_edge<<<N, 256>>>(neighbors, t, e_t, e_id, mask, node_feat, memory,
                       event_feat, time_w, time_b, u, mh, ml, flags, N);

    // 10: h1 = relu(Bf @ [mixed, q] + b1 + gated cvec) -> h1 hi/lo (N x 128)
    mma_gemm<1><<<dim3(mtiles, 1), 256, SMEM_GEMM>>>(
        mh, ml, 768, qh, ql, 128, 24,
        Bfh, Bfl, 896, 28, 128,
        b1, cvec, flags, nullptr, 0, h1h, h1l, N);

    // 11: out = h1 @ W2^T + b2 -> d_out (N x 128)   K=128 (4 k-tiles)
    mma_gemm<2><<<dim3(mtiles, 1), 256, SMEM_GEMM>>>(
        h1h, h1l, 128, nullptr, nullptr, 0, 1000,
        W2h, W2l, 128, 4, 128,
        b2, nullptr, nullptr, out, 128, nullptr, nullptr, N);
}

// round 9
// speedup vs baseline: 1.8727x; 1.0491x over previous
#include <cuda_runtime.h>
#include <cuda_bf16.h>
#include <math.h>
#include <stdint.h>

#define NN    100000
#define KNB   20
#define DKF   384
#define UROW  385
#define NNODES 200000

// ================= device scratch =================
__device__ float g_comb[(size_t)NNODES * 128];   // node_feat + memory (precomputed)
__device__ float g_u[(size_t)NN * 770];          // u (2x385) f32, read by k_edge
__device__ uint4 g_qh[(size_t)NN * 16];          // q hi  (N x 128 bf16)
__device__ uint4 g_ql[(size_t)NN * 16];          // q lo
__device__ uint4 g_mh[(size_t)NN * 96];          // mixed hi (N x 768 bf16)
__device__ uint4 g_ml[(size_t)NN * 96];          // mixed lo
__device__ uint4 g_h1h[(size_t)NN * 16];         // h1 hi (N x 128 bf16)
__device__ uint4 g_h1l[(size_t)NN * 16];         // h1 lo
__device__ uint4 g_Muh[14336], g_Mul[14336];     // Mu 896(pad 770) x 128 bf16
__device__ uint4 g_Bfh[14336], g_Bfl[14336];     // Bf 128 x 896 bf16
__device__ uint4 g_W2h[2048], g_W2l[2048];       // W2 128 x 128 bf16
__device__ float g_du[896];
__device__ float g_Pt[256 * 128];
__device__ float g_cvec[128];
__device__ float g_qhc[256];
__device__ unsigned char g_flags[NN];
__device__ int   g_mask_is_byte;

// ================= PTX helpers (baseline features only) =================
__device__ __forceinline__ uint32_t smem_u32(const void* p) {
    uint32_t r;
    asm("{ .reg .u64 t; cvta.to.shared.u64 t, %1; cvt.u32.u64 %0, t; }" : "=r"(r) : "l"(p));
    return r;
}
__device__ __forceinline__ void ldm_x4(uint32_t* r, uint32_t addr) {
    asm volatile("ldmatrix.sync.aligned.m8n8.x4.shared.b16 {%0,%1,%2,%3}, [%4];"
                 : "=r"(r[0]), "=r"(r[1]), "=r"(r[2]), "=r"(r[3]) : "r"(addr));
}
__device__ __forceinline__ void ldm_x2(uint32_t* r, uint32_t addr) {
    asm volatile("ldmatrix.sync.aligned.m8n8.x2.shared.b16 {%0,%1}, [%2];"
                 : "=r"(r[0]), "=r"(r[1]) : "r"(addr));
}
__device__ __forceinline__ void mma16816(float* c, const uint32_t* a, const uint32_t* b) {
    asm volatile("mma.sync.aligned.m16n8k16.row.col.f32.bf16.bf16.f32 "
        "{%0,%1,%2,%3}, {%4,%5,%6,%7}, {%8,%9}, {%0,%1,%2,%3};"
        : "+f"(c[0]), "+f"(c[1]), "+f"(c[2]), "+f"(c[3])
        : "r"(a[0]), "r"(a[1]), "r"(a[2]), "r"(a[3]), "r"(b[0]), "r"(b[1]));
}
__device__ __forceinline__ void cpasync16(uint32_t dst, const void* src, uint32_t srcsize) {
    asm volatile("cp.async.cg.shared.global [%0], [%1], 16, %2;"
                 :: "r"(dst), "l"(src), "r"(srcsize));
}
__device__ __forceinline__ void cpasync16(uint32_t dst, const void* src) {
    asm volatile("cp.async.cg.shared.global [%0], [%1], 16;" :: "r"(dst), "l"(src));
}

// ================= mask layout probe =================
__global__ void k_flagreset() { g_mask_is_byte = 0; }
__global__ void k_maskprobe(const unsigned char* __restrict__ m, int nbytes) {
    int i = blockIdx.x * 256 + threadIdx.x;
    if (i < nbytes && (i & 3) != 0 && m[i] != 0) g_mask_is_byte = 1;
}
__device__ __forceinline__ int mget(const void* m, int i, int isbyte) {
    return isbyte ? (((const unsigned char*)m)[i] != 0) : (((const int*)m)[i] != 0);
}

// ================= setup / compose =================
__device__ __forceinline__ void split_store(__nv_bfloat16* ph, __nv_bfloat16* pl, size_t i, float v) {
    __nv_bfloat16 h = __float2bfloat16(v);
    ph[i] = h;
    pl[i] = __float2bfloat16(v - __bfloat162float(h));
}

// comb = node_feat + memory for ALL nodes (one-time, reused by gatherq + edge)
__global__ void k_comb(const float* __restrict__ nf, const float* __restrict__ mem,
                       float* __restrict__ comb)
{
    size_t i = (size_t)blockIdx.x * 256 + threadIdx.x;   // over NNODES*32 float4s
    if (i >= (size_t)NNODES * 32) return;
    float4 a = ((const float4*)nf)[i];
    float4 b = ((const float4*)mem)[i];
    ((float4*)comb)[i] = make_float4(a.x + b.x, a.y + b.y, a.z + b.z, a.w + b.w);
}

__global__ void k_gatherq(const int* __restrict__ idx, const float* __restrict__ comb,
                          __nv_bfloat16* __restrict__ qh, __nv_bfloat16* __restrict__ ql, int n)
{
    int i = blockIdx.x * 256 + threadIdx.x;    // over n*32 float4s
    if (i >= n * 32) return;
    int node = i >> 5, c4 = i & 31;
    int src = idx[node];
    float4 a = ((const float4*)comb)[(size_t)src * 32 + c4];
    float v[4] = { a.x, a.y, a.z, a.w };
    size_t base = (size_t)i * 4;
    #pragma unroll
    for (int j = 0; j < 4; j++) split_store(qh, ql, base + j, v[j]);
}

__global__ void k_qhconst(const float* __restrict__ Wq, const float* __restrict__ bq,
                          const float* __restrict__ time_b, float* __restrict__ qhc)
{
    __shared__ float cb[128];
    int tid = threadIdx.x;
    if (tid < 128) cb[tid] = cosf(time_b[tid]);
    __syncthreads();
    float acc = bq[tid];
    const float* row = Wq + (size_t)tid * 256 + 128;
    #pragma unroll 8
    for (int j = 0; j < 128; j++) acc += row[j] * cb[j];
    qhc[tid] = acc;
}

__global__ void k_composeP(const float* __restrict__ W1, const float* __restrict__ Wo,
                           const float* __restrict__ bv, const float* __restrict__ bo,
                           float* __restrict__ Pt, float* __restrict__ cvec)
{
    int r = blockIdx.x;           // 0..127
    int a = threadIdx.x;          // 0..255
    __shared__ float w1row[256];
    __shared__ float red[256];
    w1row[a] = W1[(size_t)r * 384 + a];
    __syncthreads();
    float acc = 0.f;
    #pragma unroll 8
    for (int s = 0; s < 256; s++) acc += w1row[s] * Wo[(size_t)s * 256 + a];
    Pt[(size_t)a * 128 + r] = acc;
    red[a] = acc * bv[a] + w1row[a] * bo[a];
    __syncthreads();
    for (int off = 128; off; off >>= 1) {
        if (a < off) red[a] += red[a + off];
        __syncthreads();
    }
    if (a == 0) cvec[r] = red[0];
}

__global__ void k_composeC(const float* __restrict__ Pt, const float* __restrict__ Wv,
                           const float* __restrict__ W1,
                           __nv_bfloat16* __restrict__ Bh, __nv_bfloat16* __restrict__ Bl)
{
    int j = blockIdx.x;           // 0..895
    int r = threadIdx.x;          // 0..127
    if (j >= 768) {
        split_store(Bh, Bl, (size_t)r * 896 + j, W1[(size_t)r * 384 + 256 + (j - 768)]);
        return;
    }
    int h = j / 384, c = j % 384;
    __shared__ float wvcol[128];
    wvcol[r] = Wv[(size_t)(h * 128 + r) * 384 + c];
    __syncthreads();
    float acc = 0.f;
    #pragma unroll 8
    for (int d = 0; d < 128; d++)
        acc += Pt[(size_t)(h * 128 + d) * 128 + r] * wvcol[d];
    split_store(Bh, Bl, (size_t)r * 896 + j, acc);
}

__global__ void k_composeU(const float* __restrict__ Wk, const float* __restrict__ bk,
                           const float* __restrict__ Wq, const float* __restrict__ qhc,
                           __nv_bfloat16* __restrict__ Mh, __nv_bfloat16* __restrict__ Ml,
                           float* __restrict__ du)
{
    int hc = blockIdx.x;          // 0..769
    int h = hc / UROW, c = hc % UROW;
    int e = threadIdx.x;          // 0..159
    __shared__ float krow[128];
    if (e < 128)
        krow[e] = (c < 384) ? Wk[(size_t)(h * 128 + e) * 384 + c] : bk[h * 128 + e];
    __syncthreads();
    if (e < 128) {
        float acc = 0.f;
        #pragma unroll 8
        for (int d = 0; d < 128; d++)
            acc += krow[d] * Wq[(size_t)(h * 128 + d) * 256 + e];
        split_store(Mh, Ml, (size_t)hc * 128 + e, acc);
    } else if (e == 128) {
        float acc = 0.f;
        for (int d = 0; d < 128; d++) acc += krow[d] * qhc[h * 128 + d];
        du[hc] = acc;
    }
}

__global__ void k_splitW2(const float* __restrict__ W2,
                          __nv_bfloat16* __restrict__ wh, __nv_bfloat16* __restrict__ wl)
{
    int i = blockIdx.x * 256 + threadIdx.x;
    if (i < 128 * 128) split_store(wh, wl, i, W2[i]);
}

// ================= HMMA GEMM (cp.async double-buffered, 2 CTAs/SM) ===========
#define LDS_STRIDE 40                 // bf16 elems; 80B rows, ldmatrix conflict-free
#define TILE_B     (128 * LDS_STRIDE * 2)   // 10240 bytes per tile
#define STAGE_B    (4 * TILE_B)             // AsH AsL BsH BsL
#define SMEM_GEMM  (2 * STAGE_B)            // 81920

template<int EPI>
__global__ __launch_bounds__(256, 2)
void mma_gemm(const __nv_bfloat16* __restrict__ Ah, const __nv_bfloat16* __restrict__ Al, int lda,
              const __nv_bfloat16* __restrict__ A2h, const __nv_bfloat16* __restrict__ A2l, int lda2, int ksplit,
              const __nv_bfloat16* __restrict__ Bh, const __nv_bfloat16* __restrict__ Bl, int ldb,
              int ktiles, int Rtot,
              const float* __restrict__ bias, const float* __restrict__ bias2,
              const unsigned char* __restrict__ flags,
              float* __restrict__ OutF, int ldc,
              __nv_bfloat16* __restrict__ OutH, __nv_bfloat16* __restrict__ OutL, int Ntot)
{
    extern __shared__ char dsm[];
    const uint32_t sb = smem_u32(dsm);

    const int tid = threadIdx.x;
    const int lane = tid & 31, wid = tid >> 5;
    const int wm = wid >> 2, wn = wid & 3;      // 2 x 4 warp grid
    const int m0 = blockIdx.x * 128;
    const int r0 = blockIdx.y * 128;

    int vrows = Ntot - m0;
    if (vrows > 128) vrows = 128;
    if (vrows < 0) vrows = 0;

    float acc[4][4][4];
    #pragma unroll
    for (int a = 0; a < 4; a++)
        #pragma unroll
        for (int b = 0; b < 4; b++)
            #pragma unroll
            for (int c = 0; c < 4; c++) acc[a][b][c] = 0.f;

    const int lrow = tid >> 2;                 // 0..63 (+64 on 2nd pass)
    const int lc8 = (tid & 3) * 8;             // bf16 col within 32

    auto issue_stage = [&](int kt) {
        uint32_t base = sb + (kt & 1) * STAGE_B;
        const __nv_bfloat16 *sh, *sl; int st, k0;
        if (kt < ksplit) { sh = Ah;  sl = Al;  st = lda;  k0 = kt * 32; }
        else             { sh = A2h; sl = A2l; st = lda2; k0 = (kt - ksplit) * 32; }
        #pragma unroll
        for (int i = 0; i < 2; i++) {
            int row = lrow + i * 64;
            int srow = (row < vrows) ? row : 0;
            uint32_t sz = (row < vrows) ? 16u : 0u;
            uint32_t doff = row * (LDS_STRIDE * 2) + lc8 * 2;
            cpasync16(base + doff,
                      sh + (size_t)(m0 + srow) * st + k0 + lc8, sz);
            cpasync16(base + TILE_B + doff,
                      sl + (size_t)(m0 + srow) * st + k0 + lc8, sz);
            cpasync16(base + 2 * TILE_B + doff,
                      Bh + (size_t)(r0 + row) * ldb + kt * 32 + lc8);
            cpasync16(base + 3 * TILE_B + doff,
                      Bl + (size_t)(r0 + row) * ldb + kt * 32 + lc8);
        }
        asm volatile("cp.async.commit_group;" ::: "memory");
    };

    const int arow = wm * 64 + (lane & 15);
    const int acolsel = ((lane >> 4) & 1) * 8;
    const int l16 = lane & 15;
    const int brow = wn * 32 + (l16 & 7);
    const int bcolsel = ((l16 >> 3) & 1) * 8;

    issue_stage(0);

    for (int kt = 0; kt < ktiles; kt++) {
        if (kt + 1 < ktiles) {
            issue_stage(kt + 1);
            asm volatile("cp.async.wait_group 1;" ::: "memory");
        } else {
            asm volatile("cp.async.wait_group 0;" ::: "memory");
        }
        __syncthreads();

        const uint32_t cb = sb + (kt & 1) * STAGE_B;
        const uint32_t sAH = cb, sAL = cb + TILE_B;
        const uint32_t sBH = cb + 2 * TILE_B, sBL = cb + 3 * TILE_B;

        #pragma unroll
        for (int ks = 0; ks < 2; ks++) {
            const int acol = ks * 16 + acolsel;
            const int bcol = ks * 16 + bcolsel;
            uint32_t af[4][4], bhf[4][2], blf[4][2];
            #pragma unroll
            for (int mi = 0; mi < 4; mi++)
                ldm_x4(af[mi], sAH + (uint32_t)(((arow + mi * 16) * LDS_STRIDE + acol) * 2));
            #pragma unroll
            for (int ni = 0; ni < 4; ni++) {
                ldm_x2(bhf[ni], sBH + (uint32_t)(((brow + ni * 8) * LDS_STRIDE + bcol) * 2));
                ldm_x2(blf[ni], sBL + (uint32_t)(((brow + ni * 8) * LDS_STRIDE + bcol) * 2));
            }
            #pragma unroll
            for (int mi = 0; mi < 4; mi++)
                #pragma unroll
                for (int ni = 0; ni < 4; ni++) {
                    mma16816(acc[mi][ni], af[mi], bhf[ni]);   // Ah*Bh
                    mma16816(acc[mi][ni], af[mi], blf[ni]);   // Ah*Bl
                }
            #pragma unroll
            for (int mi = 0; mi < 4; mi++)
                ldm_x4(af[mi], sAL + (uint32_t)(((arow + mi * 16) * LDS_STRIDE + acol) * 2));
            #pragma unroll
            for (int mi = 0; mi < 4; mi++)
                #pragma unroll
                for (int ni = 0; ni < 4; ni++)
                    mma16816(acc[mi][ni], af[mi], bhf[ni]);   // Al*Bh
        }
        __syncthreads();
    }

    // ---- epilogue ----
    #pragma unroll
    for (int mi = 0; mi < 4; mi++) {
        int nrow0 = m0 + wm * 64 + mi * 16 + (lane >> 2);
        #pragma unroll
        for (int half = 0; half < 2; half++) {
            int n = nrow0 + half * 8;
            if (n >= Ntot) continue;
            bool fl = false;
            if (EPI == 1) fl = (flags[n] != 0);
            #pragma unroll
            for (int ni = 0; ni < 4; ni++) {
                int r = r0 + wn * 32 + ni * 8 + (lane & 3) * 2;
                float v0 = acc[mi][ni][half * 2 + 0];
                float v1 = acc[mi][ni][half * 2 + 1];
                if (EPI == 0) {
                    if (r < Rtot)     OutF[(size_t)n * ldc + r]     = v0 + bias[r];
                    if (r + 1 < Rtot) OutF[(size_t)n * ldc + r + 1] = v1 + bias[r + 1];
                } else if (EPI == 1) {
                    v0 += bias[r]     + (fl ? 0.f : bias2[r]);
                    v1 += bias[r + 1] + (fl ? 0.f : bias2[r + 1]);
                    v0 = fmaxf(v0, 0.f);
                    v1 = fmaxf(v1, 0.f);
                    __nv_bfloat16 h0 = __float2bfloat16(v0), h1 = __float2bfloat16(v1);
                    *(__nv_bfloat162*)(OutH + (size_t)n * 128 + r) = __halves2bfloat162(h0, h1);
                    __nv_bfloat16 l0 = __float2bfloat16(v0 - __bfloat162float(h0));
                    __nv_bfloat16 l1 = __float2bfloat16(v1 - __bfloat162float(h1));
                    *(__nv_bfloat162*)(OutL + (size_t)n * 128 + r) = __halves2bfloat162(l0, l1);
                } else {
                    OutF[(size_t)n * ldc + r]     = v0 + bias[r];
                    OutF[(size_t)n * ldc + r + 1] = v1 + bias[r + 1];
                }
            }
        }
    }
}

// ================= fused per-node edge kernel =================
// Invalid slots (mask=0, node has >=1 valid neighbor): attn is exactly 0, so
// their kv_time/kv_event are dead -> skip the gather/cos/scores, zero-fill kvc.
__global__ __launch_bounds__(256)
void k_edge(const int* __restrict__ neighbors, const float* __restrict__ t,
            const float* __restrict__ e_t, const int* __restrict__ e_id,
            const void* __restrict__ mask,
            const float* __restrict__ comb,
            const float* __restrict__ event_feat,
            const float* __restrict__ time_w, const float* __restrict__ time_b,
            const float* __restrict__ u,
            __nv_bfloat16* __restrict__ mixh, __nv_bfloat16* __restrict__ mixl,
            unsigned char* __restrict__ flags, int Ntot)
{
    int n = blockIdx.x;
    if (n >= Ntot) return;
    int tid = threadIdx.x;
    int lane = tid & 31, warp = tid >> 5;
    const int isb = g_mask_is_byte;

    __shared__ float kvc[KNB][DKF];
    __shared__ float usf[770];
    __shared__ float tw[128], tb[128];
    __shared__ float attn[2][KNB];
    __shared__ float sc[2][KNB];
    __shared__ int s_nonb;

    if (tid < 128) { tw[tid] = time_w[tid]; tb[tid] = time_b[tid]; }
    for (int i = tid; i < 770; i += 256) usf[i] = u[(size_t)n * 770 + i];
    if (warp == 0) {
        unsigned mbit = 0;
        if (lane < KNB) mbit = mget(mask, n * KNB + lane, isb) ? 1u : 0u;
        unsigned any = __ballot_sync(0xffffffffu, mbit != 0);
        if (lane == 0) s_nonb = (any == 0) ? 1 : 0;
    }
    __syncthreads();

    float tn = t[n];
    for (int k = warp; k < KNB; k += 8) {
        int mk = mget(mask, n * KNB + k, isb);
        int need = mk | s_nonb;
        int nb = neighbors[n * KNB + k];
        float dt = tn - e_t[n * KNB + k];
        int eid = e_id[n * KNB + k];
        const float4* cb4 = (const float4*)(comb + (size_t)nb * 128);
        const float4* ef4 = (const float4*)(event_feat + (size_t)eid * 128);
        for (int c4 = lane; c4 < 96; c4 += 32) {
            float4 v = make_float4(0.f, 0.f, 0.f, 0.f);
            if (c4 < 32) {
                if (mk) v = cb4[c4];
            } else if (c4 < 64) {
                if (need) {
                    int j = (c4 - 32) * 4;
                    v.x = __cosf(__fadd_rn(__fmul_rn(dt, tw[j + 0]), tb[j + 0]));
                    v.y = __cosf(__fadd_rn(__fmul_rn(dt, tw[j + 1]), tb[j + 1]));
                    v.z = __cosf(__fadd_rn(__fmul_rn(dt, tw[j + 2]), tb[j + 2]));
                    v.w = __cosf(__fadd_rn(__fmul_rn(dt, tw[j + 3]), tb[j + 3]));
                }
            } else {
                if (need) v = ef4[c4 - 64];
            }
            *(float4*)&kvc[k][c4 * 4] = v;
        }
    }
    __syncthreads();

    for (int p = warp; p < 2 * KNB; p += 8) {
        int h = p / KNB, k = p % KNB;
        int valid = mget(mask, n * KNB + k, isb) || s_nonb;   // warp-uniform
        if (!valid) continue;                                  // sc never read for invalid
        float s = 0.f;
        const float* uh = &usf[h * UROW];
        #pragma unroll 4
        for (int c = lane; c < DKF; c += 32) s += uh[c] * kvc[k][c];
        #pragma unroll
        for (int off = 16; off; off >>= 1) s += __shfl_down_sync(0xffffffffu, s, off);
        if (lane == 0) sc[h][k] = (s + uh[384]) * 0.08838834764831845f;
    }
    __syncthreads();

    if (warp < 2) {
        int h = warp;
        int valid = 0;
        float s = -INFINITY;
        if (lane < KNB) {
            valid = mget(mask, n * KNB + lane, isb) || s_nonb;
            if (valid) s = sc[h][lane];
        }
        float m = s;
        #pragma unroll
        for (int off = 16; off; off >>= 1) m = fmaxf(m, __shfl_xor_sync(0xffffffffu, m, off));
        float e = (lane < KNB && valid) ? expf(s - m) : 0.f;
        float sum = e;
        #pragma unroll
        for (int off = 16; off; off >>= 1) sum += __shfl_xor_sync(0xffffffffu, sum, off);
        if (lane < KNB) attn[h][lane] = e / sum;
    }
    __syncthreads();

    float gate = s_nonb ? 0.f : 1.f;
    for (int i = tid; i < 2 * DKF; i += 256) {
        int h = i / DKF, j = i % DKF;
        float acc = 0.f;
        #pragma unroll
        for (int k = 0; k < KNB; k++) acc += attn[h][k] * kvc[k][j];
        float m = acc * gate;
        __nv_bfloat16 hh = __float2bfloat16(m);
        mixh[(size_t)n * 768 + i] = hh;
        mixl[(size_t)n * 768 + i] = __float2bfloat16(m - __bfloat162float(hh));
    }
    if (tid == 0) flags[n] = (unsigned char)s_nonb;
}

// ================= launch =================
extern "C" void kernel_launch(void* const* d_in, const int* in_sizes, int n_in,
                              void* d_out, int out_size)
{
    const int*   idx        = (const int*)d_in[0];
    const float* t          = (const float*)d_in[1];
    const int*   neighbors  = (const int*)d_in[2];
    const float* e_t        = (const float*)d_in[3];
    const int*   e_id       = (const int*)d_in[4];
    const void*  mask       = d_in[5];
    const float* node_feat  = (const float*)d_in[6];
    const float* memory     = (const float*)d_in[7];
    const float* event_feat = (const float*)d_in[8];
    const float* time_w     = (const float*)d_in[9];
    const float* time_b     = (const float*)d_in[10];
    const float* Wq = (const float*)d_in[11];
    const float* bq = (const float*)d_in[12];
    const float* Wk = (const float*)d_in[13];
    const float* bk = (const float*)d_in[14];
    const float* Wv = (const float*)d_in[15];
    const float* bv = (const float*)d_in[16];
    const float* Wo = (const float*)d_in[17];
    const float* bo = (const float*)d_in[18];
    const float* W1 = (const float*)d_in[19];
    const float* b1 = (const float*)d_in[20];
    const float* W2 = (const float*)d_in[21];
    const float* b2 = (const float*)d_in[22];
    float* out = (float*)d_out;

    int N = in_sizes[0];
    if (N > NN) N = NN;

    float *u, *du, *Pt, *cvec, *qhc, *comb;
    __nv_bfloat16 *qh, *ql, *mh, *ml, *h1h, *h1l, *Muh, *Mul, *Bfh, *Bfl, *W2h, *W2l;
    unsigned char* flags;
    cudaGetSymbolAddress((void**)&u, g_u);
    cudaGetSymbolAddress((void**)&du, g_du);
    cudaGetSymbolAddress((void**)&Pt, g_Pt);
    cudaGetSymbolAddress((void**)&cvec, g_cvec);
    cudaGetSymbolAddress((void**)&qhc, g_qhc);
    cudaGetSymbolAddress((void**)&comb, g_comb);
    cudaGetSymbolAddress((void**)&qh, g_qh);
    cudaGetSymbolAddress((void**)&ql, g_ql);
    cudaGetSymbolAddress((void**)&mh, g_mh);
    cudaGetSymbolAddress((void**)&ml, g_ml);
    cudaGetSymbolAddress((void**)&h1h, g_h1h);
    cudaGetSymbolAddress((void**)&h1l, g_h1l);
    cudaGetSymbolAddress((void**)&Muh, g_Muh);
    cudaGetSymbolAddress((void**)&Mul, g_Mul);
    cudaGetSymbolAddress((void**)&Bfh, g_Bfh);
    cudaGetSymbolAddress((void**)&Bfl, g_Bfl);
    cudaGetSymbolAddress((void**)&W2h, g_W2h);
    cudaGetSymbolAddress((void**)&W2l, g_W2l);
    cudaGetSymbolAddress((void**)&flags, g_flags);

    cudaFuncSetAttribute(mma_gemm<0>, cudaFuncAttributeMaxDynamicSharedMemorySize, SMEM_GEMM);
    cudaFuncSetAttribute(mma_gemm<1>, cudaFuncAttributeMaxDynamicSharedMemorySize, SMEM_GEMM);
    cudaFuncSetAttribute(mma_gemm<2>, cudaFuncAttributeMaxDynamicSharedMemorySize, SMEM_GEMM);

    int mtiles = (N + 127) / 128;

    // launches 0..2 (keeps the u-GEMM as profiled launch index 3)
    k_qhconst<<<1, 256>>>(Wq, bq, time_b, qhc);
    k_composeU<<<770, 160>>>(Wk, bk, Wq, qhc, Muh, Mul, du);
    k_comb<<<(NNODES * 32 + 255) / 256, 256>>>(node_feat, memory, comb);

    // 3: u = Mu @ q + du  -> g_u (N x 770)   (qh written by launch 5 -- reorder!)
    // NOTE: gatherq must run BEFORE the u-GEMM; keep order: comb -> gatherq -> gemm
    k_gatherq<<<(N * 32 + 255) / 256, 256>>>(idx, comb, qh, ql, N);

    // 4: u = Mu @ q + du  -> g_u (N x 770)   K=128 (4 k-tiles), R=770 (7 r-tiles)
    mma_gemm<0><<<dim3(mtiles, 7), 256, SMEM_GEMM>>>(
        qh, ql, 128, nullptr, nullptr, 0, 1000,
        Muh, Mul, 128, 4, 770,
        du, nullptr, nullptr, u, 770, nullptr, nullptr, N);

    // 5..9
    k_composeP<<<128, 256>>>(W1, Wo, bv, bo, Pt, cvec);
    k_composeC<<<896, 128>>>(Pt, Wv, W1, Bfh, Bfl);
    k_splitW2<<<64, 256>>>(W2, W2h, W2l);
    k_flagreset<<<1, 1>>>();
    k_maskprobe<<<32, 256>>>((const unsigned char*)mask, 8192);

    // 10: fused edge kernel -> mixed hi/lo (N x 768)
    k_edge<<<N, 256>>>(neighbors, t, e_t, e_id, mask, comb,
                       event_feat, time_w, time_b, u, mh, ml, flags, N);

    // 11: h1 = relu(Bf @ [mixed, q] + b1 + gated cvec) -> h1 hi/lo (N x 128)
    mma_gemm<1><<<dim3(mtiles, 1), 256, SMEM_GEMM>>>(
        mh, ml, 768, qh, ql, 128, 24,
        Bfh, Bfl, 896, 28, 128,
        b1, cvec, flags, nullptr, 0, h1h, h1l, N);

    // 12: out = h1 @ W2^T + b2 -> d_out (N x 128)   K=128 (4 k-tiles)
    mma_gemm<2><<<dim3(mtiles, 1), 256, SMEM_GEMM>>>(
        h1h, h1l, 128, nullptr, nullptr, 0, 1000,
        W2h, W2l, 128, 4, 128,
        b2, nullptr, nullptr, out, 128, nullptr, nullptr, N);
}

// round 10
// speedup vs baseline: 2.2644x; 1.2092x over previous
#include <cuda_runtime.h>
#include <cuda_bf16.h>
#include <math.h>
#include <stdint.h>

#define NN    100000
#define KNB   20
#define DKF   384
#define UROW  385
#define NNODES 200000

// ================= device scratch =================
__device__ float g_comb[(size_t)NNODES * 128];   // node_feat + memory (precomputed)
__device__ float g_u[(size_t)NN * 770];          // u (2x385) f32, read by k_edge
__device__ uint4 g_qh[(size_t)NN * 16];          // q hi  (N x 128 bf16)
__device__ uint4 g_ql[(size_t)NN * 16];          // q lo
__device__ uint4 g_mh[(size_t)NN * 96];          // mixed hi (N x 768 bf16)
__device__ uint4 g_ml[(size_t)NN * 96];          // mixed lo
__device__ uint4 g_h1h[(size_t)NN * 16];         // h1 hi (N x 128 bf16)
__device__ uint4 g_h1l[(size_t)NN * 16];         // h1 lo
__device__ uint4 g_Muh[14336], g_Mul[14336];     // Mu 896(pad 770) x 128 bf16
__device__ uint4 g_Bfh[14336], g_Bfl[14336];     // Bf 128 x 896 bf16
__device__ uint4 g_W2h[2048], g_W2l[2048];       // W2 128 x 128 bf16
__device__ float g_du[896];
__device__ float g_Pt[256 * 128];
__device__ float g_cvec[128];
__device__ unsigned char g_flags[NN];
__device__ int   g_mask_is_byte;

// ================= PTX helpers (baseline features only) =================
__device__ __forceinline__ uint32_t smem_u32(const void* p) {
    uint32_t r;
    asm("{ .reg .u64 t; cvta.to.shared.u64 t, %1; cvt.u32.u64 %0, t; }" : "=r"(r) : "l"(p));
    return r;
}
__device__ __forceinline__ void ldm_x4(uint32_t* r, uint32_t addr) {
    asm volatile("ldmatrix.sync.aligned.m8n8.x4.shared.b16 {%0,%1,%2,%3}, [%4];"
                 : "=r"(r[0]), "=r"(r[1]), "=r"(r[2]), "=r"(r[3]) : "r"(addr));
}
__device__ __forceinline__ void ldm_x2(uint32_t* r, uint32_t addr) {
    asm volatile("ldmatrix.sync.aligned.m8n8.x2.shared.b16 {%0,%1}, [%2];"
                 : "=r"(r[0]), "=r"(r[1]) : "r"(addr));
}
__device__ __forceinline__ void mma16816(float* c, const uint32_t* a, const uint32_t* b) {
    asm volatile("mma.sync.aligned.m16n8k16.row.col.f32.bf16.bf16.f32 "
        "{%0,%1,%2,%3}, {%4,%5,%6,%7}, {%8,%9}, {%0,%1,%2,%3};"
        : "+f"(c[0]), "+f"(c[1]), "+f"(c[2]), "+f"(c[3])
        : "r"(a[0]), "r"(a[1]), "r"(a[2]), "r"(a[3]), "r"(b[0]), "r"(b[1]));
}
__device__ __forceinline__ void cpasync16(uint32_t dst, const void* src, uint32_t srcsize) {
    asm volatile("cp.async.cg.shared.global [%0], [%1], 16, %2;"
                 :: "r"(dst), "l"(src), "r"(srcsize));
}
__device__ __forceinline__ void cpasync16(uint32_t dst, const void* src) {
    asm volatile("cp.async.cg.shared.global [%0], [%1], 16;" :: "r"(dst), "l"(src));
}
__device__ __forceinline__ int mget(const void* m, int i, int isbyte) {
    return isbyte ? (((const unsigned char*)m)[i] != 0) : (((const int*)m)[i] != 0);
}

// ================= setup / compose =================
__device__ __forceinline__ void split_store(__nv_bfloat16* ph, __nv_bfloat16* pl, size_t i, float v) {
    __nv_bfloat16 h = __float2bfloat16(v);
    ph[i] = h;
    pl[i] = __float2bfloat16(v - __bfloat162float(h));
}

// composeU2: Mu + du, with qhconst folded in (coalesced Wq reads only).
// Mu[hc][e] = sum_d krow[d]*Wq[(h*128+d)*256+e]
// du[hc]    = sum_e cb[e]*(sum_d krow[d]*Wq[(h*128+d)*256+128+e]) + sum_e krow[e]*bq[h*128+e]
__global__ void k_composeU(const float* __restrict__ Wk, const float* __restrict__ bk,
                           const float* __restrict__ Wq, const float* __restrict__ bq,
                           const float* __restrict__ time_b,
                           __nv_bfloat16* __restrict__ Mh, __nv_bfloat16* __restrict__ Ml,
                           float* __restrict__ du)
{
    int hc = blockIdx.x;          // 0..769
    int h = hc / UROW, c = hc % UROW;
    int e = threadIdx.x;          // 0..127
    __shared__ float krow[128];
    __shared__ float cb[128];
    __shared__ float red[128];
    cb[e] = cosf(time_b[e]);
    krow[e] = (c < 384) ? Wk[(size_t)(h * 128 + e) * 384 + c] : bk[h * 128 + e];
    __syncthreads();
    float acc1 = 0.f, acc2 = 0.f;
    #pragma unroll 4
    for (int d = 0; d < 128; d++) {
        const float* row = Wq + (size_t)(h * 128 + d) * 256;
        float kd = krow[d];
        acc1 += kd * row[e];
        acc2 += kd * row[128 + e];
    }
    split_store(Mh, Ml, (size_t)hc * 128 + e, acc1);
    red[e] = acc2 * cb[e] + krow[e] * bq[h * 128 + e];
    __syncthreads();
    for (int off = 64; off; off >>= 1) {
        if (e < off) red[e] += red[e + off];
        __syncthreads();
    }
    if (e == 0) du[hc] = red[0];
}

// k_prep: comb (all nodes) + q gather/split + mask-layout probe, one launch.
__global__ void k_prep(const int* __restrict__ idx,
                       const float* __restrict__ nf, const float* __restrict__ mem,
                       float* __restrict__ comb,
                       __nv_bfloat16* __restrict__ qh, __nv_bfloat16* __restrict__ ql,
                       const unsigned char* __restrict__ mask,
                       int n, int nbComb, int nbGather)
{
    int b = blockIdx.x;
    if (b < nbComb) {
        size_t i = (size_t)b * 256 + threadIdx.x;
        if (i < (size_t)NNODES * 32) {
            float4 a = ((const float4*)nf)[i];
            float4 m = ((const float4*)mem)[i];
            ((float4*)comb)[i] = make_float4(a.x + m.x, a.y + m.y, a.z + m.z, a.w + m.w);
        }
    } else if (b < nbComb + nbGather) {
        int i = (b - nbComb) * 256 + threadIdx.x;
        if (i < n * 32) {
            int node = i >> 5, c4 = i & 31;
            int src = idx[node];
            float4 a = ((const float4*)nf)[(size_t)src * 32 + c4];
            float4 m = ((const float4*)mem)[(size_t)src * 32 + c4];
            float v[4] = { a.x + m.x, a.y + m.y, a.z + m.z, a.w + m.w };
            size_t base = (size_t)i * 4;
            #pragma unroll
            for (int j = 0; j < 4; j++) split_store(qh, ql, base + j, v[j]);
        }
    } else {
        int any = 0;
        for (int i = threadIdx.x; i < 8192; i += 256)
            if ((i & 3) != 0 && mask[i] != 0) any = 1;
        int r = __syncthreads_or(any);
        if (threadIdx.x == 0) g_mask_is_byte = r ? 1 : 0;
    }
}

__global__ void k_composeP(const float* __restrict__ W1, const float* __restrict__ Wo,
                           const float* __restrict__ bv, const float* __restrict__ bo,
                           float* __restrict__ Pt, float* __restrict__ cvec)
{
    int r = blockIdx.x;           // 0..127
    int a = threadIdx.x;          // 0..255
    __shared__ float w1row[256];
    __shared__ float red[256];
    w1row[a] = W1[(size_t)r * 384 + a];
    __syncthreads();
    float acc = 0.f;
    #pragma unroll 8
    for (int s = 0; s < 256; s++) acc += w1row[s] * Wo[(size_t)s * 256 + a];
    Pt[(size_t)a * 128 + r] = acc;
    red[a] = acc * bv[a] + w1row[a] * bo[a];
    __syncthreads();
    for (int off = 128; off; off >>= 1) {
        if (a < off) red[a] += red[a + off];
        __syncthreads();
    }
    if (a == 0) cvec[r] = red[0];
}

__global__ void k_composeC(const float* __restrict__ Pt, const float* __restrict__ Wv,
                           const float* __restrict__ W1,
                           __nv_bfloat16* __restrict__ Bh, __nv_bfloat16* __restrict__ Bl)
{
    int j = blockIdx.x;           // 0..895
    int r = threadIdx.x;          // 0..127
    if (j >= 768) {
        split_store(Bh, Bl, (size_t)r * 896 + j, W1[(size_t)r * 384 + 256 + (j - 768)]);
        return;
    }
    int h = j / 384, c = j % 384;
    __shared__ float wvcol[128];
    wvcol[r] = Wv[(size_t)(h * 128 + r) * 384 + c];
    __syncthreads();
    float acc = 0.f;
    #pragma unroll 8
    for (int d = 0; d < 128; d++)
        acc += Pt[(size_t)(h * 128 + d) * 128 + r] * wvcol[d];
    split_store(Bh, Bl, (size_t)r * 896 + j, acc);
}

__global__ void k_splitW2(const float* __restrict__ W2,
                          __nv_bfloat16* __restrict__ wh, __nv_bfloat16* __restrict__ wl)
{
    int i = blockIdx.x * 256 + threadIdx.x;
    if (i < 128 * 128) split_store(wh, wl, i, W2[i]);
}

// ================= HMMA GEMM (cp.async double-buffered, 2 CTAs/SM) ===========
#define LDS_STRIDE 40                 // bf16 elems; 80B rows, ldmatrix conflict-free
#define TILE_B     (128 * LDS_STRIDE * 2)   // 10240 bytes per tile
#define STAGE_B    (4 * TILE_B)             // AsH AsL BsH BsL
#define SMEM_GEMM  (2 * STAGE_B)            // 81920

template<int EPI>
__global__ __launch_bounds__(256, 2)
void mma_gemm(const __nv_bfloat16* __restrict__ Ah, const __nv_bfloat16* __restrict__ Al, int lda,
              const __nv_bfloat16* __restrict__ A2h, const __nv_bfloat16* __restrict__ A2l, int lda2, int ksplit,
              const __nv_bfloat16* __restrict__ Bh, const __nv_bfloat16* __restrict__ Bl, int ldb,
              int ktiles, int Rtot,
              const float* __restrict__ bias, const float* __restrict__ bias2,
              const unsigned char* __restrict__ flags,
              float* __restrict__ OutF, int ldc,
              __nv_bfloat16* __restrict__ OutH, __nv_bfloat16* __restrict__ OutL, int Ntot)
{
    extern __shared__ char dsm[];
    const uint32_t sb = smem_u32(dsm);

    const int tid = threadIdx.x;
    const int lane = tid & 31, wid = tid >> 5;
    const int wm = wid >> 2, wn = wid & 3;      // 2 x 4 warp grid
    const int m0 = blockIdx.x * 128;
    const int r0 = blockIdx.y * 128;

    int vrows = Ntot - m0;
    if (vrows > 128) vrows = 128;
    if (vrows < 0) vrows = 0;

    float acc[4][4][4];
    #pragma unroll
    for (int a = 0; a < 4; a++)
        #pragma unroll
        for (int b = 0; b < 4; b++)
            #pragma unroll
            for (int c = 0; c < 4; c++) acc[a][b][c] = 0.f;

    const int lrow = tid >> 2;                 // 0..63 (+64 on 2nd pass)
    const int lc8 = (tid & 3) * 8;             // bf16 col within 32

    auto issue_stage = [&](int kt) {
        uint32_t base = sb + (kt & 1) * STAGE_B;
        const __nv_bfloat16 *sh, *sl; int st, k0;
        if (kt < ksplit) { sh = Ah;  sl = Al;  st = lda;  k0 = kt * 32; }
        else             { sh = A2h; sl = A2l; st = lda2; k0 = (kt - ksplit) * 32; }
        #pragma unroll
        for (int i = 0; i < 2; i++) {
            int row = lrow + i * 64;
            int srow = (row < vrows) ? row : 0;
            uint32_t sz = (row < vrows) ? 16u : 0u;
            uint32_t doff = row * (LDS_STRIDE * 2) + lc8 * 2;
            cpasync16(base + doff,
                      sh + (size_t)(m0 + srow) * st + k0 + lc8, sz);
            cpasync16(base + TILE_B + doff,
                      sl + (size_t)(m0 + srow) * st + k0 + lc8, sz);
            cpasync16(base + 2 * TILE_B + doff,
                      Bh + (size_t)(r0 + row) * ldb + kt * 32 + lc8);
            cpasync16(base + 3 * TILE_B + doff,
                      Bl + (size_t)(r0 + row) * ldb + kt * 32 + lc8);
        }
        asm volatile("cp.async.commit_group;" ::: "memory");
    };

    const int arow = wm * 64 + (lane & 15);
    const int acolsel = ((lane >> 4) & 1) * 8;
    const int l16 = lane & 15;
    const int brow = wn * 32 + (l16 & 7);
    const int bcolsel = ((l16 >> 3) & 1) * 8;

    issue_stage(0);

    for (int kt = 0; kt < ktiles; kt++) {
        if (kt + 1 < ktiles) {
            issue_stage(kt + 1);
            asm volatile("cp.async.wait_group 1;" ::: "memory");
        } else {
            asm volatile("cp.async.wait_group 0;" ::: "memory");
        }
        __syncthreads();

        const uint32_t cb = sb + (kt & 1) * STAGE_B;
        const uint32_t sAH = cb, sAL = cb + TILE_B;
        const uint32_t sBH = cb + 2 * TILE_B, sBL = cb + 3 * TILE_B;

        #pragma unroll
        for (int ks = 0; ks < 2; ks++) {
            const int acol = ks * 16 + acolsel;
            const int bcol = ks * 16 + bcolsel;
            uint32_t af[4][4], bhf[4][2], blf[4][2];
            #pragma unroll
            for (int mi = 0; mi < 4; mi++)
                ldm_x4(af[mi], sAH + (uint32_t)(((arow + mi * 16) * LDS_STRIDE + acol) * 2));
            #pragma unroll
            for (int ni = 0; ni < 4; ni++) {
                ldm_x2(bhf[ni], sBH + (uint32_t)(((brow + ni * 8) * LDS_STRIDE + bcol) * 2));
                ldm_x2(blf[ni], sBL + (uint32_t)(((brow + ni * 8) * LDS_STRIDE + bcol) * 2));
            }
            #pragma unroll
            for (int mi = 0; mi < 4; mi++)
                #pragma unroll
                for (int ni = 0; ni < 4; ni++) {
                    mma16816(acc[mi][ni], af[mi], bhf[ni]);   // Ah*Bh
                    mma16816(acc[mi][ni], af[mi], blf[ni]);   // Ah*Bl
                }
            #pragma unroll
            for (int mi = 0; mi < 4; mi++)
                ldm_x4(af[mi], sAL + (uint32_t)(((arow + mi * 16) * LDS_STRIDE + acol) * 2));
            #pragma unroll
            for (int mi = 0; mi < 4; mi++)
                #pragma unroll
                for (int ni = 0; ni < 4; ni++)
                    mma16816(acc[mi][ni], af[mi], bhf[ni]);   // Al*Bh
        }
        __syncthreads();
    }

    // ---- epilogue ----
    #pragma unroll
    for (int mi = 0; mi < 4; mi++) {
        int nrow0 = m0 + wm * 64 + mi * 16 + (lane >> 2);
        #pragma unroll
        for (int half = 0; half < 2; half++) {
            int n = nrow0 + half * 8;
            if (n >= Ntot) continue;
            bool fl = false;
            if (EPI == 1) fl = (flags[n] != 0);
            #pragma unroll
            for (int ni = 0; ni < 4; ni++) {
                int r = r0 + wn * 32 + ni * 8 + (lane & 3) * 2;
                float v0 = acc[mi][ni][half * 2 + 0];
                float v1 = acc[mi][ni][half * 2 + 1];
                if (EPI == 0) {
                    if (r < Rtot)     OutF[(size_t)n * ldc + r]     = v0 + bias[r];
                    if (r + 1 < Rtot) OutF[(size_t)n * ldc + r + 1] = v1 + bias[r + 1];
                } else if (EPI == 1) {
                    v0 += bias[r]     + (fl ? 0.f : bias2[r]);
                    v1 += bias[r + 1] + (fl ? 0.f : bias2[r + 1]);
                    v0 = fmaxf(v0, 0.f);
                    v1 = fmaxf(v1, 0.f);
                    __nv_bfloat16 h0 = __float2bfloat16(v0), h1 = __float2bfloat16(v1);
                    *(__nv_bfloat162*)(OutH + (size_t)n * 128 + r) = __halves2bfloat162(h0, h1);
                    __nv_bfloat16 l0 = __float2bfloat16(v0 - __bfloat162float(h0));
                    __nv_bfloat16 l1 = __float2bfloat16(v1 - __bfloat162float(h1));
                    *(__nv_bfloat162*)(OutL + (size_t)n * 128 + r) = __halves2bfloat162(l0, l1);
                } else {
                    OutF[(size_t)n * ldc + r]     = v0 + bias[r];
                    OutF[(size_t)n * ldc + r + 1] = v1 + bias[r + 1];
                }
            }
        }
    }
}

// ================= fused per-node edge kernel (async-gather version) =========
__global__ __launch_bounds__(256)
void k_edge(const int* __restrict__ neighbors, const float* __restrict__ t,
            const float* __restrict__ e_t, const int* __restrict__ e_id,
            const void* __restrict__ mask,
            const float* __restrict__ comb,
            const float* __restrict__ event_feat,
            const float* __restrict__ time_w, const float* __restrict__ time_b,
            const float* __restrict__ u,
            __nv_bfloat16* __restrict__ mixh, __nv_bfloat16* __restrict__ mixl,
            unsigned char* __restrict__ flags, int Ntot)
{
    int n = blockIdx.x;
    if (n >= Ntot) return;
    int tid = threadIdx.x;
    int lane = tid & 31, warp = tid >> 5;
    const int isb = g_mask_is_byte;

    __shared__ float kvc[KNB][DKF];
    __shared__ float usf[770];
    __shared__ float tw[128], tb[128];
    __shared__ float attn[2][KNB];
    __shared__ float sc[2][KNB];
    __shared__ int s_nb[KNB], s_eid[KNB], s_mk[KNB];
    __shared__ float s_dt[KNB];
    __shared__ int s_nonb;

    // phase A: metadata + constants + u (all independent loads)
    if (tid < 128) { tw[tid] = time_w[tid]; tb[tid] = time_b[tid]; }
    for (int i = tid; i < 770; i += 256) usf[i] = u[(size_t)n * 770 + i];
    if (tid < KNB) {
        s_nb[tid]  = neighbors[n * KNB + tid];
        s_eid[tid] = e_id[n * KNB + tid];
        s_mk[tid]  = mget(mask, n * KNB + tid, isb);
        s_dt[tid]  = t[n] - e_t[n * KNB + tid];
    }
    __syncthreads();
    if (tid == 0) {
        int any = 0;
        #pragma unroll
        for (int k = 0; k < KNB; k++) any |= s_mk[k];
        s_nonb = !any;
    }
    __syncthreads();
    const int nonb = s_nonb;
    const uint32_t kvb = smem_u32(kvc);

    // phase B: all gathers as cp.async (zero-fill when gated off)
    for (int i = tid; i < 640; i += 256) {
        int k = i >> 5, c4 = i & 31;
        int mk = s_mk[k];
        cpasync16(kvb + (uint32_t)(k * DKF + c4 * 4) * 4,
                  comb + (size_t)s_nb[k] * 128 + c4 * 4, mk ? 16u : 0u);
        cpasync16(kvb + (uint32_t)(k * DKF + 256 + c4 * 4) * 4,
                  event_feat + (size_t)s_eid[k] * 128 + c4 * 4, (mk | nonb) ? 16u : 0u);
    }
    asm volatile("cp.async.commit_group;" ::: "memory");

    // phase C: time encode while gathers are in flight
    for (int i = tid; i < 640; i += 256) {
        int k = i >> 5, c4 = i & 31;
        float4 v = make_float4(0.f, 0.f, 0.f, 0.f);
        if (s_mk[k] | nonb) {
            float dt = s_dt[k];
            int j = c4 * 4;
            v.x = __cosf(__fadd_rn(__fmul_rn(dt, tw[j + 0]), tb[j + 0]));
            v.y = __cosf(__fadd_rn(__fmul_rn(dt, tw[j + 1]), tb[j + 1]));
            v.z = __cosf(__fadd_rn(__fmul_rn(dt, tw[j + 2]), tb[j + 2]));
            v.w = __cosf(__fadd_rn(__fmul_rn(dt, tw[j + 3]), tb[j + 3]));
        }
        *(float4*)&kvc[k][128 + c4 * 4] = v;
    }
    asm volatile("cp.async.wait_group 0;" ::: "memory");
    __syncthreads();

    // scores: 40 (head,k) dot products of length 384 (valid slots only)
    for (int p = warp; p < 2 * KNB; p += 8) {
        int h = p / KNB, k = p % KNB;
        if (!(s_mk[k] | nonb)) continue;          // warp-uniform
        float s = 0.f;
        const float* uh = &usf[h * UROW];
        #pragma unroll 4
        for (int c = lane; c < DKF; c += 32) s += uh[c] * kvc[k][c];
        #pragma unroll
        for (int off = 16; off; off >>= 1) s += __shfl_down_sync(0xffffffffu, s, off);
        if (lane == 0) sc[h][k] = (s + uh[384]) * 0.08838834764831845f;
    }
    __syncthreads();

    // masked softmax per head (warps 0,1)
    if (warp < 2) {
        int h = warp;
        int valid = 0;
        float s = -INFINITY;
        if (lane < KNB) {
            valid = s_mk[lane] | nonb;
            if (valid) s = sc[h][lane];
        }
        float m = s;
        #pragma unroll
        for (int off = 16; off; off >>= 1) m = fmaxf(m, __shfl_xor_sync(0xffffffffu, m, off));
        float e = (lane < KNB && valid) ? expf(s - m) : 0.f;
        float sum = e;
        #pragma unroll
        for (int off = 16; off; off >>= 1) sum += __shfl_xor_sync(0xffffffffu, sum, off);
        if (lane < KNB) attn[h][lane] = e / sum;
    }
    __syncthreads();

    // mixed[h][j] = sum_k attn[h][k]*kvc[k][j]  (pairs -> bf16x2 stores)
    float gate = nonb ? 0.f : 1.f;
    for (int i2 = tid; i2 < DKF; i2 += 256) {      // 384 pairs over 768 elems
        int i = i2 * 2;
        int h = i / DKF, j = i % DKF;
        float a0 = 0.f, a1 = 0.f;
        #pragma unroll
        for (int k = 0; k < KNB; k++) {
            float w = attn[h][k];
            a0 += w * kvc[k][j];
            a1 += w * kvc[k][j + 1];
        }
        a0 *= gate; a1 *= gate;
        __nv_bfloat16 h0 = __float2bfloat16(a0), h1 = __float2bfloat16(a1);
        *(__nv_bfloat162*)(mixh + (size_t)n * 768 + i) = __halves2bfloat162(h0, h1);
        __nv_bfloat16 l0 = __float2bfloat16(a0 - __bfloat162float(h0));
        __nv_bfloat16 l1 = __float2bfloat16(a1 - __bfloat162float(h1));
        *(__nv_bfloat162*)(mixl + (size_t)n * 768 + i) = __halves2bfloat162(l0, l1);
    }
    if (tid == 0) flags[n] = (unsigned char)nonb;
}

// ================= launch =================
extern "C" void kernel_launch(void* const* d_in, const int* in_sizes, int n_in,
                              void* d_out, int out_size)
{
    const int*   idx        = (const int*)d_in[0];
    const float* t          = (const float*)d_in[1];
    const int*   neighbors  = (const int*)d_in[2];
    const float* e_t        = (const float*)d_in[3];
    const int*   e_id       = (const int*)d_in[4];
    const void*  mask       = d_in[5];
    const float* node_feat  = (const float*)d_in[6];
    const float* memory     = (const float*)d_in[7];
    const float* event_feat = (const float*)d_in[8];
    const float* time_w     = (const float*)d_in[9];
    const float* time_b     = (const float*)d_in[10];
    const float* Wq = (const float*)d_in[11];
    const float* bq = (const float*)d_in[12];
    const float* Wk = (const float*)d_in[13];
    const float* bk = (const float*)d_in[14];
    const float* Wv = (const float*)d_in[15];
    const float* bv = (const float*)d_in[16];
    const float* Wo = (const float*)d_in[17];
    const float* bo = (const float*)d_in[18];
    const float* W1 = (const float*)d_in[19];
    const float* b1 = (const float*)d_in[20];
    const float* W2 = (const float*)d_in[21];
    const float* b2 = (const float*)d_in[22];
    float* out = (float*)d_out;

    int N = in_sizes[0];
    if (N > NN) N = NN;

    float *u, *du, *Pt, *cvec, *comb;
    __nv_bfloat16 *qh, *ql, *mh, *ml, *h1h, *h1l, *Muh, *Mul, *Bfh, *Bfl, *W2h, *W2l;
    unsigned char* flags;
    cudaGetSymbolAddress((void**)&u, g_u);
    cudaGetSymbolAddress((void**)&du, g_du);
    cudaGetSymbolAddress((void**)&Pt, g_Pt);
    cudaGetSymbolAddress((void**)&cvec, g_cvec);
    cudaGetSymbolAddress((void**)&comb, g_comb);
    cudaGetSymbolAddress((void**)&qh, g_qh);
    cudaGetSymbolAddress((void**)&ql, g_ql);
    cudaGetSymbolAddress((void**)&mh, g_mh);
    cudaGetSymbolAddress((void**)&ml, g_ml);
    cudaGetSymbolAddress((void**)&h1h, g_h1h);
    cudaGetSymbolAddress((void**)&h1l, g_h1l);
    cudaGetSymbolAddress((void**)&Muh, g_Muh);
    cudaGetSymbolAddress((void**)&Mul, g_Mul);
    cudaGetSymbolAddress((void**)&Bfh, g_Bfh);
    cudaGetSymbolAddress((void**)&Bfl, g_Bfl);
    cudaGetSymbolAddress((void**)&W2h, g_W2h);
    cudaGetSymbolAddress((void**)&W2l, g_W2l);
    cudaGetSymbolAddress((void**)&flags, g_flags);

    cudaFuncSetAttribute(mma_gemm<0>, cudaFuncAttributeMaxDynamicSharedMemorySize, SMEM_GEMM);
    cudaFuncSetAttribute(mma_gemm<1>, cudaFuncAttributeMaxDynamicSharedMemorySize, SMEM_GEMM);
    cudaFuncSetAttribute(mma_gemm<2>, cudaFuncAttributeMaxDynamicSharedMemorySize, SMEM_GEMM);

    int mtiles = (N + 127) / 128;
    int nbComb = (NNODES * 32 + 255) / 256;
    int nbGather = (N * 32 + 255) / 256;

    // 0: composeU (qhconst folded in)
    k_composeU<<<770, 128>>>(Wk, bk, Wq, bq, time_b, Muh, Mul, du);
    // 1: fused prep (comb + q gather/split + mask probe)
    k_prep<<<nbComb + nbGather + 1, 256>>>(idx, node_feat, memory, comb,
                                           qh, ql, (const unsigned char*)mask,
                                           N, nbComb, nbGather);
    // 2: u = Mu @ q + du  -> g_u (N x 770)
    mma_gemm<0><<<dim3(mtiles, 7), 256, SMEM_GEMM>>>(
        qh, ql, 128, nullptr, nullptr, 0, 1000,
        Muh, Mul, 128, 4, 770,
        du, nullptr, nullptr, u, 770, nullptr, nullptr, N);
    // 3: fused edge kernel -> mixed hi/lo (N x 768)   [ncu profiles this slot]
    k_edge<<<N, 256>>>(neighbors, t, e_t, e_id, mask, comb,
                       event_feat, time_w, time_b, u, mh, ml, flags, N);
    // 4..6: compose final weights
    k_composeP<<<128, 256>>>(W1, Wo, bv, bo, Pt, cvec);
    k_composeC<<<896, 128>>>(Pt, Wv, W1, Bfh, Bfl);
    k_splitW2<<<64, 256>>>(W2, W2h, W2l);
    // 7: h1 = relu(Bf @ [mixed, q] + b1 + gated cvec) -> h1 hi/lo (N x 128)
    mma_gemm<1><<<dim3(mtiles, 1), 256, SMEM_GEMM>>>(
        mh, ml, 768, qh, ql, 128, 24,
        Bfh, Bfl, 896, 28, 128,
        b1, cvec, flags, nullptr, 0, h1h, h1l, N);
    // 8: out = h1 @ W2^T + b2 -> d_out (N x 128)
    mma_gemm<2><<<dim3(mtiles, 1), 256, SMEM_GEMM>>>(
        h1h, h1l, 128, nullptr, nullptr, 0, 1000,
        W2h, W2l, 128, 4, 128,
        b2, nullptr, nullptr, out, 128, nullptr, nullptr, N);
}

// round 11
// speedup vs baseline: 2.6312x; 1.1620x over previous
#include <cuda_runtime.h>
#include <cuda_bf16.h>
#include <math.h>
#include <stdint.h>

#define NN    100000
#define KNB   20
#define DKF   384
#define UPAD  400     // padded per-head u stride (float4-aligned)
#define NNODES 200000

// ================= device scratch =================
__device__ float g_comb[(size_t)NNODES * 128];   // node_feat + memory (precomputed)
__device__ float g_u[(size_t)NN * 800];          // u padded: [h0 c0..384 pad][h1 c0..384 pad]
__device__ uint4 g_qh[(size_t)NN * 16];          // q hi  (N x 128 bf16)
__device__ uint4 g_ql[(size_t)NN * 16];          // q lo
__device__ uint4 g_mh[(size_t)NN * 96];          // mixed hi (N x 768 bf16)
__device__ uint4 g_ml[(size_t)NN * 96];          // mixed lo
__device__ uint4 g_h1h[(size_t)NN * 16];         // h1 hi (N x 128 bf16)
__device__ uint4 g_h1l[(size_t)NN * 16];         // h1 lo
__device__ uint4 g_Muh[14336], g_Mul[14336];     // Mu 800(pad 896) x 128 bf16
__device__ uint4 g_Bfh[14336], g_Bfl[14336];     // Bf 128 x 896 bf16
__device__ uint4 g_W2h[2048], g_W2l[2048];       // W2 128 x 128 bf16
__device__ float g_du[896];
__device__ float g_Pt[256 * 128];
__device__ float g_cvec[128];
__device__ unsigned char g_flags[NN];
__device__ int   g_mask_is_byte;

// ================= PTX helpers (baseline features only) =================
__device__ __forceinline__ uint32_t smem_u32(const void* p) {
    uint32_t r;
    asm("{ .reg .u64 t; cvta.to.shared.u64 t, %1; cvt.u32.u64 %0, t; }" : "=r"(r) : "l"(p));
    return r;
}
__device__ __forceinline__ void ldm_x4(uint32_t* r, uint32_t addr) {
    asm volatile("ldmatrix.sync.aligned.m8n8.x4.shared.b16 {%0,%1,%2,%3}, [%4];"
                 : "=r"(r[0]), "=r"(r[1]), "=r"(r[2]), "=r"(r[3]) : "r"(addr));
}
__device__ __forceinline__ void ldm_x2(uint32_t* r, uint32_t addr) {
    asm volatile("ldmatrix.sync.aligned.m8n8.x2.shared.b16 {%0,%1}, [%2];"
                 : "=r"(r[0]), "=r"(r[1]) : "r"(addr));
}
__device__ __forceinline__ void mma16816(float* c, const uint32_t* a, const uint32_t* b) {
    asm volatile("mma.sync.aligned.m16n8k16.row.col.f32.bf16.bf16.f32 "
        "{%0,%1,%2,%3}, {%4,%5,%6,%7}, {%8,%9}, {%0,%1,%2,%3};"
        : "+f"(c[0]), "+f"(c[1]), "+f"(c[2]), "+f"(c[3])
        : "r"(a[0]), "r"(a[1]), "r"(a[2]), "r"(a[3]), "r"(b[0]), "r"(b[1]));
}
__device__ __forceinline__ void cpasync16(uint32_t dst, const void* src, uint32_t srcsize) {
    asm volatile("cp.async.cg.shared.global [%0], [%1], 16, %2;"
                 :: "r"(dst), "l"(src), "r"(srcsize));
}
__device__ __forceinline__ void cpasync16(uint32_t dst, const void* src) {
    asm volatile("cp.async.cg.shared.global [%0], [%1], 16;" :: "r"(dst), "l"(src));
}
__device__ __forceinline__ int mget(const void* m, int i, int isbyte) {
    return isbyte ? (((const unsigned char*)m)[i] != 0) : (((const int*)m)[i] != 0);
}

// ================= setup / compose =================
__device__ __forceinline__ void split_store(__nv_bfloat16* ph, __nv_bfloat16* pl, size_t i, float v) {
    __nv_bfloat16 h = __float2bfloat16(v);
    ph[i] = h;
    pl[i] = __float2bfloat16(v - __bfloat162float(h));
}

// composeU: Mu + du with qhconst folded in; PADDED rows (800 = 2 x 400).
__global__ void k_composeU(const float* __restrict__ Wk, const float* __restrict__ bk,
                           const float* __restrict__ Wq, const float* __restrict__ bq,
                           const float* __restrict__ time_b,
                           __nv_bfloat16* __restrict__ Mh, __nv_bfloat16* __restrict__ Ml,
                           float* __restrict__ du)
{
    int hc = blockIdx.x;          // 0..799
    int h = hc / UPAD, c = hc % UPAD;
    int e = threadIdx.x;          // 0..127
    __shared__ float krow[128];
    __shared__ float cb[128];
    __shared__ float red[128];
    cb[e] = cosf(time_b[e]);
    krow[e] = (c < 384) ? Wk[(size_t)(h * 128 + e) * 384 + c]
            : ((c == 384) ? bk[h * 128 + e] : 0.f);
    __syncthreads();
    float acc1 = 0.f, acc2 = 0.f;
    #pragma unroll 4
    for (int d = 0; d < 128; d++) {
        const float* row = Wq + (size_t)(h * 128 + d) * 256;
        float kd = krow[d];
        acc1 += kd * row[e];
        acc2 += kd * row[128 + e];
    }
    split_store(Mh, Ml, (size_t)hc * 128 + e, acc1);
    red[e] = acc2 * cb[e] + krow[e] * bq[h * 128 + e];
    __syncthreads();
    for (int off = 64; off; off >>= 1) {
        if (e < off) red[e] += red[e + off];
        __syncthreads();
    }
    if (e == 0) du[hc] = red[0];
}

// k_prep: comb (all nodes) + q gather/split + mask-layout probe, one launch.
__global__ void k_prep(const int* __restrict__ idx,
                       const float* __restrict__ nf, const float* __restrict__ mem,
                       float* __restrict__ comb,
                       __nv_bfloat16* __restrict__ qh, __nv_bfloat16* __restrict__ ql,
                       const unsigned char* __restrict__ mask,
                       int n, int nbComb, int nbGather)
{
    int b = blockIdx.x;
    if (b < nbComb) {
        size_t i = (size_t)b * 256 + threadIdx.x;
        if (i < (size_t)NNODES * 32) {
            float4 a = ((const float4*)nf)[i];
            float4 m = ((const float4*)mem)[i];
            ((float4*)comb)[i] = make_float4(a.x + m.x, a.y + m.y, a.z + m.z, a.w + m.w);
        }
    } else if (b < nbComb + nbGather) {
        int i = (b - nbComb) * 256 + threadIdx.x;
        if (i < n * 32) {
            int node = i >> 5, c4 = i & 31;
            int src = idx[node];
            float4 a = ((const float4*)nf)[(size_t)src * 32 + c4];
            float4 m = ((const float4*)mem)[(size_t)src * 32 + c4];
            float v[4] = { a.x + m.x, a.y + m.y, a.z + m.z, a.w + m.w };
            size_t base = (size_t)i * 4;
            #pragma unroll
            for (int j = 0; j < 4; j++) split_store(qh, ql, base + j, v[j]);
        }
    } else {
        int any = 0;
        for (int i = threadIdx.x; i < 8192; i += 256)
            if ((i & 3) != 0 && mask[i] != 0) any = 1;
        int r = __syncthreads_or(any);
        if (threadIdx.x == 0) g_mask_is_byte = r ? 1 : 0;
    }
}

__global__ void k_composeP(const float* __restrict__ W1, const float* __restrict__ Wo,
                           const float* __restrict__ bv, const float* __restrict__ bo,
                           float* __restrict__ Pt, float* __restrict__ cvec)
{
    int r = blockIdx.x;           // 0..127
    int a = threadIdx.x;          // 0..255
    __shared__ float w1row[256];
    __shared__ float red[256];
    w1row[a] = W1[(size_t)r * 384 + a];
    __syncthreads();
    float acc = 0.f;
    #pragma unroll 8
    for (int s = 0; s < 256; s++) acc += w1row[s] * Wo[(size_t)s * 256 + a];
    Pt[(size_t)a * 128 + r] = acc;
    red[a] = acc * bv[a] + w1row[a] * bo[a];
    __syncthreads();
    for (int off = 128; off; off >>= 1) {
        if (a < off) red[a] += red[a + off];
        __syncthreads();
    }
    if (a == 0) cvec[r] = red[0];
}

__global__ void k_composeC(const float* __restrict__ Pt, const float* __restrict__ Wv,
                           const float* __restrict__ W1,
                           __nv_bfloat16* __restrict__ Bh, __nv_bfloat16* __restrict__ Bl)
{
    int j = blockIdx.x;           // 0..895
    int r = threadIdx.x;          // 0..127
    if (j >= 768) {
        split_store(Bh, Bl, (size_t)r * 896 + j, W1[(size_t)r * 384 + 256 + (j - 768)]);
        return;
    }
    int h = j / 384, c = j % 384;
    __shared__ float wvcol[128];
    wvcol[r] = Wv[(size_t)(h * 128 + r) * 384 + c];
    __syncthreads();
    float acc = 0.f;
    #pragma unroll 8
    for (int d = 0; d < 128; d++)
        acc += Pt[(size_t)(h * 128 + d) * 128 + r] * wvcol[d];
    split_store(Bh, Bl, (size_t)r * 896 + j, acc);
}

__global__ void k_splitW2(const float* __restrict__ W2,
                          __nv_bfloat16* __restrict__ wh, __nv_bfloat16* __restrict__ wl)
{
    int i = blockIdx.x * 256 + threadIdx.x;
    if (i < 128 * 128) split_store(wh, wl, i, W2[i]);
}

// ================= HMMA GEMM (cp.async double-buffered, 2 CTAs/SM) ===========
#define LDS_STRIDE 40                 // bf16 elems; 80B rows, ldmatrix conflict-free
#define TILE_B     (128 * LDS_STRIDE * 2)   // 10240 bytes per tile
#define STAGE_B    (4 * TILE_B)             // AsH AsL BsH BsL
#define SMEM_GEMM  (2 * STAGE_B)            // 81920

template<int EPI>
__global__ __launch_bounds__(256, 2)
void mma_gemm(const __nv_bfloat16* __restrict__ Ah, const __nv_bfloat16* __restrict__ Al, int lda,
              const __nv_bfloat16* __restrict__ A2h, const __nv_bfloat16* __restrict__ A2l, int lda2, int ksplit,
              const __nv_bfloat16* __restrict__ Bh, const __nv_bfloat16* __restrict__ Bl, int ldb,
              int ktiles, int Rtot,
              const float* __restrict__ bias, const float* __restrict__ bias2,
              const unsigned char* __restrict__ flags,
              float* __restrict__ OutF, int ldc,
              __nv_bfloat16* __restrict__ OutH, __nv_bfloat16* __restrict__ OutL, int Ntot)
{
    extern __shared__ char dsm[];
    const uint32_t sb = smem_u32(dsm);

    const int tid = threadIdx.x;
    const int lane = tid & 31, wid = tid >> 5;
    const int wm = wid >> 2, wn = wid & 3;      // 2 x 4 warp grid
    const int m0 = blockIdx.x * 128;
    const int r0 = blockIdx.y * 128;

    int vrows = Ntot - m0;
    if (vrows > 128) vrows = 128;
    if (vrows < 0) vrows = 0;

    float acc[4][4][4];
    #pragma unroll
    for (int a = 0; a < 4; a++)
        #pragma unroll
        for (int b = 0; b < 4; b++)
            #pragma unroll
            for (int c = 0; c < 4; c++) acc[a][b][c] = 0.f;

    const int lrow = tid >> 2;                 // 0..63 (+64 on 2nd pass)
    const int lc8 = (tid & 3) * 8;             // bf16 col within 32

    auto issue_stage = [&](int kt) {
        uint32_t base = sb + (kt & 1) * STAGE_B;
        const __nv_bfloat16 *sh, *sl; int st, k0;
        if (kt < ksplit) { sh = Ah;  sl = Al;  st = lda;  k0 = kt * 32; }
        else             { sh = A2h; sl = A2l; st = lda2; k0 = (kt - ksplit) * 32; }
        #pragma unroll
        for (int i = 0; i < 2; i++) {
            int row = lrow + i * 64;
            int srow = (row < vrows) ? row : 0;
            uint32_t sz = (row < vrows) ? 16u : 0u;
            uint32_t doff = row * (LDS_STRIDE * 2) + lc8 * 2;
            cpasync16(base + doff,
                      sh + (size_t)(m0 + srow) * st + k0 + lc8, sz);
            cpasync16(base + TILE_B + doff,
                      sl + (size_t)(m0 + srow) * st + k0 + lc8, sz);
            cpasync16(base + 2 * TILE_B + doff,
                      Bh + (size_t)(r0 + row) * ldb + kt * 32 + lc8);
            cpasync16(base + 3 * TILE_B + doff,
                      Bl + (size_t)(r0 + row) * ldb + kt * 32 + lc8);
        }
        asm volatile("cp.async.commit_group;" ::: "memory");
    };

    const int arow = wm * 64 + (lane & 15);
    const int acolsel = ((lane >> 4) & 1) * 8;
    const int l16 = lane & 15;
    const int brow = wn * 32 + (l16 & 7);
    const int bcolsel = ((l16 >> 3) & 1) * 8;

    issue_stage(0);

    for (int kt = 0; kt < ktiles; kt++) {
        if (kt + 1 < ktiles) {
            issue_stage(kt + 1);
            asm volatile("cp.async.wait_group 1;" ::: "memory");
        } else {
            asm volatile("cp.async.wait_group 0;" ::: "memory");
        }
        __syncthreads();

        const uint32_t cb = sb + (kt & 1) * STAGE_B;
        const uint32_t sAH = cb, sAL = cb + TILE_B;
        const uint32_t sBH = cb + 2 * TILE_B, sBL = cb + 3 * TILE_B;

        #pragma unroll
        for (int ks = 0; ks < 2; ks++) {
            const int acol = ks * 16 + acolsel;
            const int bcol = ks * 16 + bcolsel;
            uint32_t af[4][4], bhf[4][2], blf[4][2];
            #pragma unroll
            for (int mi = 0; mi < 4; mi++)
                ldm_x4(af[mi], sAH + (uint32_t)(((arow + mi * 16) * LDS_STRIDE + acol) * 2));
            #pragma unroll
            for (int ni = 0; ni < 4; ni++) {
                ldm_x2(bhf[ni], sBH + (uint32_t)(((brow + ni * 8) * LDS_STRIDE + bcol) * 2));
                ldm_x2(blf[ni], sBL + (uint32_t)(((brow + ni * 8) * LDS_STRIDE + bcol) * 2));
            }
            #pragma unroll
            for (int mi = 0; mi < 4; mi++)
                #pragma unroll
                for (int ni = 0; ni < 4; ni++) {
                    mma16816(acc[mi][ni], af[mi], bhf[ni]);   // Ah*Bh
                    mma16816(acc[mi][ni], af[mi], blf[ni]);   // Ah*Bl
                }
            #pragma unroll
            for (int mi = 0; mi < 4; mi++)
                ldm_x4(af[mi], sAL + (uint32_t)(((arow + mi * 16) * LDS_STRIDE + acol) * 2));
            #pragma unroll
            for (int mi = 0; mi < 4; mi++)
                #pragma unroll
                for (int ni = 0; ni < 4; ni++)
                    mma16816(acc[mi][ni], af[mi], bhf[ni]);   // Al*Bh
        }
        __syncthreads();
    }

    // ---- epilogue ----
    #pragma unroll
    for (int mi = 0; mi < 4; mi++) {
        int nrow0 = m0 + wm * 64 + mi * 16 + (lane >> 2);
        #pragma unroll
        for (int half = 0; half < 2; half++) {
            int n = nrow0 + half * 8;
            if (n >= Ntot) continue;
            bool fl = false;
            if (EPI == 1) fl = (flags[n] != 0);
            #pragma unroll
            for (int ni = 0; ni < 4; ni++) {
                int r = r0 + wn * 32 + ni * 8 + (lane & 3) * 2;
                float v0 = acc[mi][ni][half * 2 + 0];
                float v1 = acc[mi][ni][half * 2 + 1];
                if (EPI == 0) {
                    if (r < Rtot)     OutF[(size_t)n * ldc + r]     = v0 + bias[r];
                    if (r + 1 < Rtot) OutF[(size_t)n * ldc + r + 1] = v1 + bias[r + 1];
                } else if (EPI == 1) {
                    v0 += bias[r]     + (fl ? 0.f : bias2[r]);
                    v1 += bias[r + 1] + (fl ? 0.f : bias2[r + 1]);
                    v0 = fmaxf(v0, 0.f);
                    v1 = fmaxf(v1, 0.f);
                    __nv_bfloat16 h0 = __float2bfloat16(v0), h1 = __float2bfloat16(v1);
                    *(__nv_bfloat162*)(OutH + (size_t)n * 128 + r) = __halves2bfloat162(h0, h1);
                    __nv_bfloat16 l0 = __float2bfloat16(v0 - __bfloat162float(h0));
                    __nv_bfloat16 l1 = __float2bfloat16(v1 - __bfloat162float(h1));
                    *(__nv_bfloat162*)(OutL + (size_t)n * 128 + r) = __halves2bfloat162(l0, l1);
                } else {
                    OutF[(size_t)n * ldc + r]     = v0 + bias[r];
                    OutF[(size_t)n * ldc + r + 1] = v1 + bias[r + 1];
                }
            }
        }
    }
}

// ================= fused per-node edge kernel =================
// u in registers (both heads), every kvc read feeds BOTH heads -> smem bytes halved.
__global__ __launch_bounds__(256)
void k_edge(const int* __restrict__ neighbors, const float* __restrict__ t,
            const float* __restrict__ e_t, const int* __restrict__ e_id,
            const void* __restrict__ mask,
            const float* __restrict__ comb,
            const float* __restrict__ event_feat,
            const float* __restrict__ time_w, const float* __restrict__ time_b,
            const float* __restrict__ u,
            __nv_bfloat16* __restrict__ mixh, __nv_bfloat16* __restrict__ mixl,
            unsigned char* __restrict__ flags, int Ntot)
{
    int n = blockIdx.x;
    if (n >= Ntot) return;
    int tid = threadIdx.x;
    int lane = tid & 31, warp = tid >> 5;
    const int isb = g_mask_is_byte;

    __shared__ float kvc[KNB][DKF];
    __shared__ float tw[128], tb[128];
    __shared__ float attn[2][KNB];
    __shared__ float sc[2][KNB];
    __shared__ int s_nb[KNB], s_eid[KNB], s_mk[KNB];
    __shared__ float s_dt[KNB];
    __shared__ int s_nonb;

    // phase A: metadata + constants
    if (tid < 128) { tw[tid] = time_w[tid]; tb[tid] = time_b[tid]; }
    if (tid < KNB) {
        s_nb[tid]  = neighbors[n * KNB + tid];
        s_eid[tid] = e_id[n * KNB + tid];
        s_mk[tid]  = mget(mask, n * KNB + tid, isb);
        s_dt[tid]  = t[n] - e_t[n * KNB + tid];
    }
    __syncthreads();
    if (tid == 0) {
        int any = 0;
        #pragma unroll
        for (int k = 0; k < KNB; k++) any |= s_mk[k];
        s_nonb = !any;
    }
    __syncthreads();
    const int nonb = s_nonb;
    const uint32_t kvb = smem_u32(kvc);

    // phase B: all gathers as cp.async (zero-fill when gated off)
    for (int i = tid; i < 640; i += 256) {
        int k = i >> 5, c4 = i & 31;
        int mk = s_mk[k];
        cpasync16(kvb + (uint32_t)(k * DKF + c4 * 4) * 4,
                  comb + (size_t)s_nb[k] * 128 + c4 * 4, mk ? 16u : 0u);
        cpasync16(kvb + (uint32_t)(k * DKF + 256 + c4 * 4) * 4,
                  event_feat + (size_t)s_eid[k] * 128 + c4 * 4, (mk | nonb) ? 16u : 0u);
    }
    asm volatile("cp.async.commit_group;" ::: "memory");

    // phase C: time encode + u -> regs while gathers are in flight
    const float* ubase = u + (size_t)n * 800;
    float4 u0[3], u1[3];
    #pragma unroll
    for (int i = 0; i < 3; i++) {
        u0[i] = *(const float4*)(ubase + lane * 4 + 128 * i);
        u1[i] = *(const float4*)(ubase + UPAD + lane * 4 + 128 * i);
    }
    float ub0 = ubase[384], ub1 = ubase[UPAD + 384];

    for (int i = tid; i < 640; i += 256) {
        int k = i >> 5, c4 = i & 31;
        float4 v = make_float4(0.f, 0.f, 0.f, 0.f);
        if (s_mk[k] | nonb) {
            float dt = s_dt[k];
            int j = c4 * 4;
            v.x = __cosf(__fadd_rn(__fmul_rn(dt, tw[j + 0]), tb[j + 0]));
            v.y = __cosf(__fadd_rn(__fmul_rn(dt, tw[j + 1]), tb[j + 1]));
            v.z = __cosf(__fadd_rn(__fmul_rn(dt, tw[j + 2]), tb[j + 2]));
            v.w = __cosf(__fadd_rn(__fmul_rn(dt, tw[j + 3]), tb[j + 3]));
        }
        *(float4*)&kvc[k][128 + c4 * 4] = v;
    }
    asm volatile("cp.async.wait_group 0;" ::: "memory");
    __syncthreads();

    // scores: each warp handles k slots; one kvc float4 read feeds BOTH heads
    for (int k = warp; k < KNB; k += 8) {
        if (!(s_mk[k] | nonb)) continue;          // warp-uniform
        float a0 = 0.f, a1 = 0.f;
        #pragma unroll
        for (int i = 0; i < 3; i++) {
            float4 v = *(const float4*)&kvc[k][lane * 4 + 128 * i];
            a0 += u0[i].x * v.x + u0[i].y * v.y + u0[i].z * v.z + u0[i].w * v.w;
            a1 += u1[i].x * v.x + u1[i].y * v.y + u1[i].z * v.z + u1[i].w * v.w;
        }
        #pragma unroll
        for (int off = 16; off; off >>= 1) {
            a0 += __shfl_down_sync(0xffffffffu, a0, off);
            a1 += __shfl_down_sync(0xffffffffu, a1, off);
        }
        if (lane == 0) {
            sc[0][k] = (a0 + ub0) * 0.08838834764831845f;
            sc[1][k] = (a1 + ub1) * 0.08838834764831845f;
        }
    }
    __syncthreads();

    // masked softmax per head (warps 0,1)
    if (warp < 2) {
        int h = warp;
        int valid = 0;
        float s = -INFINITY;
        if (lane < KNB) {
            valid = s_mk[lane] | nonb;
            if (valid) s = sc[h][lane];
        }
        float m = s;
        #pragma unroll
        for (int off = 16; off; off >>= 1) m = fmaxf(m, __shfl_xor_sync(0xffffffffu, m, off));
        float e = (lane < KNB && valid) ? expf(s - m) : 0.f;
        float sum = e;
        #pragma unroll
        for (int off = 16; off; off >>= 1) sum += __shfl_xor_sync(0xffffffffu, sum, off);
        if (lane < KNB) attn[h][lane] = e / sum;
    }
    __syncthreads();

    // mix: one float2 kvc read feeds BOTH heads (threads 0..191, 2 cols each)
    float gate = nonb ? 0.f : 1.f;
    if (tid < 192) {
        int j = tid * 2;
        float a00 = 0.f, a01 = 0.f, a10 = 0.f, a11 = 0.f;
        #pragma unroll
        for (int k = 0; k < KNB; k++) {
            float2 v = *(const float2*)&kvc[k][j];
            float w0 = attn[0][k], w1 = attn[1][k];
            a00 += w0 * v.x; a01 += w0 * v.y;
            a10 += w1 * v.x; a11 += w1 * v.y;
        }
        a00 *= gate; a01 *= gate; a10 *= gate; a11 *= gate;
        __nv_bfloat16 h00 = __float2bfloat16(a00), h01 = __float2bfloat16(a01);
        __nv_bfloat16 h10 = __float2bfloat16(a10), h11 = __float2bfloat16(a11);
        *(__nv_bfloat162*)(mixh + (size_t)n * 768 + j)       = __halves2bfloat162(h00, h01);
        *(__nv_bfloat162*)(mixh + (size_t)n * 768 + 384 + j) = __halves2bfloat162(h10, h11);
        __nv_bfloat16 l00 = __float2bfloat16(a00 - __bfloat162float(h00));
        __nv_bfloat16 l01 = __float2bfloat16(a01 - __bfloat162float(h01));
        __nv_bfloat16 l10 = __float2bfloat16(a10 - __bfloat162float(h10));
        __nv_bfloat16 l11 = __float2bfloat16(a11 - __bfloat162float(h11));
        *(__nv_bfloat162*)(mixl + (size_t)n * 768 + j)       = __halves2bfloat162(l00, l01);
        *(__nv_bfloat162*)(mixl + (size_t)n * 768 + 384 + j) = __halves2bfloat162(l10, l11);
    }
    if (tid == 0) flags[n] = (unsigned char)nonb;
}

// ================= launch =================
extern "C" void kernel_launch(void* const* d_in, const int* in_sizes, int n_in,
                              void* d_out, int out_size)
{
    const int*   idx        = (const int*)d_in[0];
    const float* t          = (const float*)d_in[1];
    const int*   neighbors  = (const int*)d_in[2];
    const float* e_t        = (const float*)d_in[3];
    const int*   e_id       = (const int*)d_in[4];
    const void*  mask       = d_in[5];
    const float* node_feat  = (const float*)d_in[6];
    const float* memory     = (const float*)d_in[7];
    const float* event_feat = (const float*)d_in[8];
    const float* time_w     = (const float*)d_in[9];
    const float* time_b     = (const float*)d_in[10];
    const float* Wq = (const float*)d_in[11];
    const float* bq = (const float*)d_in[12];
    const float* Wk = (const float*)d_in[13];
    const float* bk = (const float*)d_in[14];
    const float* Wv = (const float*)d_in[15];
    const float* bv = (const float*)d_in[16];
    const float* Wo = (const float*)d_in[17];
    const float* bo = (const float*)d_in[18];
    const float* W1 = (const float*)d_in[19];
    const float* b1 = (const float*)d_in[20];
    const float* W2 = (const float*)d_in[21];
    const float* b2 = (const float*)d_in[22];
    float* out = (float*)d_out;

    int N = in_sizes[0];
    if (N > NN) N = NN;

    float *u, *du, *Pt, *cvec, *comb;
    __nv_bfloat16 *qh, *ql, *mh, *ml, *h1h, *h1l, *Muh, *Mul, *Bfh, *Bfl, *W2h, *W2l;
    unsigned char* flags;
    cudaGetSymbolAddress((void**)&u, g_u);
    cudaGetSymbolAddress((void**)&du, g_du);
    cudaGetSymbolAddress((void**)&Pt, g_Pt);
    cudaGetSymbolAddress((void**)&cvec, g_cvec);
    cudaGetSymbolAddress((void**)&comb, g_comb);
    cudaGetSymbolAddress((void**)&qh, g_qh);
    cudaGetSymbolAddress((void**)&ql, g_ql);
    cudaGetSymbolAddress((void**)&mh, g_mh);
    cudaGetSymbolAddress((void**)&ml, g_ml);
    cudaGetSymbolAddress((void**)&h1h, g_h1h);
    cudaGetSymbolAddress((void**)&h1l, g_h1l);
    cudaGetSymbolAddress((void**)&Muh, g_Muh);
    cudaGetSymbolAddress((void**)&Mul, g_Mul);
    cudaGetSymbolAddress((void**)&Bfh, g_Bfh);
    cudaGetSymbolAddress((void**)&Bfl, g_Bfl);
    cudaGetSymbolAddress((void**)&W2h, g_W2h);
    cudaGetSymbolAddress((void**)&W2l, g_W2l);
    cudaGetSymbolAddress((void**)&flags, g_flags);

    cudaFuncSetAttribute(mma_gemm<0>, cudaFuncAttributeMaxDynamicSharedMemorySize, SMEM_GEMM);
    cudaFuncSetAttribute(mma_gemm<1>, cudaFuncAttributeMaxDynamicSharedMemorySize, SMEM_GEMM);
    cudaFuncSetAttribute(mma_gemm<2>, cudaFuncAttributeMaxDynamicSharedMemorySize, SMEM_GEMM);

    int mtiles = (N + 127) / 128;
    int nbComb = (NNODES * 32 + 255) / 256;
    int nbGather = (N * 32 + 255) / 256;

    // 0: composeU (padded 800 rows, qhconst folded in)
    k_composeU<<<800, 128>>>(Wk, bk, Wq, bq, time_b, Muh, Mul, du);
    // 1: fused prep (comb + q gather/split + mask probe)
    k_prep<<<nbComb + nbGather + 1, 256>>>(idx, node_feat, memory, comb,
                                           qh, ql, (const unsigned char*)mask,
                                           N, nbComb, nbGather);
    // 2: u = Mu @ q + du  -> g_u (N x 800, padded)
    mma_gemm<0><<<dim3(mtiles, 7), 256, SMEM_GEMM>>>(
        qh, ql, 128, nullptr, nullptr, 0, 1000,
        Muh, Mul, 128, 4, 800,
        du, nullptr, nullptr, u, 800, nullptr, nullptr, N);
    // 3: fused edge kernel -> mixed hi/lo (N x 768)   [ncu profiles this slot]
    k_edge<<<N, 256>>>(neighbors, t, e_t, e_id, mask, comb,
                       event_feat, time_w, time_b, u, mh, ml, flags, N);
    // 4..6: compose final weights
    k_composeP<<<128, 256>>>(W1, Wo, bv, bo, Pt, cvec);
    k_composeC<<<896, 128>>>(Pt, Wv, W1, Bfh, Bfl);
    k_splitW2<<<64, 256>>>(W2, W2h, W2l);
    // 7: h1 = relu(Bf @ [mixed, q] + b1 + gated cvec) -> h1 hi/lo (N x 128)
    mma_gemm<1><<<dim3(mtiles, 1), 256, SMEM_GEMM>>>(
        mh, ml, 768, qh, ql, 128, 24,
        Bfh, Bfl, 896, 28, 128,
        b1, cvec, flags, nullptr, 0, h1h, h1l, N);
    // 8: out = h1 @ W2^T + b2 -> d_out (N x 128)
    mma_gemm<2><<<dim3(mtiles, 1), 256, SMEM_GEMM>>>(
        h1h, h1l, 128, nullptr, nullptr, 0, 1000,
        W2h, W2l, 128, 4, 128,
        b2, nullptr, nullptr, out, 128, nullptr, nullptr, N);
}

// round 12
// speedup vs baseline: 2.6769x; 1.0173x over previous
#include <cuda_runtime.h>
#include <cuda_bf16.h>
#include <math.h>
#include <stdint.h>

#define NN    100000
#define KNB   20
#define DKF   384
#define UPAD  400     // padded per-head u stride (float4-aligned)
#define NNODES 200000

// ================= device scratch =================
__device__ float g_comb[(size_t)NNODES * 128];   // node_feat + memory (precomputed)
__device__ float g_u[(size_t)NN * 800];          // u padded: [h0 c0..384 pad][h1 c0..384 pad]
__device__ uint4 g_qh[(size_t)NN * 16];          // q hi  (N x 128 bf16)
__device__ uint4 g_ql[(size_t)NN * 16];          // q lo
__device__ uint4 g_mh[(size_t)NN * 96];          // mixed hi (N x 768 bf16)
__device__ uint4 g_ml[(size_t)NN * 96];          // mixed lo
__device__ uint4 g_h1h[(size_t)NN * 16];         // h1 hi (N x 128 bf16)
__device__ uint4 g_h1l[(size_t)NN * 16];         // h1 lo
__device__ uint4 g_Muh[14336], g_Mul[14336];     // Mu 800(pad 896) x 128 bf16
__device__ uint4 g_Bfh[14336], g_Bfl[14336];     // Bf 128 x 896 bf16
__device__ uint4 g_W2h[2048], g_W2l[2048];       // W2 128 x 128 bf16
__device__ float g_du[896];
__device__ float g_Pt[256 * 128];
__device__ float g_cvec[128];
__device__ unsigned char g_flags[NN];
__device__ int   g_mask_is_byte;

// ================= PTX helpers (baseline features only) =================
__device__ __forceinline__ uint32_t smem_u32(const void* p) {
    uint32_t r;
    asm("{ .reg .u64 t; cvta.to.shared.u64 t, %1; cvt.u32.u64 %0, t; }" : "=r"(r) : "l"(p));
    return r;
}
__device__ __forceinline__ void ldm_x4(uint32_t* r, uint32_t addr) {
    asm volatile("ldmatrix.sync.aligned.m8n8.x4.shared.b16 {%0,%1,%2,%3}, [%4];"
                 : "=r"(r[0]), "=r"(r[1]), "=r"(r[2]), "=r"(r[3]) : "r"(addr));
}
__device__ __forceinline__ void ldm_x2(uint32_t* r, uint32_t addr) {
    asm volatile("ldmatrix.sync.aligned.m8n8.x2.shared.b16 {%0,%1}, [%2];"
                 : "=r"(r[0]), "=r"(r[1]) : "r"(addr));
}
__device__ __forceinline__ void mma16816(float* c, const uint32_t* a, const uint32_t* b) {
    asm volatile("mma.sync.aligned.m16n8k16.row.col.f32.bf16.bf16.f32 "
        "{%0,%1,%2,%3}, {%4,%5,%6,%7}, {%8,%9}, {%0,%1,%2,%3};"
        : "+f"(c[0]), "+f"(c[1]), "+f"(c[2]), "+f"(c[3])
        : "r"(a[0]), "r"(a[1]), "r"(a[2]), "r"(a[3]), "r"(b[0]), "r"(b[1]));
}
__device__ __forceinline__ void cpasync16(uint32_t dst, const void* src, uint32_t srcsize) {
    asm volatile("cp.async.cg.shared.global [%0], [%1], 16, %2;"
                 :: "r"(dst), "l"(src), "r"(srcsize));
}
__device__ __forceinline__ void cpasync16(uint32_t dst, const void* src) {
    asm volatile("cp.async.cg.shared.global [%0], [%1], 16;" :: "r"(dst), "l"(src));
}
__device__ __forceinline__ int mget(const void* m, int i, int isbyte) {
    return isbyte ? (((const unsigned char*)m)[i] != 0) : (((const int*)m)[i] != 0);
}

// ================= setup / compose =================
__device__ __forceinline__ void split_store(__nv_bfloat16* ph, __nv_bfloat16* pl, size_t i, float v) {
    __nv_bfloat16 h = __float2bfloat16(v);
    ph[i] = h;
    pl[i] = __float2bfloat16(v - __bfloat162float(h));
}

// composeU: Mu + du with qhconst folded in; PADDED rows (800 = 2 x 400).
__global__ void k_composeU(const float* __restrict__ Wk, const float* __restrict__ bk,
                           const float* __restrict__ Wq, const float* __restrict__ bq,
                           const float* __restrict__ time_b,
                           __nv_bfloat16* __restrict__ Mh, __nv_bfloat16* __restrict__ Ml,
                           float* __restrict__ du)
{
    int hc = blockIdx.x;          // 0..799
    int h = hc / UPAD, c = hc % UPAD;
    int e = threadIdx.x;          // 0..127
    __shared__ float krow[128];
    __shared__ float cb[128];
    __shared__ float red[128];
    cb[e] = cosf(time_b[e]);
    krow[e] = (c < 384) ? Wk[(size_t)(h * 128 + e) * 384 + c]
            : ((c == 384) ? bk[h * 128 + e] : 0.f);
    __syncthreads();
    float acc1 = 0.f, acc2 = 0.f;
    #pragma unroll 4
    for (int d = 0; d < 128; d++) {
        const float* row = Wq + (size_t)(h * 128 + d) * 256;
        float kd = krow[d];
        acc1 += kd * row[e];
        acc2 += kd * row[128 + e];
    }
    split_store(Mh, Ml, (size_t)hc * 128 + e, acc1);
    red[e] = acc2 * cb[e] + krow[e] * bq[h * 128 + e];
    __syncthreads();
    for (int off = 64; off; off >>= 1) {
        if (e < off) red[e] += red[e + off];
        __syncthreads();
    }
    if (e == 0) du[hc] = red[0];
}

// k_prep: comb (all nodes) + q gather/split + mask-layout probe, one launch.
__global__ void k_prep(const int* __restrict__ idx,
                       const float* __restrict__ nf, const float* __restrict__ mem,
                       float* __restrict__ comb,
                       __nv_bfloat16* __restrict__ qh, __nv_bfloat16* __restrict__ ql,
                       const unsigned char* __restrict__ mask,
                       int n, int nbComb, int nbGather)
{
    int b = blockIdx.x;
    if (b < nbComb) {
        size_t i = (size_t)b * 256 + threadIdx.x;
        if (i < (size_t)NNODES * 32) {
            float4 a = ((const float4*)nf)[i];
            float4 m = ((const float4*)mem)[i];
            ((float4*)comb)[i] = make_float4(a.x + m.x, a.y + m.y, a.z + m.z, a.w + m.w);
        }
    } else if (b < nbComb + nbGather) {
        int i = (b - nbComb) * 256 + threadIdx.x;
        if (i < n * 32) {
            int node = i >> 5, c4 = i & 31;
            int src = idx[node];
            float4 a = ((const float4*)nf)[(size_t)src * 32 + c4];
            float4 m = ((const float4*)mem)[(size_t)src * 32 + c4];
            float v[4] = { a.x + m.x, a.y + m.y, a.z + m.z, a.w + m.w };
            size_t base = (size_t)i * 4;
            #pragma unroll
            for (int j = 0; j < 4; j++) split_store(qh, ql, base + j, v[j]);
        }
    } else {
        int any = 0;
        for (int i = threadIdx.x; i < 8192; i += 256)
            if ((i & 3) != 0 && mask[i] != 0) any = 1;
        int r = __syncthreads_or(any);
        if (threadIdx.x == 0) g_mask_is_byte = r ? 1 : 0;
    }
}

__global__ void k_composeP(const float* __restrict__ W1, const float* __restrict__ Wo,
                           const float* __restrict__ bv, const float* __restrict__ bo,
                           float* __restrict__ Pt, float* __restrict__ cvec)
{
    int r = blockIdx.x;           // 0..127
    int a = threadIdx.x;          // 0..255
    __shared__ float w1row[256];
    __shared__ float red[256];
    w1row[a] = W1[(size_t)r * 384 + a];
    __syncthreads();
    float acc = 0.f;
    #pragma unroll 8
    for (int s = 0; s < 256; s++) acc += w1row[s] * Wo[(size_t)s * 256 + a];
    Pt[(size_t)a * 128 + r] = acc;
    red[a] = acc * bv[a] + w1row[a] * bo[a];
    __syncthreads();
    for (int off = 128; off; off >>= 1) {
        if (a < off) red[a] += red[a + off];
        __syncthreads();
    }
    if (a == 0) cvec[r] = red[0];
}

__global__ void k_composeC(const float* __restrict__ Pt, const float* __restrict__ Wv,
                           const float* __restrict__ W1,
                           __nv_bfloat16* __restrict__ Bh, __nv_bfloat16* __restrict__ Bl)
{
    int j = blockIdx.x;           // 0..895
    int r = threadIdx.x;          // 0..127
    if (j >= 768) {
        split_store(Bh, Bl, (size_t)r * 896 + j, W1[(size_t)r * 384 + 256 + (j - 768)]);
        return;
    }
    int h = j / 384, c = j % 384;
    __shared__ float wvcol[128];
    wvcol[r] = Wv[(size_t)(h * 128 + r) * 384 + c];
    __syncthreads();
    float acc = 0.f;
    #pragma unroll 8
    for (int d = 0; d < 128; d++)
        acc += Pt[(size_t)(h * 128 + d) * 128 + r] * wvcol[d];
    split_store(Bh, Bl, (size_t)r * 896 + j, acc);
}

__global__ void k_splitW2(const float* __restrict__ W2,
                          __nv_bfloat16* __restrict__ wh, __nv_bfloat16* __restrict__ wl)
{
    int i = blockIdx.x * 256 + threadIdx.x;
    if (i < 128 * 128) split_store(wh, wl, i, W2[i]);
}

// ================= HMMA GEMM (cp.async double-buffered, 2 CTAs/SM) ===========
#define LDS_STRIDE 40                 // bf16 elems; 80B rows, ldmatrix conflict-free
#define TILE_B     (128 * LDS_STRIDE * 2)   // 10240 bytes per tile
#define STAGE_B    (4 * TILE_B)             // AsH AsL BsH BsL
#define SMEM_GEMM  (2 * STAGE_B)            // 81920

template<int EPI>
__global__ __launch_bounds__(256, 2)
void mma_gemm(const __nv_bfloat16* __restrict__ Ah, const __nv_bfloat16* __restrict__ Al, int lda,
              const __nv_bfloat16* __restrict__ A2h, const __nv_bfloat16* __restrict__ A2l, int lda2, int ksplit,
              const __nv_bfloat16* __restrict__ Bh, const __nv_bfloat16* __restrict__ Bl, int ldb,
              int ktiles, int Rtot,
              const float* __restrict__ bias, const float* __restrict__ bias2,
              const unsigned char* __restrict__ flags,
              float* __restrict__ OutF, int ldc,
              __nv_bfloat16* __restrict__ OutH, __nv_bfloat16* __restrict__ OutL, int Ntot)
{
    extern __shared__ char dsm[];
    const uint32_t sb = smem_u32(dsm);

    const int tid = threadIdx.x;
    const int lane = tid & 31, wid = tid >> 5;
    const int wm = wid >> 2, wn = wid & 3;      // 2 x 4 warp grid
    const int m0 = blockIdx.x * 128;
    const int r0 = blockIdx.y * 128;

    int vrows = Ntot - m0;
    if (vrows > 128) vrows = 128;
    if (vrows < 0) vrows = 0;

    float acc[4][4][4];
    #pragma unroll
    for (int a = 0; a < 4; a++)
        #pragma unroll
        for (int b = 0; b < 4; b++)
            #pragma unroll
            for (int c = 0; c < 4; c++) acc[a][b][c] = 0.f;

    const int lrow = tid >> 2;                 // 0..63 (+64 on 2nd pass)
    const int lc8 = (tid & 3) * 8;             // bf16 col within 32

    auto issue_stage = [&](int kt) {
        uint32_t base = sb + (kt & 1) * STAGE_B;
        const __nv_bfloat16 *sh, *sl; int st, k0;
        if (kt < ksplit) { sh = Ah;  sl = Al;  st = lda;  k0 = kt * 32; }
        else             { sh = A2h; sl = A2l; st = lda2; k0 = (kt - ksplit) * 32; }
        #pragma unroll
        for (int i = 0; i < 2; i++) {
            int row = lrow + i * 64;
            int srow = (row < vrows) ? row : 0;
            uint32_t sz = (row < vrows) ? 16u : 0u;
            uint32_t doff = row * (LDS_STRIDE * 2) + lc8 * 2;
            cpasync16(base + doff,
                      sh + (size_t)(m0 + srow) * st + k0 + lc8, sz);
            cpasync16(base + TILE_B + doff,
                      sl + (size_t)(m0 + srow) * st + k0 + lc8, sz);
            cpasync16(base + 2 * TILE_B + doff,
                      Bh + (size_t)(r0 + row) * ldb + kt * 32 + lc8);
            cpasync16(base + 3 * TILE_B + doff,
                      Bl + (size_t)(r0 + row) * ldb + kt * 32 + lc8);
        }
        asm volatile("cp.async.commit_group;" ::: "memory");
    };

    const int arow = wm * 64 + (lane & 15);
    const int acolsel = ((lane >> 4) & 1) * 8;
    const int l16 = lane & 15;
    const int brow = wn * 32 + (l16 & 7);
    const int bcolsel = ((l16 >> 3) & 1) * 8;

    issue_stage(0);

    for (int kt = 0; kt < ktiles; kt++) {
        if (kt + 1 < ktiles) {
            issue_stage(kt + 1);
            asm volatile("cp.async.wait_group 1;" ::: "memory");
        } else {
            asm volatile("cp.async.wait_group 0;" ::: "memory");
        }
        __syncthreads();

        const uint32_t cb = sb + (kt & 1) * STAGE_B;
        const uint32_t sAH = cb, sAL = cb + TILE_B;
        const uint32_t sBH = cb + 2 * TILE_B, sBL = cb + 3 * TILE_B;

        #pragma unroll
        for (int ks = 0; ks < 2; ks++) {
            const int acol = ks * 16 + acolsel;
            const int bcol = ks * 16 + bcolsel;
            uint32_t af[4][4], bhf[4][2], blf[4][2];
            #pragma unroll
            for (int mi = 0; mi < 4; mi++)
                ldm_x4(af[mi], sAH + (uint32_t)(((arow + mi * 16) * LDS_STRIDE + acol) * 2));
            #pragma unroll
            for (int ni = 0; ni < 4; ni++) {
                ldm_x2(bhf[ni], sBH + (uint32_t)(((brow + ni * 8) * LDS_STRIDE + bcol) * 2));
                ldm_x2(blf[ni], sBL + (uint32_t)(((brow + ni * 8) * LDS_STRIDE + bcol) * 2));
            }
            #pragma unroll
            for (int mi = 0; mi < 4; mi++)
                #pragma unroll
                for (int ni = 0; ni < 4; ni++) {
                    mma16816(acc[mi][ni], af[mi], bhf[ni]);   // Ah*Bh
                    mma16816(acc[mi][ni], af[mi], blf[ni]);   // Ah*Bl
                }
            #pragma unroll
            for (int mi = 0; mi < 4; mi++)
                ldm_x4(af[mi], sAL + (uint32_t)(((arow + mi * 16) * LDS_STRIDE + acol) * 2));
            #pragma unroll
            for (int mi = 0; mi < 4; mi++)
                #pragma unroll
                for (int ni = 0; ni < 4; ni++)
                    mma16816(acc[mi][ni], af[mi], bhf[ni]);   // Al*Bh
        }
        __syncthreads();
    }

    // ---- epilogue ----
    #pragma unroll
    for (int mi = 0; mi < 4; mi++) {
        int nrow0 = m0 + wm * 64 + mi * 16 + (lane >> 2);
        #pragma unroll
        for (int half = 0; half < 2; half++) {
            int n = nrow0 + half * 8;
            if (n >= Ntot) continue;
            bool fl = false;
            if (EPI == 1) fl = (flags[n] != 0);
            #pragma unroll
            for (int ni = 0; ni < 4; ni++) {
                int r = r0 + wn * 32 + ni * 8 + (lane & 3) * 2;
                float v0 = acc[mi][ni][half * 2 + 0];
                float v1 = acc[mi][ni][half * 2 + 1];
                if (EPI == 0) {
                    if (r < Rtot)     OutF[(size_t)n * ldc + r]     = v0 + bias[r];
                    if (r + 1 < Rtot) OutF[(size_t)n * ldc + r + 1] = v1 + bias[r + 1];
                } else if (EPI == 1) {
                    v0 += bias[r]     + (fl ? 0.f : bias2[r]);
                    v1 += bias[r + 1] + (fl ? 0.f : bias2[r + 1]);
                    v0 = fmaxf(v0, 0.f);
                    v1 = fmaxf(v1, 0.f);
                    __nv_bfloat16 h0 = __float2bfloat16(v0), h1 = __float2bfloat16(v1);
                    *(__nv_bfloat162*)(OutH + (size_t)n * 128 + r) = __halves2bfloat162(h0, h1);
                    __nv_bfloat16 l0 = __float2bfloat16(v0 - __bfloat162float(h0));
                    __nv_bfloat16 l1 = __float2bfloat16(v1 - __bfloat162float(h1));
                    *(__nv_bfloat162*)(OutL + (size_t)n * 128 + r) = __halves2bfloat162(l0, l1);
                } else {
                    OutF[(size_t)n * ldc + r]     = v0 + bias[r];
                    OutF[(size_t)n * ldc + r + 1] = v1 + bias[r + 1];
                }
            }
        }
    }
}

// ================= fused per-node edge kernel =================
// u in registers of score warps 0-3 only (halves redundant u loads);
// every kvc read feeds BOTH heads.
__global__ __launch_bounds__(256)
void k_edge(const int* __restrict__ neighbors, const float* __restrict__ t,
            const float* __restrict__ e_t, const int* __restrict__ e_id,
            const void* __restrict__ mask,
            const float* __restrict__ comb,
            const float* __restrict__ event_feat,
            const float* __restrict__ time_w, const float* __restrict__ time_b,
            const float* __restrict__ u,
            __nv_bfloat16* __restrict__ mixh, __nv_bfloat16* __restrict__ mixl,
            unsigned char* __restrict__ flags, int Ntot)
{
    int n = blockIdx.x;
    if (n >= Ntot) return;
    int tid = threadIdx.x;
    int lane = tid & 31, warp = tid >> 5;
    const int isb = g_mask_is_byte;

    __shared__ float kvc[KNB][DKF];
    __shared__ float tw[128], tb[128];
    __shared__ float attn[2][KNB];
    __shared__ float sc[2][KNB];
    __shared__ int s_nb[KNB], s_eid[KNB], s_mk[KNB];
    __shared__ float s_dt[KNB];
    __shared__ int s_nonb;

    // u -> regs for score warps 0-3 (issued first; independent of everything)
    const float* ubase = u + (size_t)n * 800;
    float4 u0[3], u1[3];
    float ub0 = 0.f, ub1 = 0.f;
    if (warp < 4) {
        #pragma unroll
        for (int i = 0; i < 3; i++) {
            u0[i] = *(const float4*)(ubase + lane * 4 + 128 * i);
            u1[i] = *(const float4*)(ubase + UPAD + lane * 4 + 128 * i);
        }
        ub0 = ubase[384]; ub1 = ubase[UPAD + 384];
    }

    // constants loaded by warps 4-7; metadata by warp 0 lanes <20
    if (tid >= 128) { tw[tid - 128] = time_w[tid - 128]; tb[tid - 128] = time_b[tid - 128]; }
    if (tid < KNB) {
        s_nb[tid]  = neighbors[n * KNB + tid];
        s_eid[tid] = e_id[n * KNB + tid];
        s_mk[tid]  = mget(mask, n * KNB + tid, isb);
        s_dt[tid]  = t[n] - e_t[n * KNB + tid];
    }
    __syncthreads();
    if (tid == 0) {
        int any = 0;
        #pragma unroll
        for (int k = 0; k < KNB; k++) any |= s_mk[k];
        s_nonb = !any;
    }
    __syncthreads();
    const int nonb = s_nonb;
    const uint32_t kvb = smem_u32(kvc);

    // phase B: all gathers as cp.async (zero-fill when gated off)
    for (int i = tid; i < 640; i += 256) {
        int k = i >> 5, c4 = i & 31;
        int mk = s_mk[k];
        cpasync16(kvb + (uint32_t)(k * DKF + c4 * 4) * 4,
                  comb + (size_t)s_nb[k] * 128 + c4 * 4, mk ? 16u : 0u);
        cpasync16(kvb + (uint32_t)(k * DKF + 256 + c4 * 4) * 4,
                  event_feat + (size_t)s_eid[k] * 128 + c4 * 4, (mk | nonb) ? 16u : 0u);
    }
    asm volatile("cp.async.commit_group;" ::: "memory");

    // phase C: time encode while gathers are in flight
    for (int i = tid; i < 640; i += 256) {
        int k = i >> 5, c4 = i & 31;
        float4 v = make_float4(0.f, 0.f, 0.f, 0.f);
        if (s_mk[k] | nonb) {
            float dt = s_dt[k];
            int j = c4 * 4;
            v.x = __cosf(__fadd_rn(__fmul_rn(dt, tw[j + 0]), tb[j + 0]));
            v.y = __cosf(__fadd_rn(__fmul_rn(dt, tw[j + 1]), tb[j + 1]));
            v.z = __cosf(__fadd_rn(__fmul_rn(dt, tw[j + 2]), tb[j + 2]));
            v.w = __cosf(__fadd_rn(__fmul_rn(dt, tw[j + 3]), tb[j + 3]));
        }
        *(float4*)&kvc[k][128 + c4 * 4] = v;
    }
    asm volatile("cp.async.wait_group 0;" ::: "memory");
    __syncthreads();

    // scores: 4 warps, 5 k-slots each; one kvc float4 read feeds BOTH heads
    if (warp < 4) {
        for (int k = warp; k < KNB; k += 4) {
            if (!(s_mk[k] | nonb)) continue;      // warp-uniform
            float a0 = 0.f, a1 = 0.f;
            #pragma unroll
            for (int i = 0; i < 3; i++) {
                float4 v = *(const float4*)&kvc[k][lane * 4 + 128 * i];
                a0 += u0[i].x * v.x + u0[i].y * v.y + u0[i].z * v.z + u0[i].w * v.w;
                a1 += u1[i].x * v.x + u1[i].y * v.y + u1[i].z * v.z + u1[i].w * v.w;
            }
            #pragma unroll
            for (int off = 16; off; off >>= 1) {
                a0 += __shfl_down_sync(0xffffffffu, a0, off);
                a1 += __shfl_down_sync(0xffffffffu, a1, off);
            }
            if (lane == 0) {
                sc[0][k] = (a0 + ub0) * 0.08838834764831845f;
                sc[1][k] = (a1 + ub1) * 0.08838834764831845f;
            }
        }
    }
    __syncthreads();

    // masked softmax per head (warps 0,1)
    if (warp < 2) {
        int h = warp;
        int valid = 0;
        float s = -INFINITY;
        if (lane < KNB) {
            valid = s_mk[lane] | nonb;
            if (valid) s = sc[h][lane];
        }
        float m = s;
        #pragma unroll
        for (int off = 16; off; off >>= 1) m = fmaxf(m, __shfl_xor_sync(0xffffffffu, m, off));
        float e = (lane < KNB && valid) ? __expf(s - m) : 0.f;
        float sum = e;
        #pragma unroll
        for (int off = 16; off; off >>= 1) sum += __shfl_xor_sync(0xffffffffu, sum, off);
        if (lane < KNB) attn[h][lane] = e / sum;
    }
    __syncthreads();

    // mix: one float2 kvc read feeds BOTH heads (threads 0..191, 2 cols each)
    float gate = nonb ? 0.f : 1.f;
    if (tid < 192) {
        int j = tid * 2;
        float a00 = 0.f, a01 = 0.f, a10 = 0.f, a11 = 0.f;
        #pragma unroll
        for (int k = 0; k < KNB; k++) {
            float2 v = *(const float2*)&kvc[k][j];
            float w0 = attn[0][k], w1 = attn[1][k];
            a00 += w0 * v.x; a01 += w0 * v.y;
            a10 += w1 * v.x; a11 += w1 * v.y;
        }
        a00 *= gate; a01 *= gate; a10 *= gate; a11 *= gate;
        __nv_bfloat16 h00 = __float2bfloat16(a00), h01 = __float2bfloat16(a01);
        __nv_bfloat16 h10 = __float2bfloat16(a10), h11 = __float2bfloat16(a11);
        *(__nv_bfloat162*)(mixh + (size_t)n * 768 + j)       = __halves2bfloat162(h00, h01);
        *(__nv_bfloat162*)(mixh + (size_t)n * 768 + 384 + j) = __halves2bfloat162(h10, h11);
        __nv_bfloat16 l00 = __float2bfloat16(a00 - __bfloat162float(h00));
        __nv_bfloat16 l01 = __float2bfloat16(a01 - __bfloat162float(h01));
        __nv_bfloat16 l10 = __float2bfloat16(a10 - __bfloat162float(h10));
        __nv_bfloat16 l11 = __float2bfloat16(a11 - __bfloat162float(h11));
        *(__nv_bfloat162*)(mixl + (size_t)n * 768 + j)       = __halves2bfloat162(l00, l01);
        *(__nv_bfloat162*)(mixl + (size_t)n * 768 + 384 + j) = __halves2bfloat162(l10, l11);
    }
    if (tid == 0) flags[n] = (unsigned char)nonb;
}

// ================= launch =================
extern "C" void kernel_launch(void* const* d_in, const int* in_sizes, int n_in,
                              void* d_out, int out_size)
{
    const int*   idx        = (const int*)d_in[0];
    const float* t          = (const float*)d_in[1];
    const int*   neighbors  = (const int*)d_in[2];
    const float* e_t        = (const float*)d_in[3];
    const int*   e_id       = (const int*)d_in[4];
    const void*  mask       = d_in[5];
    const float* node_feat  = (const float*)d_in[6];
    const float* memory     = (const float*)d_in[7];
    const float* event_feat = (const float*)d_in[8];
    const float* time_w     = (const float*)d_in[9];
    const float* time_b     = (const float*)d_in[10];
    const float* Wq = (const float*)d_in[11];
    const float* bq = (const float*)d_in[12];
    const float* Wk = (const float*)d_in[13];
    const float* bk = (const float*)d_in[14];
    const float* Wv = (const float*)d_in[15];
    const float* bv = (const float*)d_in[16];
    const float* Wo = (const float*)d_in[17];
    const float* bo = (const float*)d_in[18];
    const float* W1 = (const float*)d_in[19];
    const float* b1 = (const float*)d_in[20];
    const float* W2 = (const float*)d_in[21];
    const float* b2 = (const float*)d_in[22];
    float* out = (float*)d_out;

    int N = in_sizes[0];
    if (N > NN) N = NN;

    float *u, *du, *Pt, *cvec, *comb;
    __nv_bfloat16 *qh, *ql, *mh, *ml, *h1h, *h1l, *Muh, *Mul, *Bfh, *Bfl, *W2h, *W2l;
    unsigned char* flags;
    cudaGetSymbolAddress((void**)&u, g_u);
    cudaGetSymbolAddress((void**)&du, g_du);
    cudaGetSymbolAddress((void**)&Pt, g_Pt);
    cudaGetSymbolAddress((void**)&cvec, g_cvec);
    cudaGetSymbolAddress((void**)&comb, g_comb);
    cudaGetSymbolAddress((void**)&qh, g_qh);
    cudaGetSymbolAddress((void**)&ql, g_ql);
    cudaGetSymbolAddress((void**)&mh, g_mh);
    cudaGetSymbolAddress((void**)&ml, g_ml);
    cudaGetSymbolAddress((void**)&h1h, g_h1h);
    cudaGetSymbolAddress((void**)&h1l, g_h1l);
    cudaGetSymbolAddress((void**)&Muh, g_Muh);
    cudaGetSymbolAddress((void**)&Mul, g_Mul);
    cudaGetSymbolAddress((void**)&Bfh, g_Bfh);
    cudaGetSymbolAddress((void**)&Bfl, g_Bfl);
    cudaGetSymbolAddress((void**)&W2h, g_W2h);
    cudaGetSymbolAddress((void**)&W2l, g_W2l);
    cudaGetSymbolAddress((void**)&flags, g_flags);

    cudaFuncSetAttribute(mma_gemm<0>, cudaFuncAttributeMaxDynamicSharedMemorySize, SMEM_GEMM);
    cudaFuncSetAttribute(mma_gemm<1>, cudaFuncAttributeMaxDynamicSharedMemorySize, SMEM_GEMM);
    cudaFuncSetAttribute(mma_gemm<2>, cudaFuncAttributeMaxDynamicSharedMemorySize, SMEM_GEMM);

    int mtiles = (N + 127) / 128;
    int nbComb = (NNODES * 32 + 255) / 256;
    int nbGather = (N * 32 + 255) / 256;

    // 0: composeU (padded 800 rows, qhconst folded in)
    k_composeU<<<800, 128>>>(Wk, bk, Wq, bq, time_b, Muh, Mul, du);
    // 1: fused prep (comb + q gather/split + mask probe)
    k_prep<<<nbComb + nbGather + 1, 256>>>(idx, node_feat, memory, comb,
                                           qh, ql, (const unsigned char*)mask,
                                           N, nbComb, nbGather);
    // 2: u = Mu @ q + du  -> g_u (N x 800, padded)
    mma_gemm<0><<<dim3(mtiles, 7), 256, SMEM_GEMM>>>(
        qh, ql, 128, nullptr, nullptr, 0, 1000,
        Muh, Mul, 128, 4, 800,
        du, nullptr, nullptr, u, 800, nullptr, nullptr, N);
    // 3: fused edge kernel -> mixed hi/lo (N x 768)   [ncu profiles this slot]
    k_edge<<<N, 256>>>(neighbors, t, e_t, e_id, mask, comb,
                       event_feat, time_w, time_b, u, mh, ml, flags, N);
    // 4..6: compose final weights
    k_composeP<<<128, 256>>>(W1, Wo, bv, bo, Pt, cvec);
    k_composeC<<<896, 128>>>(Pt, Wv, W1, Bfh, Bfl);
    k_splitW2<<<64, 256>>>(W2, W2h, W2l);
    // 7: h1 = relu(Bf @ [mixed, q] + b1 + gated cvec) -> h1 hi/lo (N x 128)
    mma_gemm<1><<<dim3(mtiles, 1), 256, SMEM_GEMM>>>(
        mh, ml, 768, qh, ql, 128, 24,
        Bfh, Bfl, 896, 28, 128,
        b1, cvec, flags, nullptr, 0, h1h, h1l, N);
    // 8: out = h1 @ W2^T + b2 -> d_out (N x 128)
    mma_gemm<2><<<dim3(mtiles, 1), 256, SMEM_GEMM>>>(
        h1h, h1l, 128, nullptr, nullptr, 0, 1000,
        W2h, W2l, 128, 4, 128,
        b2, nullptr, nullptr, out, 128, nullptr, nullptr, N);
}